// round 5
// baseline (speedup 1.0000x reference)
#include <cuda_runtime.h>
#include <cuda_bf16.h>
#include <cstdint>
#include <math.h>

// ---------------- problem constants ----------------
#define PB   4
#define PN1  2048
#define PN2  512
#define PD   768
#define PH   8
#define PDK  64
#define PDV  96
#define PNRP 96
#define PDY0 1536
#define PDFF 1536
#define PMQ  2560              // needed pos rows: m = i - j + 511 in [0, 2558]
#define PSCALE 0.125f          // DK^-0.5

// ---------------- scratch layout (floats) ----------------
#define OFF_Y      0L
#define OFF_X1     (OFF_Y    + (long)PB*PN2*PD)
#define OFF_Y1     (OFF_X1   + (long)PB*PN1*PD)
#define OFF_Q      (OFF_Y1   + (long)PB*PN2*PD)
#define OFF_K      (OFF_Q    + (long)PB*PN1*PH*PDK)
#define OFF_KB     (OFF_K    + (long)PB*PN2*PH*PDK)
#define OFF_V1     (OFF_KB   + (long)PB*PN2*PH*PDK)
#define OFF_V2     (OFF_V1   + (long)PB*PN1*PH*PDV)
#define OFF_POS    (OFF_V2   + (long)PB*PN2*PH*PDV)
#define OFF_RELQ   (OFF_POS  + (long)PMQ*PNRP)
#define OFF_REL    (OFF_RELQ + (long)PMQ*PH*PDK)
#define OFF_ATT    (OFF_REL  + (long)PB*PH*PN2*PMQ)
#define OFF_OUT1   (OFF_ATT  + (long)PB*PH*PN1*PN2)
#define OFF_OUT2   (OFF_OUT1 + (long)PB*PN1*PH*PDV)
#define OFF_X4     (OFF_OUT2 + (long)PB*PN2*PH*PDV)
#define OFF_Y4     (OFF_X4   + (long)PB*PN1*PD)
#define OFF_HID    (OFF_Y4   + (long)PB*PN2*PD)
#define SCRATCH_TOTAL (OFF_HID + (long)PB*PN1*PDFF)

__device__ float g_scratch[SCRATCH_TOTAL];

// =================== mma helpers ===================
__device__ __forceinline__ uint32_t sptr(const void* p) {
    return (uint32_t)__cvta_generic_to_shared(p);
}
__device__ __forceinline__ void ldsm4(uint32_t r[4], const __nv_bfloat16* p) {
    uint32_t a = sptr(p);
    asm volatile("ldmatrix.sync.aligned.m8n8.x4.shared.b16 {%0,%1,%2,%3}, [%4];"
                 : "=r"(r[0]), "=r"(r[1]), "=r"(r[2]), "=r"(r[3]) : "r"(a));
}
__device__ __forceinline__ void mma16816(float c[4], const uint32_t a[4], const uint32_t b[2]) {
    asm volatile(
        "mma.sync.aligned.m16n8k16.row.col.f32.bf16.bf16.f32 "
        "{%0,%1,%2,%3}, {%4,%5,%6,%7}, {%8,%9}, {%0,%1,%2,%3};"
        : "+f"(c[0]), "+f"(c[1]), "+f"(c[2]), "+f"(c[3])
        : "r"(a[0]), "r"(a[1]), "r"(a[2]), "r"(a[3]), "r"(b[0]), "r"(b[1]));
}
// split x into hi+lo bf16; pack pairs
__device__ __forceinline__ uint32_t pack2(float a, float b, uint32_t& lo) {
    __nv_bfloat16 ha = __float2bfloat16(a), hb = __float2bfloat16(b);
    __nv_bfloat16 la = __float2bfloat16(a - __bfloat162float(ha));
    __nv_bfloat16 lb = __float2bfloat16(b - __bfloat162float(hb));
    lo = ((uint32_t)__bfloat16_as_ushort(lb) << 16) | (uint32_t)__bfloat16_as_ushort(la);
    return ((uint32_t)__bfloat16_as_ushort(hb) << 16) | (uint32_t)__bfloat16_as_ushort(ha);
}
__device__ __forceinline__ void bsplit(float x, __nv_bfloat16& h, __nv_bfloat16& l) {
    h = __float2bfloat16(x);
    l = __float2bfloat16(x - __bfloat162float(h));
}

// =================== bf16x3 HMMA GEMM ===================
// CTA tile 128x128, BK=32, 8 warps (4 along m, 2 along n), warp tile 32x64.
// Double-buffered smem + register prefetch of the next K-slab.
// Requires: M % 128 == 0, K % 32 == 0 (true for all calls). N guarded.
#define SA 40            // padded smem k-stride in halfwords (bank-conflict-free)
#define TSZ (128 * SA)   // halfwords per matrix per stage
#define GSMEM (2 * 4 * TSZ * 2)   // bytes: 2 stages x {Ah,Al,Bh,Bl} x 128x40 bf16

template <bool TA, bool TB>
__global__ __launch_bounds__(256) void gemm_k(
    const float* __restrict__ A, const float* __restrict__ B,
    const float* __restrict__ bias, const float* __restrict__ Res,
    float* __restrict__ C,
    int M, int N, int K, int lda, int ldb, int ldc,
    long sAb, long sAh, long sBb, long sBh, long sCb, long sCh, int Hn,
    float alpha, int doRelu)
{
    int z = blockIdx.z;
    int bb = z / Hn, hh = z % Hn;
    A += bb * sAb + hh * sAh;
    B += bb * sBb + hh * sBh;
    C += bb * sCb + hh * sCh;
    if (Res) Res += bb * sCb + hh * sCh;

    extern __shared__ __nv_bfloat16 smem[];

    int m0 = blockIdx.y * 128;
    int n0 = blockIdx.x * 128;
    int tid = threadIdx.x, w = tid >> 5, lane = tid & 31;
    int wm = (w & 3) * 32;    // warp m-offset
    int wn = (w >> 2) * 64;   // warp n-offset

    float acc[2][8][4];
    #pragma unroll
    for (int f = 0; f < 2; f++)
        #pragma unroll
        for (int g = 0; g < 8; g++)
            #pragma unroll
            for (int e = 0; e < 4; e++) acc[f][g][e] = 0.f;

    float4 ra[4], rb[4];
    int nk = K >> 5;

    // ---- loaders: GMEM -> regs ----
    auto ldA = [&](int s) {
        int k0 = s << 5;
        if (!TA) {
            #pragma unroll
            for (int i = 0; i < 4; i++) {
                int idx = tid + i * 256;
                int m = idx >> 3, kq = (idx & 7) << 2;
                ra[i] = *(const float4*)(A + (long)(m0 + m) * lda + k0 + kq);
            }
        } else {
            #pragma unroll
            for (int i = 0; i < 4; i++) {
                int idx = tid + i * 256;
                int k = idx >> 5, mq = (idx & 31) << 2;
                ra[i] = *(const float4*)(A + (long)(k0 + k) * lda + m0 + mq);
            }
        }
    };
    auto ldB = [&](int s) {
        int k0 = s << 5;
        if (TB) {
            #pragma unroll
            for (int i = 0; i < 4; i++) {
                int idx = tid + i * 256;
                int n = idx >> 3, kq = (idx & 7) << 2;
                if (n0 + n < N)
                    rb[i] = *(const float4*)(B + (long)(n0 + n) * ldb + k0 + kq);
                else
                    rb[i] = make_float4(0.f, 0.f, 0.f, 0.f);
            }
        } else {
            #pragma unroll
            for (int i = 0; i < 4; i++) {
                int idx = tid + i * 256;
                int k = idx >> 5, nq = (idx & 31) << 2;
                int nb = n0 + nq;
                if (nb + 3 < N) {
                    rb[i] = *(const float4*)(B + (long)(k0 + k) * ldb + nb);
                } else {
                    rb[i] = make_float4(0.f, 0.f, 0.f, 0.f);
                    const float* bp = B + (long)(k0 + k) * ldb;
                    if (nb + 0 < N) rb[i].x = bp[nb + 0];
                    if (nb + 1 < N) rb[i].y = bp[nb + 1];
                    if (nb + 2 < N) rb[i].z = bp[nb + 2];
                }
            }
        }
    };
    // ---- regs -> smem (hi/lo split) ----
    auto stAB = [&](int buf) {
        __nv_bfloat16* Ah = smem + buf * 4 * TSZ;
        __nv_bfloat16* Al = Ah + TSZ;
        __nv_bfloat16* Bh = Ah + 2 * TSZ;
        __nv_bfloat16* Bl = Ah + 3 * TSZ;
        if (!TA) {
            #pragma unroll
            for (int i = 0; i < 4; i++) {
                int idx = tid + i * 256;
                int m = idx >> 3, kq = (idx & 7) << 2;
                uint32_t l0, l1;
                uint32_t h0 = pack2(ra[i].x, ra[i].y, l0);
                uint32_t h1 = pack2(ra[i].z, ra[i].w, l1);
                int off = m * SA + kq;
                *(uint2*)(Ah + off) = make_uint2(h0, h1);
                *(uint2*)(Al + off) = make_uint2(l0, l1);
            }
        } else {
            #pragma unroll
            for (int i = 0; i < 4; i++) {
                int idx = tid + i * 256;
                int k = idx >> 5, mq = (idx & 31) << 2;
                float vv[4] = { ra[i].x, ra[i].y, ra[i].z, ra[i].w };
                #pragma unroll
                for (int j = 0; j < 4; j++) {
                    __nv_bfloat16 h, l;
                    bsplit(vv[j], h, l);
                    Ah[(mq + j) * SA + k] = h;
                    Al[(mq + j) * SA + k] = l;
                }
            }
        }
        if (TB) {
            #pragma unroll
            for (int i = 0; i < 4; i++) {
                int idx = tid + i * 256;
                int n = idx >> 3, kq = (idx & 7) << 2;
                uint32_t l0, l1;
                uint32_t h0 = pack2(rb[i].x, rb[i].y, l0);
                uint32_t h1 = pack2(rb[i].z, rb[i].w, l1);
                int off = n * SA + kq;
                *(uint2*)(Bh + off) = make_uint2(h0, h1);
                *(uint2*)(Bl + off) = make_uint2(l0, l1);
            }
        } else {
            #pragma unroll
            for (int i = 0; i < 4; i++) {
                int idx = tid + i * 256;
                int k = idx >> 5, nq = (idx & 31) << 2;
                float vv[4] = { rb[i].x, rb[i].y, rb[i].z, rb[i].w };
                #pragma unroll
                for (int j = 0; j < 4; j++) {
                    __nv_bfloat16 h, l;
                    bsplit(vv[j], h, l);
                    Bh[(nq + j) * SA + k] = h;
                    Bl[(nq + j) * SA + k] = l;
                }
            }
        }
    };

    // ---- pipeline ----
    ldA(0); ldB(0);
    stAB(0);
    __syncthreads();

    for (int s = 0; s < nk; s++) {
        if (s + 1 < nk) { ldA(s + 1); ldB(s + 1); }

        const __nv_bfloat16* Ah = smem + (s & 1) * 4 * TSZ;
        const __nv_bfloat16* Al = Ah + TSZ;
        const __nv_bfloat16* Bh = Ah + 2 * TSZ;
        const __nv_bfloat16* Bl = Ah + 3 * TSZ;

        #pragma unroll
        for (int kk = 0; kk < 32; kk += 16) {
            uint32_t ah[2][4], al[2][4];
            #pragma unroll
            for (int f = 0; f < 2; f++) {
                int r = wm + f * 16 + (lane & 15);
                int c = kk + ((lane >> 4) << 3);
                ldsm4(ah[f], Ah + r * SA + c);
                ldsm4(al[f], Al + r * SA + c);
            }
            uint32_t bh[8][2], bl[8][2];
            #pragma unroll
            for (int gp = 0; gp < 4; gp++) {
                int r = wn + gp * 16 + (lane & 7) + ((lane >> 4) << 3);
                int c = kk + (((lane >> 3) & 1) << 3);
                uint32_t t[4];
                ldsm4(t, Bh + r * SA + c);
                bh[2*gp][0] = t[0]; bh[2*gp][1] = t[1];
                bh[2*gp+1][0] = t[2]; bh[2*gp+1][1] = t[3];
                ldsm4(t, Bl + r * SA + c);
                bl[2*gp][0] = t[0]; bl[2*gp][1] = t[1];
                bl[2*gp+1][0] = t[2]; bl[2*gp+1][1] = t[3];
            }
            #pragma unroll
            for (int f = 0; f < 2; f++)
                #pragma unroll
                for (int g = 0; g < 8; g++) {
                    mma16816(acc[f][g], ah[f], bh[g]);
                    mma16816(acc[f][g], al[f], bh[g]);
                    mma16816(acc[f][g], ah[f], bl[g]);
                }
        }
        __syncthreads();
        if (s + 1 < nk) {
            stAB((s + 1) & 1);
            __syncthreads();
        }
    }

    // ---- epilogue ----
    int gid = lane >> 2, tg = lane & 3;
    #pragma unroll
    for (int f = 0; f < 2; f++) {
        #pragma unroll
        for (int g = 0; g < 8; g++) {
            int r0 = m0 + wm + f * 16 + gid;
            int c0 = n0 + wn + g * 8 + tg * 2;
            #pragma unroll
            for (int e = 0; e < 4; e++) {
                int r = r0 + ((e >> 1) << 3);
                int c = c0 + (e & 1);
                if (c >= N) continue;
                float v = acc[f][g][e] * alpha;
                if (bias) v += bias[c];
                if (Res)  v += Res[(long)r * ldc + c];
                if (doRelu) v = fmaxf(v, 0.f);
                C[(long)r * ldc + c] = v;
            }
        }
    }
}

// ---------------- LayerNorm ----------------
__device__ __forceinline__ float warpSum(float v) {
    #pragma unroll
    for (int o = 16; o; o >>= 1) v += __shfl_xor_sync(0xffffffffu, v, o);
    return v;
}
__device__ __forceinline__ float warpMax(float v) {
    #pragma unroll
    for (int o = 16; o; o >>= 1) v = fmaxf(v, __shfl_xor_sync(0xffffffffu, v, o));
    return v;
}

__global__ __launch_bounds__(256) void ln_k(const float* __restrict__ X,
                                            const float* __restrict__ g,
                                            const float* __restrict__ bta,
                                            float* __restrict__ Y)
{
    long row = blockIdx.x;
    const float* xr = X + row * PD;
    float* yr = Y + row * PD;
    int t = threadIdx.x, lane = t & 31, wid = t >> 5;

    float s1 = 0.f, s2 = 0.f;
    for (int c = t; c < PD; c += 256) { float v = xr[c]; s1 += v; s2 += v * v; }
    s1 = warpSum(s1); s2 = warpSum(s2);
    __shared__ float sA[8], sB[8];
    if (lane == 0) { sA[wid] = s1; sB[wid] = s2; }
    __syncthreads();
    float t1 = 0.f, t2 = 0.f;
    #pragma unroll
    for (int wI = 0; wI < 8; wI++) { t1 += sA[wI]; t2 += sB[wI]; }
    float mean = t1 / (float)PD;
    float var  = t2 / (float)PD - mean * mean;
    float rs = rsqrtf(var + 1e-5f);
    for (int c = t; c < PD; c += 256)
        yr[c] = (xr[c] - mean) * rs * g[c] + bta[c];
}

// ---------------- Enformer positional features ----------------
__global__ void pos_k(float* __restrict__ pos)
{
    int m = blockIdx.x * blockDim.x + threadIdx.x;
    if (m >= PMQ) return;
    float d = (float)(m - (PN1 - 1));
    float ad = fabsf(d);

    float fe[16], fc[16], fg[16];
    float pmax = 0.f;
    const float ln2 = 0.6931471805599453f;
    #pragma unroll
    for (int i = 0; i < 16; i++) {
        float e = 3.0f + 8.0f * (float)i / 15.0f;
        float hl = exp2f(e);
        fe[i] = expf(-ln2 / hl * ad);
        float cw = exp2f((float)(i + 1)) - 1.0f;
        fc[i] = (cw > ad) ? 1.0f : 0.0f;
        float mean = 128.0f * (float)(i + 1);
        float conc = (mean / 64.0f) * (mean / 64.0f);
        float rate = mean / 4096.0f;
        float logp = (conc - 1.0f) * logf(ad) - rate * ad
                   - (lgammaf(conc) - conc * logf(rate));
        float prob = expf(logp) + 1e-8f;
        fg[i] = prob;
        pmax = fmaxf(pmax, prob);
    }
    float sgn = (d > 0.f) ? 1.f : ((d < 0.f) ? -1.f : 0.f);
    float inv = 1.0f / pmax;
    float* row = pos + (long)m * PNRP;
    #pragma unroll
    for (int i = 0; i < 16; i++) {
        float gv = fg[i] * inv;
        row[i]      = fe[i];
        row[16 + i] = fc[i];
        row[32 + i] = gv;
        row[48 + i] = sgn * fe[i];
        row[64 + i] = sgn * fc[i];
        row[80 + i] = sgn * gv;
    }
}

// ---------------- kb = k * SCALE + rel_pos_bias ----------------
__global__ void kb_k(const float* __restrict__ k, const float* __restrict__ rpb,
                     float* __restrict__ kb, int total)
{
    for (int i = blockIdx.x * blockDim.x + threadIdx.x; i < total;
         i += gridDim.x * blockDim.x)
        kb[i] = k[i] * PSCALE + rpb[i & 511];
}

// ---------------- fused rel-shift gather + softmax ----------------
__global__ __launch_bounds__(128) void softmax_k(float* __restrict__ att,
                                                 const float* __restrict__ rel)
{
    int i = blockIdx.x;
    long z = blockIdx.y;
    float* row = att + (z * PN1 + i) * (long)PN2;
    const float* relz = rel + z * (long)PN2 * PMQ;
    int t = threadIdx.x, lane = t & 31, wid = t >> 5;

    float v[4];
    float mx = -1e30f;
    #pragma unroll
    for (int u = 0; u < 4; u++) {
        int j = t + u * 128;
        float val = row[j] + relz[(long)j * PMQ + (i + (PN2 - 1) - j)];
        v[u] = val;
        mx = fmaxf(mx, val);
    }
    __shared__ float sh[4];
    mx = warpMax(mx);
    if (lane == 0) sh[wid] = mx;
    __syncthreads();
    float gmx = fmaxf(fmaxf(sh[0], sh[1]), fmaxf(sh[2], sh[3]));
    __syncthreads();

    float s = 0.f;
    #pragma unroll
    for (int u = 0; u < 4; u++) { v[u] = expf(v[u] - gmx); s += v[u]; }
    s = warpSum(s);
    if (lane == 0) sh[wid] = s;
    __syncthreads();
    float gs = sh[0] + sh[1] + sh[2] + sh[3];
    float inv = 1.0f / gs;
    #pragma unroll
    for (int u = 0; u < 4; u++) row[t + u * 128] = v[u] * inv;
}

// ---------------- host orchestration ----------------
static inline dim3 gg(int M, int N, int Z) {
    return dim3((unsigned)((N + 127) / 128), (unsigned)(M / 128), (unsigned)Z);
}

extern "C" void kernel_launch(void* const* d_in, const int* in_sizes, int n_in,
                              void* d_out, int out_size)
{
    const float* x     = (const float*)d_in[0];
    const float* y0    = (const float*)d_in[1];
    const float* W_res = (const float*)d_in[2];
    const float* lnx_g = (const float*)d_in[3];
    const float* lnx_b = (const float*)d_in[4];
    const float* lny_g = (const float*)d_in[5];
    const float* lny_b = (const float*)d_in[6];
    const float* Wq    = (const float*)d_in[7];
    const float* Wk    = (const float*)d_in[8];
    const float* Wv1   = (const float*)d_in[9];
    const float* Wv2   = (const float*)d_in[10];
    const float* Wo1   = (const float*)d_in[11];
    const float* bo1   = (const float*)d_in[12];
    const float* Wo2   = (const float*)d_in[13];
    const float* bo2   = (const float*)d_in[14];
    const float* Wrel  = (const float*)d_in[15];
    const float* rpb   = (const float*)d_in[16];
    const float* fx_g  = (const float*)d_in[17];
    const float* fx_b  = (const float*)d_in[18];
    const float* fx_w1 = (const float*)d_in[19];
    const float* fx_b1 = (const float*)d_in[20];
    const float* fx_w2 = (const float*)d_in[21];
    const float* fx_b2 = (const float*)d_in[22];
    const float* fy_g  = (const float*)d_in[23];
    const float* fy_b  = (const float*)d_in[24];
    const float* fy_w1 = (const float*)d_in[25];
    const float* fy_b1 = (const float*)d_in[26];
    const float* fy_w2 = (const float*)d_in[27];
    const float* fy_b2 = (const float*)d_in[28];

    // opt-in to >48KB dynamic smem (idempotent host API; capture-safe)
    cudaFuncSetAttribute(gemm_k<false, false>,
                         cudaFuncAttributeMaxDynamicSharedMemorySize, GSMEM);
    cudaFuncSetAttribute(gemm_k<false, true>,
                         cudaFuncAttributeMaxDynamicSharedMemorySize, GSMEM);
    cudaFuncSetAttribute(gemm_k<true, false>,
                         cudaFuncAttributeMaxDynamicSharedMemorySize, GSMEM);

    float* S = nullptr;
    cudaGetSymbolAddress((void**)&S, g_scratch);
    float* gy   = S + OFF_Y;
    float* gx1  = S + OFF_X1;
    float* gy1  = S + OFF_Y1;
    float* gq   = S + OFF_Q;
    float* gk   = S + OFF_K;
    float* gkb  = S + OFF_KB;
    float* gv1  = S + OFF_V1;
    float* gv2  = S + OFF_V2;
    float* gpos = S + OFF_POS;
    float* grq  = S + OFF_RELQ;
    float* grel = S + OFF_REL;
    float* gatt = S + OFF_ATT;
    float* go1  = S + OFF_OUT1;
    float* go2  = S + OFF_OUT2;
    float* gx4  = S + OFF_X4;
    float* gy4  = S + OFF_Y4;
    float* gh   = S + OFF_HID;

    float* outx = (float*)d_out;
    float* outy = outx + (long)PB * PN1 * PD;

    const int HDK = PH * PDK;   // 512
    const int HDV = PH * PDV;   // 768

    // x1 = LN(x), y = y0 @ W_res, y1 = LN(y)
    ln_k<<<PB * PN1, 256>>>(x, lnx_g, lnx_b, gx1);
    gemm_k<false, false><<<gg(PB*PN2, PD, 1), 256, GSMEM>>>(
        y0, W_res, nullptr, nullptr, gy,
        PB*PN2, PD, PDY0, PDY0, PD, PD, 0,0,0,0,0,0, 1, 1.f, 0);
    ln_k<<<PB * PN2, 256>>>(gy, lny_g, lny_b, gy1);

    // q, k, v2, v1 projections
    gemm_k<false, false><<<gg(PB*PN1, HDK, 1), 256, GSMEM>>>(
        gx1, Wq, nullptr, nullptr, gq,
        PB*PN1, HDK, PD, PD, HDK, HDK, 0,0,0,0,0,0, 1, 1.f, 0);
    gemm_k<false, false><<<gg(PB*PN2, HDK, 1), 256, GSMEM>>>(
        gy1, Wk, nullptr, nullptr, gk,
        PB*PN2, HDK, PD, PD, HDK, HDK, 0,0,0,0,0,0, 1, 1.f, 0);
    gemm_k<false, false><<<gg(PB*PN2, HDV, 1), 256, GSMEM>>>(
        gy1, Wv2, nullptr, nullptr, gv2,
        PB*PN2, HDV, PD, PD, HDV, HDV, 0,0,0,0,0,0, 1, 1.f, 0);
    gemm_k<false, false><<<gg(PB*PN1, HDV, 1), 256, GSMEM>>>(
        gx1, Wv1, nullptr, nullptr, gv1,
        PB*PN1, HDV, PD, PD, HDV, HDV, 0,0,0,0,0,0, 1, 1.f, 0);

    // positional features + rel_q = pos @ Wrel (only m < PMQ needed)
    pos_k<<<(PMQ + 127) / 128, 128>>>(gpos);
    gemm_k<false, false><<<gg(PMQ, HDK, 1), 256, GSMEM>>>(
        gpos, Wrel, nullptr, nullptr, grq,
        PMQ, HDK, PNRP, PNRP, HDK, HDK, 0,0,0,0,0,0, 1, 1.f, 0);

    // kb = k * SCALE + rel_pos_bias
    kb_k<<<2048, 256>>>(gk, rpb, gkb, PB*PN2*HDK);

    // content logits = SCALE * q @ k^T   (batched over b,h; NT)
    gemm_k<false, true><<<gg(PN1, PN2, PB*PH), 256, GSMEM>>>(
        gq, gk, nullptr, nullptr, gatt,
        PN1, PN2, PDK, HDK, HDK, PN2,
        (long)PN1*HDK, PDK, (long)PN2*HDK, PDK,
        (long)PH*PN1*PN2, (long)PN1*PN2, PH, PSCALE, 0);

    // rel = kb @ rel_q^T  (batched; rel_q shared across b -> sBb = 0)
    gemm_k<false, true><<<gg(PN2, PMQ, PB*PH), 256, GSMEM>>>(
        gkb, grq, nullptr, nullptr, grel,
        PN2, PMQ, PDK, HDK, HDK, PMQ,
        (long)PN2*HDK, PDK, 0L, PDK,
        (long)PH*PN2*PMQ, (long)PN2*PMQ, PH, 1.f, 0);

    // fused rel-shift gather + softmax (in place over gatt)
    softmax_k<<<dim3(PN1, PB*PH), 128>>>(gatt, grel);

    // out1 = attn @ v2   (batched NN)
    gemm_k<false, false><<<gg(PN1, PDV, PB*PH), 256, GSMEM>>>(
        gatt, gv2, nullptr, nullptr, go1,
        PN1, PDV, PN2, PN2, HDV, HDV,
        (long)PH*PN1*PN2, (long)PN1*PN2, (long)PN2*HDV, PDV,
        (long)PN1*HDV, PDV, PH, 1.f, 0);

    // out2 = attn^T @ v1 (batched TN)
    gemm_k<true, false><<<gg(PN2, PDV, PB*PH), 256, GSMEM>>>(
        gatt, gv1, nullptr, nullptr, go2,
        PN2, PDV, PN1, PN2, HDV, HDV,
        (long)PH*PN1*PN2, (long)PN1*PN2, (long)PN1*HDV, PDV,
        (long)PN2*HDV, PDV, PH, 1.f, 0);

    // x4 = x + out1 @ Wo1 + bo1 ;  y4 = y + out2 @ Wo2 + bo2
    gemm_k<false, false><<<gg(PB*PN1, PD, 1), 256, GSMEM>>>(
        go1, Wo1, bo1, x, gx4,
        PB*PN1, PD, HDV, HDV, PD, PD, 0,0,0,0,0,0, 1, 1.f, 0);
    gemm_k<false, false><<<gg(PB*PN2, PD, 1), 256, GSMEM>>>(
        go2, Wo2, bo2, gy, gy4,
        PB*PN2, PD, HDV, HDV, PD, PD, 0,0,0,0,0,0, 1, 1.f, 0);

    // FFN x: x5 = x4 + relu(LN(x4) @ w1 + b1) @ w2 + b2  -> outx
    ln_k<<<PB * PN1, 256>>>(gx4, fx_g, fx_b, gx1);
    gemm_k<false, false><<<gg(PB*PN1, PDFF, 1), 256, GSMEM>>>(
        gx1, fx_w1, fx_b1, nullptr, gh,
        PB*PN1, PDFF, PD, PD, PDFF, PDFF, 0,0,0,0,0,0, 1, 1.f, 1);
    gemm_k<false, false><<<gg(PB*PN1, PD, 1), 256, GSMEM>>>(
        gh, fx_w2, fx_b2, gx4, outx,
        PB*PN1, PD, PDFF, PDFF, PD, PD, 0,0,0,0,0,0, 1, 1.f, 0);

    // FFN y -> outy
    ln_k<<<PB * PN2, 256>>>(gy4, fy_g, fy_b, gy1);
    gemm_k<false, false><<<gg(PB*PN2, PDFF, 1), 256, GSMEM>>>(
        gy1, fy_w1, fy_b1, nullptr, gh,
        PB*PN2, PDFF, PD, PD, PDFF, PDFF, 0,0,0,0,0,0, 1, 1.f, 1);
    gemm_k<false, false><<<gg(PB*PN2, PD, 1), 256, GSMEM>>>(
        gh, fy_w2, fy_b2, gy4, outy,
        PB*PN2, PD, PDFF, PDFF, PD, PD, 0,0,0,0,0,0, 1, 1.f, 0);

    (void)in_sizes; (void)n_in; (void)out_size;
}

// round 6
// speedup vs baseline: 1.0449x; 1.0449x over previous
#include <cuda_runtime.h>
#include <cuda_bf16.h>
#include <cstdint>
#include <math.h>

// ---------------- problem constants ----------------
#define PB   4
#define PN1  2048
#define PN2  512
#define PD   768
#define PH   8
#define PDK  64
#define PDV  96
#define PNRP 96
#define PDY0 1536
#define PDFF 1536
#define PMQ  2560              // needed pos rows: m = i - j + 511 in [0, 2558]
#define PSCALE 0.125f          // DK^-0.5

// ---------------- scratch layout (floats) ----------------
#define OFF_Y      0L
#define OFF_X1     (OFF_Y    + (long)PB*PN2*PD)
#define OFF_Y1     (OFF_X1   + (long)PB*PN1*PD)
#define OFF_Q      (OFF_Y1   + (long)PB*PN2*PD)
#define OFF_K      (OFF_Q    + (long)PB*PN1*PH*PDK)
#define OFF_KB     (OFF_K    + (long)PB*PN2*PH*PDK)
#define OFF_V1     (OFF_KB   + (long)PB*PN2*PH*PDK)
#define OFF_V2     (OFF_V1   + (long)PB*PN1*PH*PDV)
#define OFF_POS    (OFF_V2   + (long)PB*PN2*PH*PDV)
#define OFF_RELQ   (OFF_POS  + (long)PMQ*PNRP)
#define OFF_REL    (OFF_RELQ + (long)PMQ*PH*PDK)
#define OFF_ATT    (OFF_REL  + (long)PB*PH*PN2*PMQ)
#define OFF_OUT1   (OFF_ATT  + (long)PB*PH*PN1*PN2)
#define OFF_OUT2   (OFF_OUT1 + (long)PB*PN1*PH*PDV)
#define OFF_X4     (OFF_OUT2 + (long)PB*PN2*PH*PDV)
#define OFF_Y4     (OFF_X4   + (long)PB*PN1*PD)
#define OFF_HID    (OFF_Y4   + (long)PB*PN2*PD)
#define SCRATCH_TOTAL (OFF_HID + (long)PB*PN1*PDFF)

__device__ float g_scratch[SCRATCH_TOTAL];

// =================== mma helpers ===================
__device__ __forceinline__ uint32_t sptr(const void* p) {
    return (uint32_t)__cvta_generic_to_shared(p);
}
__device__ __forceinline__ void ldsm4(uint32_t r[4], const __nv_bfloat16* p) {
    uint32_t a = sptr(p);
    asm volatile("ldmatrix.sync.aligned.m8n8.x4.shared.b16 {%0,%1,%2,%3}, [%4];"
                 : "=r"(r[0]), "=r"(r[1]), "=r"(r[2]), "=r"(r[3]) : "r"(a));
}
__device__ __forceinline__ void mma16816(float c[4], const uint32_t a[4], const uint32_t b0, const uint32_t b1) {
    asm volatile(
        "mma.sync.aligned.m16n8k16.row.col.f32.bf16.bf16.f32 "
        "{%0,%1,%2,%3}, {%4,%5,%6,%7}, {%8,%9}, {%0,%1,%2,%3};"
        : "+f"(c[0]), "+f"(c[1]), "+f"(c[2]), "+f"(c[3])
        : "r"(a[0]), "r"(a[1]), "r"(a[2]), "r"(a[3]), "r"(b0), "r"(b1));
}
// split x into hi+lo bf16; pack pairs
__device__ __forceinline__ uint32_t pack2(float a, float b, uint32_t& lo) {
    __nv_bfloat16 ha = __float2bfloat16(a), hb = __float2bfloat16(b);
    __nv_bfloat16 la = __float2bfloat16(a - __bfloat162float(ha));
    __nv_bfloat16 lb = __float2bfloat16(b - __bfloat162float(hb));
    lo = ((uint32_t)__bfloat16_as_ushort(lb) << 16) | (uint32_t)__bfloat16_as_ushort(la);
    return ((uint32_t)__bfloat16_as_ushort(hb) << 16) | (uint32_t)__bfloat16_as_ushort(ha);
}
__device__ __forceinline__ void bsplit(float x, __nv_bfloat16& h, __nv_bfloat16& l) {
    h = __float2bfloat16(x);
    l = __float2bfloat16(x - __bfloat162float(h));
}

// =================== bf16x3 HMMA GEMM ===================
// CTA tile 128x128, BK=32, 8 warps (4 along m, 2 along n), warp tile 32x64.
// Single smem stage (40KB) + register prefetch of the next K-slab.
// __launch_bounds__(256,2) keeps regs <=128 so 2 CTAs co-reside per SM.
// Requires: M % 128 == 0, K % 32 == 0 (true for all calls). N guarded.
#define SA 40            // padded smem k-stride in halfwords (bank-conflict-free)
#define TSZ (128 * SA)   // halfwords per matrix
#define GSMEM (4 * TSZ * 2)   // bytes: {Ah,Al,Bh,Bl} x 128x40 bf16 = 40960

template <bool TA, bool TB>
__global__ __launch_bounds__(256, 2) void gemm_k(
    const float* __restrict__ A, const float* __restrict__ B,
    const float* __restrict__ bias, const float* __restrict__ Res,
    float* __restrict__ C,
    int M, int N, int K, int lda, int ldb, int ldc,
    long sAb, long sAh, long sBb, long sBh, long sCb, long sCh, int Hn,
    float alpha, int doRelu)
{
    int z = blockIdx.z;
    int bb = z / Hn, hh = z % Hn;
    A += bb * sAb + hh * sAh;
    B += bb * sBb + hh * sBh;
    C += bb * sCb + hh * sCh;
    if (Res) Res += bb * sCb + hh * sCh;

    extern __shared__ __nv_bfloat16 smem[];
    __nv_bfloat16* sAh_ = smem;
    __nv_bfloat16* sAl_ = smem + TSZ;
    __nv_bfloat16* sBh_ = smem + 2 * TSZ;
    __nv_bfloat16* sBl_ = smem + 3 * TSZ;

    int m0 = blockIdx.y * 128;
    int n0 = blockIdx.x * 128;
    int tid = threadIdx.x, w = tid >> 5, lane = tid & 31;
    int wm = (w & 3) * 32;    // warp m-offset
    int wn = (w >> 2) * 64;   // warp n-offset

    float acc[2][8][4];
    #pragma unroll
    for (int f = 0; f < 2; f++)
        #pragma unroll
        for (int g = 0; g < 8; g++)
            #pragma unroll
            for (int e = 0; e < 4; e++) acc[f][g][e] = 0.f;

    float4 ra[4], rb[4];
    int nk = K >> 5;

    // ---- loaders: GMEM -> regs ----
    auto ldA = [&](int s) {
        int k0 = s << 5;
        if (!TA) {
            #pragma unroll
            for (int i = 0; i < 4; i++) {
                int idx = tid + i * 256;
                int m = idx >> 3, kq = (idx & 7) << 2;
                ra[i] = *(const float4*)(A + (long)(m0 + m) * lda + k0 + kq);
            }
        } else {
            #pragma unroll
            for (int i = 0; i < 4; i++) {
                int idx = tid + i * 256;
                int k = idx >> 5, mq = (idx & 31) << 2;
                ra[i] = *(const float4*)(A + (long)(k0 + k) * lda + m0 + mq);
            }
        }
    };
    auto ldB = [&](int s) {
        int k0 = s << 5;
        if (TB) {
            #pragma unroll
            for (int i = 0; i < 4; i++) {
                int idx = tid + i * 256;
                int n = idx >> 3, kq = (idx & 7) << 2;
                if (n0 + n < N)
                    rb[i] = *(const float4*)(B + (long)(n0 + n) * ldb + k0 + kq);
                else
                    rb[i] = make_float4(0.f, 0.f, 0.f, 0.f);
            }
        } else {
            #pragma unroll
            for (int i = 0; i < 4; i++) {
                int idx = tid + i * 256;
                int k = idx >> 5, nq = (idx & 31) << 2;
                int nb = n0 + nq;
                if (nb + 3 < N) {
                    rb[i] = *(const float4*)(B + (long)(k0 + k) * ldb + nb);
                } else {
                    rb[i] = make_float4(0.f, 0.f, 0.f, 0.f);
                    const float* bp = B + (long)(k0 + k) * ldb;
                    if (nb + 0 < N) rb[i].x = bp[nb + 0];
                    if (nb + 1 < N) rb[i].y = bp[nb + 1];
                    if (nb + 2 < N) rb[i].z = bp[nb + 2];
                }
            }
        }
    };
    // ---- regs -> smem (hi/lo split) ----
    auto stAB = [&]() {
        if (!TA) {
            #pragma unroll
            for (int i = 0; i < 4; i++) {
                int idx = tid + i * 256;
                int m = idx >> 3, kq = (idx & 7) << 2;
                uint32_t l0, l1;
                uint32_t h0 = pack2(ra[i].x, ra[i].y, l0);
                uint32_t h1 = pack2(ra[i].z, ra[i].w, l1);
                int off = m * SA + kq;
                *(uint2*)(sAh_ + off) = make_uint2(h0, h1);
                *(uint2*)(sAl_ + off) = make_uint2(l0, l1);
            }
        } else {
            #pragma unroll
            for (int i = 0; i < 4; i++) {
                int idx = tid + i * 256;
                int k = idx >> 5, mq = (idx & 31) << 2;
                float vv[4] = { ra[i].x, ra[i].y, ra[i].z, ra[i].w };
                #pragma unroll
                for (int j = 0; j < 4; j++) {
                    __nv_bfloat16 h, l;
                    bsplit(vv[j], h, l);
                    sAh_[(mq + j) * SA + k] = h;
                    sAl_[(mq + j) * SA + k] = l;
                }
            }
        }
        if (TB) {
            #pragma unroll
            for (int i = 0; i < 4; i++) {
                int idx = tid + i * 256;
                int n = idx >> 3, kq = (idx & 7) << 2;
                uint32_t l0, l1;
                uint32_t h0 = pack2(rb[i].x, rb[i].y, l0);
                uint32_t h1 = pack2(rb[i].z, rb[i].w, l1);
                int off = n * SA + kq;
                *(uint2*)(sBh_ + off) = make_uint2(h0, h1);
                *(uint2*)(sBl_ + off) = make_uint2(l0, l1);
            }
        } else {
            #pragma unroll
            for (int i = 0; i < 4; i++) {
                int idx = tid + i * 256;
                int k = idx >> 5, nq = (idx & 31) << 2;
                float vv[4] = { rb[i].x, rb[i].y, rb[i].z, rb[i].w };
                #pragma unroll
                for (int j = 0; j < 4; j++) {
                    __nv_bfloat16 h, l;
                    bsplit(vv[j], h, l);
                    sBh_[(nq + j) * SA + k] = h;
                    sBl_[(nq + j) * SA + k] = l;
                }
            }
        }
    };

    // ---- pipeline: load(0), store(0), then loop ----
    ldA(0); ldB(0);
    stAB();
    __syncthreads();

    for (int s = 0; s < nk; s++) {
        if (s + 1 < nk) { ldA(s + 1); ldB(s + 1); }

        #pragma unroll
        for (int kk = 0; kk < 32; kk += 16) {
            uint32_t ah[2][4], al[2][4];
            #pragma unroll
            for (int f = 0; f < 2; f++) {
                int r = wm + f * 16 + (lane & 15);
                int c = kk + ((lane >> 4) << 3);
                ldsm4(ah[f], sAh_ + r * SA + c);
                ldsm4(al[f], sAl_ + r * SA + c);
            }
            // process B in 4 groups of n16 to keep live registers low
            #pragma unroll
            for (int gp = 0; gp < 4; gp++) {
                int r = wn + gp * 16 + (lane & 7) + ((lane >> 4) << 3);
                int c = kk + (((lane >> 3) & 1) << 3);
                uint32_t th[4], tl[4];
                ldsm4(th, sBh_ + r * SA + c);
                ldsm4(tl, sBl_ + r * SA + c);
                #pragma unroll
                for (int f = 0; f < 2; f++) {
                    mma16816(acc[f][2*gp],   ah[f], th[0], th[1]);
                    mma16816(acc[f][2*gp],   al[f], th[0], th[1]);
                    mma16816(acc[f][2*gp],   ah[f], tl[0], tl[1]);
                    mma16816(acc[f][2*gp+1], ah[f], th[2], th[3]);
                    mma16816(acc[f][2*gp+1], al[f], th[2], th[3]);
                    mma16816(acc[f][2*gp+1], ah[f], tl[2], tl[3]);
                }
            }
        }
        __syncthreads();
        if (s + 1 < nk) {
            stAB();
            __syncthreads();
        }
    }

    // ---- epilogue ----
    int gid = lane >> 2, tg = lane & 3;
    #pragma unroll
    for (int f = 0; f < 2; f++) {
        #pragma unroll
        for (int g = 0; g < 8; g++) {
            int r0 = m0 + wm + f * 16 + gid;
            int c0 = n0 + wn + g * 8 + tg * 2;
            #pragma unroll
            for (int e = 0; e < 4; e++) {
                int r = r0 + ((e >> 1) << 3);
                int c = c0 + (e & 1);
                if (c >= N) continue;
                float v = acc[f][g][e] * alpha;
                if (bias) v += bias[c];
                if (Res)  v += Res[(long)r * ldc + c];
                if (doRelu) v = fmaxf(v, 0.f);
                C[(long)r * ldc + c] = v;
            }
        }
    }
}

// ---------------- LayerNorm ----------------
__device__ __forceinline__ float warpSum(float v) {
    #pragma unroll
    for (int o = 16; o; o >>= 1) v += __shfl_xor_sync(0xffffffffu, v, o);
    return v;
}
__device__ __forceinline__ float warpMax(float v) {
    #pragma unroll
    for (int o = 16; o; o >>= 1) v = fmaxf(v, __shfl_xor_sync(0xffffffffu, v, o));
    return v;
}

__global__ __launch_bounds__(256) void ln_k(const float* __restrict__ X,
                                            const float* __restrict__ g,
                                            const float* __restrict__ bta,
                                            float* __restrict__ Y)
{
    long row = blockIdx.x;
    const float* xr = X + row * PD;
    float* yr = Y + row * PD;
    int t = threadIdx.x, lane = t & 31, wid = t >> 5;

    float s1 = 0.f, s2 = 0.f;
    for (int c = t; c < PD; c += 256) { float v = xr[c]; s1 += v; s2 += v * v; }
    s1 = warpSum(s1); s2 = warpSum(s2);
    __shared__ float sA[8], sB[8];
    if (lane == 0) { sA[wid] = s1; sB[wid] = s2; }
    __syncthreads();
    float t1 = 0.f, t2 = 0.f;
    #pragma unroll
    for (int wI = 0; wI < 8; wI++) { t1 += sA[wI]; t2 += sB[wI]; }
    float mean = t1 / (float)PD;
    float var  = t2 / (float)PD - mean * mean;
    float rs = rsqrtf(var + 1e-5f);
    for (int c = t; c < PD; c += 256)
        yr[c] = (xr[c] - mean) * rs * g[c] + bta[c];
}

// ---------------- Enformer positional features ----------------
__global__ void pos_k(float* __restrict__ pos)
{
    int m = blockIdx.x * blockDim.x + threadIdx.x;
    if (m >= PMQ) return;
    float d = (float)(m - (PN1 - 1));
    float ad = fabsf(d);

    float fe[16], fc[16], fg[16];
    float pmax = 0.f;
    const float ln2 = 0.6931471805599453f;
    #pragma unroll
    for (int i = 0; i < 16; i++) {
        float e = 3.0f + 8.0f * (float)i / 15.0f;
        float hl = exp2f(e);
        fe[i] = expf(-ln2 / hl * ad);
        float cw = exp2f((float)(i + 1)) - 1.0f;
        fc[i] = (cw > ad) ? 1.0f : 0.0f;
        float mean = 128.0f * (float)(i + 1);
        float conc = (mean / 64.0f) * (mean / 64.0f);
        float rate = mean / 4096.0f;
        float logp = (conc - 1.0f) * logf(ad) - rate * ad
                   - (lgammaf(conc) - conc * logf(rate));
        float prob = expf(logp) + 1e-8f;
        fg[i] = prob;
        pmax = fmaxf(pmax, prob);
    }
    float sgn = (d > 0.f) ? 1.f : ((d < 0.f) ? -1.f : 0.f);
    float inv = 1.0f / pmax;
    float* row = pos + (long)m * PNRP;
    #pragma unroll
    for (int i = 0; i < 16; i++) {
        float gv = fg[i] * inv;
        row[i]      = fe[i];
        row[16 + i] = fc[i];
        row[32 + i] = gv;
        row[48 + i] = sgn * fe[i];
        row[64 + i] = sgn * fc[i];
        row[80 + i] = sgn * gv;
    }
}

// ---------------- kb = k * SCALE + rel_pos_bias ----------------
__global__ void kb_k(const float* __restrict__ k, const float* __restrict__ rpb,
                     float* __restrict__ kb, int total)
{
    for (int i = blockIdx.x * blockDim.x + threadIdx.x; i < total;
         i += gridDim.x * blockDim.x)
        kb[i] = k[i] * PSCALE + rpb[i & 511];
}

// ---------------- fused rel-shift gather + softmax ----------------
__global__ __launch_bounds__(128) void softmax_k(float* __restrict__ att,
                                                 const float* __restrict__ rel)
{
    int i = blockIdx.x;
    long z = blockIdx.y;
    float* row = att + (z * PN1 + i) * (long)PN2;
    const float* relz = rel + z * (long)PN2 * PMQ;
    int t = threadIdx.x, lane = t & 31, wid = t >> 5;

    float v[4];
    float mx = -1e30f;
    #pragma unroll
    for (int u = 0; u < 4; u++) {
        int j = t + u * 128;
        float val = row[j] + relz[(long)j * PMQ + (i + (PN2 - 1) - j)];
        v[u] = val;
        mx = fmaxf(mx, val);
    }
    __shared__ float sh[4];
    mx = warpMax(mx);
    if (lane == 0) sh[wid] = mx;
    __syncthreads();
    float gmx = fmaxf(fmaxf(sh[0], sh[1]), fmaxf(sh[2], sh[3]));
    __syncthreads();

    float s = 0.f;
    #pragma unroll
    for (int u = 0; u < 4; u++) { v[u] = expf(v[u] - gmx); s += v[u]; }
    s = warpSum(s);
    if (lane == 0) sh[wid] = s;
    __syncthreads();
    float gs = sh[0] + sh[1] + sh[2] + sh[3];
    float inv = 1.0f / gs;
    #pragma unroll
    for (int u = 0; u < 4; u++) row[t + u * 128] = v[u] * inv;
}

// ---------------- host orchestration ----------------
static inline dim3 gg(int M, int N, int Z) {
    return dim3((unsigned)((N + 127) / 128), (unsigned)(M / 128), (unsigned)Z);
}

extern "C" void kernel_launch(void* const* d_in, const int* in_sizes, int n_in,
                              void* d_out, int out_size)
{
    const float* x     = (const float*)d_in[0];
    const float* y0    = (const float*)d_in[1];
    const float* W_res = (const float*)d_in[2];
    const float* lnx_g = (const float*)d_in[3];
    const float* lnx_b = (const float*)d_in[4];
    const float* lny_g = (const float*)d_in[5];
    const float* lny_b = (const float*)d_in[6];
    const float* Wq    = (const float*)d_in[7];
    const float* Wk    = (const float*)d_in[8];
    const float* Wv1   = (const float*)d_in[9];
    const float* Wv2   = (const float*)d_in[10];
    const float* Wo1   = (const float*)d_in[11];
    const float* bo1   = (const float*)d_in[12];
    const float* Wo2   = (const float*)d_in[13];
    const float* bo2   = (const float*)d_in[14];
    const float* Wrel  = (const float*)d_in[15];
    const float* rpb   = (const float*)d_in[16];
    const float* fx_g  = (const float*)d_in[17];
    const float* fx_b  = (const float*)d_in[18];
    const float* fx_w1 = (const float*)d_in[19];
    const float* fx_b1 = (const float*)d_in[20];
    const float* fx_w2 = (const float*)d_in[21];
    const float* fx_b2 = (const float*)d_in[22];
    const float* fy_g  = (const float*)d_in[23];
    const float* fy_b  = (const float*)d_in[24];
    const float* fy_w1 = (const float*)d_in[25];
    const float* fy_b1 = (const float*)d_in[26];
    const float* fy_w2 = (const float*)d_in[27];
    const float* fy_b2 = (const float*)d_in[28];

    float* S = nullptr;
    cudaGetSymbolAddress((void**)&S, g_scratch);
    float* gy   = S + OFF_Y;
    float* gx1  = S + OFF_X1;
    float* gy1  = S + OFF_Y1;
    float* gq   = S + OFF_Q;
    float* gk   = S + OFF_K;
    float* gkb  = S + OFF_KB;
    float* gv1  = S + OFF_V1;
    float* gv2  = S + OFF_V2;
    float* gpos = S + OFF_POS;
    float* grq  = S + OFF_RELQ;
    float* grel = S + OFF_REL;
    float* gatt = S + OFF_ATT;
    float* go1  = S + OFF_OUT1;
    float* go2  = S + OFF_OUT2;
    float* gx4  = S + OFF_X4;
    float* gy4  = S + OFF_Y4;
    float* gh   = S + OFF_HID;

    float* outx = (float*)d_out;
    float* outy = outx + (long)PB * PN1 * PD;

    const int HDK = PH * PDK;   // 512
    const int HDV = PH * PDV;   // 768

    // x1 = LN(x), y = y0 @ W_res, y1 = LN(y)
    ln_k<<<PB * PN1, 256>>>(x, lnx_g, lnx_b, gx1);
    gemm_k<false, false><<<gg(PB*PN2, PD, 1), 256, GSMEM>>>(
        y0, W_res, nullptr, nullptr, gy,
        PB*PN2, PD, PDY0, PDY0, PD, PD, 0,0,0,0,0,0, 1, 1.f, 0);
    ln_k<<<PB * PN2, 256>>>(gy, lny_g, lny_b, gy1);

    // q, k, v2, v1 projections
    gemm_k<false, false><<<gg(PB*PN1, HDK, 1), 256, GSMEM>>>(
        gx1, Wq, nullptr, nullptr, gq,
        PB*PN1, HDK, PD, PD, HDK, HDK, 0,0,0,0,0,0, 1, 1.f, 0);
    gemm_k<false, false><<<gg(PB*PN2, HDK, 1), 256, GSMEM>>>(
        gy1, Wk, nullptr, nullptr, gk,
        PB*PN2, HDK, PD, PD, HDK, HDK, 0,0,0,0,0,0, 1, 1.f, 0);
    gemm_k<false, false><<<gg(PB*PN2, HDV, 1), 256, GSMEM>>>(
        gy1, Wv2, nullptr, nullptr, gv2,
        PB*PN2, HDV, PD, PD, HDV, HDV, 0,0,0,0,0,0, 1, 1.f, 0);
    gemm_k<false, false><<<gg(PB*PN1, HDV, 1), 256, GSMEM>>>(
        gx1, Wv1, nullptr, nullptr, gv1,
        PB*PN1, HDV, PD, PD, HDV, HDV, 0,0,0,0,0,0, 1, 1.f, 0);

    // positional features + rel_q = pos @ Wrel (only m < PMQ needed)
    pos_k<<<(PMQ + 127) / 128, 128>>>(gpos);
    gemm_k<false, false><<<gg(PMQ, HDK, 1), 256, GSMEM>>>(
        gpos, Wrel, nullptr, nullptr, grq,
        PMQ, HDK, PNRP, PNRP, HDK, HDK, 0,0,0,0,0,0, 1, 1.f, 0);

    // kb = k * SCALE + rel_pos_bias
    kb_k<<<2048, 256>>>(gk, rpb, gkb, PB*PN2*HDK);

    // content logits = SCALE * q @ k^T   (batched over b,h; NT)
    gemm_k<false, true><<<gg(PN1, PN2, PB*PH), 256, GSMEM>>>(
        gq, gk, nullptr, nullptr, gatt,
        PN1, PN2, PDK, HDK, HDK, PN2,
        (long)PN1*HDK, PDK, (long)PN2*HDK, PDK,
        (long)PH*PN1*PN2, (long)PN1*PN2, PH, PSCALE, 0);

    // rel = kb @ rel_q^T  (batched; rel_q shared across b -> sBb = 0)
    gemm_k<false, true><<<gg(PN2, PMQ, PB*PH), 256, GSMEM>>>(
        gkb, grq, nullptr, nullptr, grel,
        PN2, PMQ, PDK, HDK, HDK, PMQ,
        (long)PN2*HDK, PDK, 0L, PDK,
        (long)PH*PN2*PMQ, (long)PN2*PMQ, PH, 1.f, 0);

    // fused rel-shift gather + softmax (in place over gatt)
    softmax_k<<<dim3(PN1, PB*PH), 128>>>(gatt, grel);

    // out1 = attn @ v2   (batched NN)
    gemm_k<false, false><<<gg(PN1, PDV, PB*PH), 256, GSMEM>>>(
        gatt, gv2, nullptr, nullptr, go1,
        PN1, PDV, PN2, PN2, HDV, HDV,
        (long)PH*PN1*PN2, (long)PN1*PN2, (long)PN2*HDV, PDV,
        (long)PN1*HDV, PDV, PH, 1.f, 0);

    // out2 = attn^T @ v1 (batched TN)
    gemm_k<true, false><<<gg(PN2, PDV, PB*PH), 256, GSMEM>>>(
        gatt, gv1, nullptr, nullptr, go2,
        PN2, PDV, PN1, PN2, HDV, HDV,
        (long)PH*PN1*PN2, (long)PN1*PN2, (long)PN1*HDV, PDV,
        (long)PN2*HDV, PDV, PH, 1.f, 0);

    // x4 = x + out1 @ Wo1 + bo1 ;  y4 = y + out2 @ Wo2 + bo2
    gemm_k<false, false><<<gg(PB*PN1, PD, 1), 256, GSMEM>>>(
        go1, Wo1, bo1, x, gx4,
        PB*PN1, PD, HDV, HDV, PD, PD, 0,0,0,0,0,0, 1, 1.f, 0);
    gemm_k<false, false><<<gg(PB*PN2, PD, 1), 256, GSMEM>>>(
        go2, Wo2, bo2, gy, gy4,
        PB*PN2, PD, HDV, HDV, PD, PD, 0,0,0,0,0,0, 1, 1.f, 0);

    // FFN x: x5 = x4 + relu(LN(x4) @ w1 + b1) @ w2 + b2  -> outx
    ln_k<<<PB * PN1, 256>>>(gx4, fx_g, fx_b, gx1);
    gemm_k<false, false><<<gg(PB*PN1, PDFF, 1), 256, GSMEM>>>(
        gx1, fx_w1, fx_b1, nullptr, gh,
        PB*PN1, PDFF, PD, PD, PDFF, PDFF, 0,0,0,0,0,0, 1, 1.f, 1);
    gemm_k<false, false><<<gg(PB*PN1, PD, 1), 256, GSMEM>>>(
        gh, fx_w2, fx_b2, gx4, outx,
        PB*PN1, PD, PDFF, PDFF, PD, PD, 0,0,0,0,0,0, 1, 1.f, 0);

    // FFN y -> outy
    ln_k<<<PB * PN2, 256>>>(gy4, fy_g, fy_b, gy1);
    gemm_k<false, false><<<gg(PB*PN2, PDFF, 1), 256, GSMEM>>>(
        gy1, fy_w1, fy_b1, nullptr, gh,
        PB*PN2, PDFF, PD, PD, PDFF, PDFF, 0,0,0,0,0,0, 1, 1.f, 1);
    gemm_k<false, false><<<gg(PB*PN2, PD, 1), 256, GSMEM>>>(
        gh, fy_w2, fy_b2, gy4, outy,
        PB*PN2, PD, PDFF, PDFF, PD, PD, 0,0,0,0,0,0, 1, 1.f, 0);

    (void)in_sizes; (void)n_in; (void)out_size;
}

// round 7
// speedup vs baseline: 1.8213x; 1.7432x over previous
#include <cuda_runtime.h>
#include <cuda_bf16.h>
#include <cstdint>
#include <math.h>

// ---------------- problem constants ----------------
#define PB   4
#define PN1  2048
#define PN2  512
#define PD   768
#define PH   8
#define PDK  64
#define PDV  96
#define PNRP 96
#define PDY0 1536
#define PDFF 1536
#define PMQ  2560              // needed pos rows: m = i - j + 511 in [0, 2558]
#define PSCALE 0.125f          // DK^-0.5
#define HDK  512
#define HDV  768

// ---------------- fp32 scratch ----------------
#define OFF_Y      0L
#define OFF_Y1     (OFF_Y    + (long)PB*PN2*PD)
#define OFF_Q      (OFF_Y1   + (long)PB*PN2*PD)
#define OFF_K      (OFF_Q    + (long)PB*PN1*HDK)
#define OFF_V1     (OFF_K    + (long)PB*PN2*HDK)
#define OFF_V2     (OFF_V1   + (long)PB*PN1*HDV)
#define OFF_POS    (OFF_V2   + (long)PB*PN2*HDV)
#define OFF_RELQ   (OFF_POS  + (long)PMQ*PNRP)
#define OFF_REL    (OFF_RELQ + (long)PMQ*HDK)
#define OFF_ATT    (OFF_REL  + (long)PB*PH*PN2*PMQ)
#define OFF_OUT1   (OFF_ATT  + (long)PB*PH*PN1*PN2)
#define OFF_OUT2   (OFF_OUT1 + (long)PB*PN1*HDV)
#define OFF_X4     (OFF_OUT2 + (long)PB*PN2*HDV)
#define OFF_Y4     (OFF_X4   + (long)PB*PN1*PD)
#define OFF_HID    (OFF_Y4   + (long)PB*PN2*PD)
#define OFF_X1     (OFF_HID  + (long)PB*PN1*PDFF)
#define SCRATCH_TOTAL (OFF_X1 + (long)PB*PN1*PD)
__device__ float g_scratch[SCRATCH_TOTAL];

// ---------------- bf16 plane scratch (hi plane at off, lo at off+size) ----------------
#define BF_X1   0L
#define BF_Y1   (BF_X1  + 2L*PB*PN1*PD)
#define BF_Y0   (BF_Y1  + 2L*PB*PN2*PD)
#define BF_Q    (BF_Y0  + 2L*PB*PN2*PDY0)
#define BF_K    (BF_Q   + 2L*PB*PN1*HDK)
#define BF_KB   (BF_K   + 2L*PB*PN2*HDK)
#define BF_RQ   (BF_KB  + 2L*PB*PN2*HDK)
#define BF_ATT  (BF_RQ  + 2L*PMQ*HDK)
#define BF_V2T  (BF_ATT + 2L*PB*PH*PN1*PN2)
#define BF_GO1  (BF_V2T + 2L*PB*PH*PDV*PN2)
#define BF_GH   (BF_GO1 + 2L*PB*PN1*HDV)
#define BF_WRT  (BF_GH  + 2L*PB*PN1*PDFF)
#define BF_WQT  (BF_WRT + 2L*PDY0*PD)
#define BF_WKT  (BF_WQT + 2L*PD*HDK)
#define BF_WV2T (BF_WKT + 2L*PD*HDK)
#define BF_WV1T (BF_WV2T+ 2L*PD*HDV)
#define BF_WO1T (BF_WV1T+ 2L*PD*HDV)
#define BF_FX1T (BF_WO1T+ 2L*HDV*PD)
#define BF_FX2T (BF_FX1T+ 2L*PD*PDFF)
#define BF_FY1T (BF_FX2T+ 2L*PDFF*PD)
#define BF_FY2T (BF_FY1T+ 2L*PD*PDFF)
#define BF_TOTAL (BF_FY2T+ 2L*PDFF*PD)
__device__ __nv_bfloat16 g_bf[BF_TOTAL];

// =================== helpers ===================
__device__ __forceinline__ uint32_t sptr(const void* p) {
    return (uint32_t)__cvta_generic_to_shared(p);
}
__device__ __forceinline__ void ldsm4(uint32_t r[4], const __nv_bfloat16* p) {
    uint32_t a = sptr(p);
    asm volatile("ldmatrix.sync.aligned.m8n8.x4.shared.b16 {%0,%1,%2,%3}, [%4];"
                 : "=r"(r[0]), "=r"(r[1]), "=r"(r[2]), "=r"(r[3]) : "r"(a));
}
__device__ __forceinline__ void ldsm2(uint32_t r[2], const __nv_bfloat16* p) {
    uint32_t a = sptr(p);
    asm volatile("ldmatrix.sync.aligned.m8n8.x2.shared.b16 {%0,%1}, [%2];"
                 : "=r"(r[0]), "=r"(r[1]) : "r"(a));
}
__device__ __forceinline__ void mma16816(float c[4], const uint32_t a[4], uint32_t b0, uint32_t b1) {
    asm volatile(
        "mma.sync.aligned.m16n8k16.row.col.f32.bf16.bf16.f32 "
        "{%0,%1,%2,%3}, {%4,%5,%6,%7}, {%8,%9}, {%0,%1,%2,%3};"
        : "+f"(c[0]), "+f"(c[1]), "+f"(c[2]), "+f"(c[3])
        : "r"(a[0]), "r"(a[1]), "r"(a[2]), "r"(a[3]), "r"(b0), "r"(b1));
}
__device__ __forceinline__ void bsplit(float x, __nv_bfloat16& h, __nv_bfloat16& l) {
    h = __float2bfloat16(x);
    l = __float2bfloat16(x - __bfloat162float(h));
}
__device__ __forceinline__ uint32_t pack2(float a, float b, uint32_t& lo) {
    __nv_bfloat16 ha, la, hb, lb;
    bsplit(a, ha, la); bsplit(b, hb, lb);
    lo = ((uint32_t)__bfloat16_as_ushort(lb) << 16) | (uint32_t)__bfloat16_as_ushort(la);
    return ((uint32_t)__bfloat16_as_ushort(hb) << 16) | (uint32_t)__bfloat16_as_ushort(ha);
}
__device__ __forceinline__ void cpa16(uint32_t saddr, const void* g, bool pred) {
    int sz = pred ? 16 : 0;
    asm volatile("cp.async.cg.shared.global [%0], [%1], 16, %2;"
                 :: "r"(saddr), "l"(g), "r"(sz) : "memory");
}
__device__ __forceinline__ void cpa_commit() {
    asm volatile("cp.async.commit_group;" ::: "memory");
}
template<int NW> __device__ __forceinline__ void cpa_wait() {
    asm volatile("cp.async.wait_group %0;" :: "n"(NW) : "memory");
}

// =================== NEW: pre-split bf16 GEMM with cp.async ===================
// C = alpha*(A @ B^T) (+bias)(+Res)(relu), A=[M,K] planes, B=[N,K] planes (k-contig).
// Optional epilogue split of C into Chi/Clo planes (same geometry as C).
// CTA 128x128, BK=32, 8 warps 4m x 2n (warp 32x64), 2-stage cp.async ring.
// Requires M%128==0, K%32==0. N guarded.
#define SA   40
#define BTSZ (128 * SA)          // halfwords per plane per stage
#define BSTG (4 * BTSZ)          // halfwords per stage
#define BSMEM (2 * BSTG * 2)     // bytes = 81920

__global__ __launch_bounds__(256, 2) void gemm_bf(
    const __nv_bfloat16* __restrict__ Ah, const __nv_bfloat16* __restrict__ Al,
    const __nv_bfloat16* __restrict__ Bh, const __nv_bfloat16* __restrict__ Bl,
    const float* __restrict__ bias, const float* __restrict__ Res,
    float* __restrict__ C, __nv_bfloat16* __restrict__ Chi, __nv_bfloat16* __restrict__ Clo,
    int M, int N, int K, int lda, int ldb, int ldc,
    long sAb, long sAh_, long sBb, long sBh_, long sCb, long sCh_, int Hn,
    float alpha, int doRelu)
{
    int z = blockIdx.z;
    int bb = z / Hn, hh = z % Hn;
    long ao = bb * sAb + hh * sAh_;
    long bo = bb * sBb + hh * sBh_;
    long co = bb * sCb + hh * sCh_;
    Ah += ao; Al += ao; Bh += bo; Bl += bo;
    C += co;
    if (Res) Res += co;
    if (Chi) { Chi += co; Clo += co; }

    extern __shared__ __nv_bfloat16 sm[];
    uint32_t sbase = sptr(sm);

    int m0 = blockIdx.y * 128;
    int n0 = blockIdx.x * 128;
    int tid = threadIdx.x, w = tid >> 5, lane = tid & 31;
    int wm = (w & 3) * 32;
    int wn = (w >> 2) * 64;

    float acc[2][8][4];
    #pragma unroll
    for (int f = 0; f < 2; f++)
        #pragma unroll
        for (int g = 0; g < 8; g++)
            #pragma unroll
            for (int e = 0; e < 4; e++) acc[f][g][e] = 0.f;

    int nk = K >> 5;

    auto issue = [&](int s, int buf) {
        int k0 = s << 5;
        uint32_t st = sbase + (uint32_t)buf * (BSTG * 2);
        #pragma unroll
        for (int i = 0; i < 4; i++) {              // A: 2 planes x 128 rows x 4 segs
            int idx = tid + i * 256;
            int pl = idx >> 9, rem = idx & 511, row = rem >> 2, seg = rem & 3;
            const __nv_bfloat16* g = (pl ? Al : Ah) + (long)(m0 + row) * lda + k0 + seg * 8;
            cpa16(st + (uint32_t)(pl * BTSZ + row * SA + seg * 8) * 2, g, true);
        }
        #pragma unroll
        for (int i = 0; i < 4; i++) {              // B
            int idx = tid + i * 256;
            int pl = idx >> 9, rem = idx & 511, row = rem >> 2, seg = rem & 3;
            int rg = n0 + row;
            int rc = (rg < N) ? rg : 0;
            const __nv_bfloat16* g = (pl ? Bl : Bh) + (long)rc * ldb + k0 + seg * 8;
            cpa16(st + (uint32_t)((2 + pl) * BTSZ + row * SA + seg * 8) * 2, g, rg < N);
        }
        cpa_commit();
    };

    issue(0, 0);
    issue(1, 1);

    for (int s = 0; s < nk; s++) {
        if (s + 2 <= nk) cpa_wait<1>(); else cpa_wait<0>();
        __syncthreads();

        const __nv_bfloat16* base = sm + (s & 1) * BSTG;
        const __nv_bfloat16* pAh = base;
        const __nv_bfloat16* pAl = base + BTSZ;
        const __nv_bfloat16* pBh = base + 2 * BTSZ;
        const __nv_bfloat16* pBl = base + 3 * BTSZ;

        #pragma unroll
        for (int kk = 0; kk < 32; kk += 16) {
            uint32_t ah[2][4], al[2][4];
            #pragma unroll
            for (int f = 0; f < 2; f++) {
                int r = wm + f * 16 + (lane & 15);
                int c = kk + ((lane >> 4) << 3);
                ldsm4(ah[f], pAh + r * SA + c);
                ldsm4(al[f], pAl + r * SA + c);
            }
            #pragma unroll
            for (int gp = 0; gp < 4; gp++) {
                int r = wn + gp * 16 + (lane & 7) + ((lane >> 4) << 3);
                int c = kk + (((lane >> 3) & 1) << 3);
                uint32_t th[4], tl[4];
                ldsm4(th, pBh + r * SA + c);
                ldsm4(tl, pBl + r * SA + c);
                #pragma unroll
                for (int f = 0; f < 2; f++) {
                    mma16816(acc[f][2*gp],   ah[f], th[0], th[1]);
                    mma16816(acc[f][2*gp],   al[f], th[0], th[1]);
                    mma16816(acc[f][2*gp],   ah[f], tl[0], tl[1]);
                    mma16816(acc[f][2*gp+1], ah[f], th[2], th[3]);
                    mma16816(acc[f][2*gp+1], al[f], th[2], th[3]);
                    mma16816(acc[f][2*gp+1], ah[f], tl[2], tl[3]);
                }
            }
        }
        __syncthreads();
        if (s + 2 < nk) issue(s + 2, s & 1);
    }

    // ---- epilogue ----
    int gid = lane >> 2, tg = lane & 3;
    #pragma unroll
    for (int f = 0; f < 2; f++) {
        #pragma unroll
        for (int g = 0; g < 8; g++) {
            int r0 = m0 + wm + f * 16 + gid;
            int c0 = n0 + wn + g * 8 + tg * 2;
            #pragma unroll
            for (int e = 0; e < 4; e++) {
                int r = r0 + ((e >> 1) << 3);
                int c = c0 + (e & 1);
                if (c >= N) continue;
                float v = acc[f][g][e] * alpha;
                if (bias) v += bias[c];
                if (Res)  v += Res[(long)r * ldc + c];
                if (doRelu) v = fmaxf(v, 0.f);
                C[(long)r * ldc + c] = v;
                if (Chi) {
                    __nv_bfloat16 h, l;
                    bsplit(v, h, l);
                    Chi[(long)r * ldc + c] = h;
                    Clo[(long)r * ldc + c] = l;
                }
            }
        }
    }
}

// =================== OLD: R3 float bf16x3 GEMM (for pos/out2/Wo2) ===================
#define OBM 128
#define OBN 64
#define OBK 32

template <bool TA, bool TB>
__global__ __launch_bounds__(256) void gemm_k(
    const float* __restrict__ A, const float* __restrict__ B,
    const float* __restrict__ bias, const float* __restrict__ Res,
    float* __restrict__ C,
    int M, int N, int K, int lda, int ldb, int ldc,
    long sAb, long sAh_, long sBb, long sBh_, long sCb, long sCh_, int Hn,
    float alpha, int doRelu)
{
    int z = blockIdx.z;
    int bb = z / Hn, hh = z % Hn;
    A += bb * sAb + hh * sAh_;
    B += bb * sBb + hh * sBh_;
    C += bb * sCb + hh * sCh_;
    if (Res) Res += bb * sCb + hh * sCh_;

    __shared__ __nv_bfloat16 Ash[OBM * SA];
    __shared__ __nv_bfloat16 Asl[OBM * SA];
    __shared__ __nv_bfloat16 Bsh[OBN * SA];
    __shared__ __nv_bfloat16 Bsl[OBN * SA];

    int m0 = blockIdx.y * OBM;
    int n0 = blockIdx.x * OBN;
    int tid = threadIdx.x;
    int w = tid >> 5, lane = tid & 31;
    int wm = (w & 3) * 32;
    int wn = (w >> 2) * 32;

    float acc[2][4][4];
    #pragma unroll
    for (int f = 0; f < 2; f++)
        #pragma unroll
        for (int g = 0; g < 4; g++)
            #pragma unroll
            for (int e = 0; e < 4; e++) acc[f][g][e] = 0.f;

    for (int k0 = 0; k0 < K; k0 += OBK) {
        if (!TA) {
            #pragma unroll
            for (int idx = tid; idx < OBM * 8; idx += 256) {
                int m = idx >> 3, kq = (idx & 7) << 2;
                float4 v = make_float4(0.f, 0.f, 0.f, 0.f);
                if (m0 + m < M)
                    v = *(const float4*)(A + (long)(m0 + m) * lda + k0 + kq);
                uint32_t l0, l1;
                uint32_t h0 = pack2(v.x, v.y, l0);
                uint32_t h1 = pack2(v.z, v.w, l1);
                *(uint2*)(Ash + m*SA + kq) = make_uint2(h0, h1);
                *(uint2*)(Asl + m*SA + kq) = make_uint2(l0, l1);
            }
        } else {
            #pragma unroll
            for (int idx = tid; idx < OBK * 32; idx += 256) {
                int k = idx >> 5, mq = (idx & 31) << 2;
                float4 v = make_float4(0.f, 0.f, 0.f, 0.f);
                if (m0 + mq < M)
                    v = *(const float4*)(A + (long)(k0 + k) * lda + m0 + mq);
                float vv[4] = { v.x, v.y, v.z, v.w };
                #pragma unroll
                for (int j = 0; j < 4; j++) {
                    __nv_bfloat16 h, l;
                    bsplit(vv[j], h, l);
                    Ash[(mq + j) * SA + k] = h;
                    Asl[(mq + j) * SA + k] = l;
                }
            }
        }
        if (TB) {
            #pragma unroll
            for (int idx = tid; idx < OBN * 8; idx += 256) {
                int n = idx >> 3, kq = (idx & 7) << 2;
                float4 v = make_float4(0.f, 0.f, 0.f, 0.f);
                if (n0 + n < N)
                    v = *(const float4*)(B + (long)(n0 + n) * ldb + k0 + kq);
                uint32_t l0, l1;
                uint32_t h0 = pack2(v.x, v.y, l0);
                uint32_t h1 = pack2(v.z, v.w, l1);
                *(uint2*)(Bsh + n*SA + kq) = make_uint2(h0, h1);
                *(uint2*)(Bsl + n*SA + kq) = make_uint2(l0, l1);
            }
        } else {
            #pragma unroll
            for (int idx = tid; idx < OBK * 16; idx += 256) {
                int k = idx >> 4, nq = (idx & 15) << 2;
                float4 v = make_float4(0.f, 0.f, 0.f, 0.f);
                int nb = n0 + nq;
                if (nb + 3 < N) {
                    v = *(const float4*)(B + (long)(k0 + k) * ldb + nb);
                } else {
                    const float* bp = B + (long)(k0 + k) * ldb;
                    if (nb + 0 < N) v.x = bp[nb + 0];
                    if (nb + 1 < N) v.y = bp[nb + 1];
                    if (nb + 2 < N) v.z = bp[nb + 2];
                }
                float vv[4] = { v.x, v.y, v.z, v.w };
                #pragma unroll
                for (int j = 0; j < 4; j++) {
                    __nv_bfloat16 h, l;
                    bsplit(vv[j], h, l);
                    Bsh[(nq + j) * SA + k] = h;
                    Bsl[(nq + j) * SA + k] = l;
                }
            }
        }
        __syncthreads();

        #pragma unroll
        for (int kk = 0; kk < OBK; kk += 16) {
            uint32_t ah[2][4], al[2][4];
            #pragma unroll
            for (int f = 0; f < 2; f++) {
                int r = wm + f * 16 + (lane & 15);
                int c = kk + ((lane >> 4) << 3);
                ldsm4(ah[f], Ash + r * SA + c);
                ldsm4(al[f], Asl + r * SA + c);
            }
            uint32_t bh[4][2], bl[4][2];
            #pragma unroll
            for (int g = 0; g < 4; g++) {
                int r = wn + g * 8 + (lane & 7);
                int c = kk + (((lane >> 3) & 1) << 3);
                ldsm2(bh[g], Bsh + r * SA + c);
                ldsm2(bl[g], Bsl + r * SA + c);
            }
            #pragma unroll
            for (int f = 0; f < 2; f++)
                #pragma unroll
                for (int g = 0; g < 4; g++) {
                    mma16816(acc[f][g], ah[f], bh[g][0], bh[g][1]);
                    mma16816(acc[f][g], al[f], bh[g][0], bh[g][1]);
                    mma16816(acc[f][g], ah[f], bl[g][0], bl[g][1]);
                }
        }
        __syncthreads();
    }

    int gid = lane >> 2, tg = lane & 3;
    #pragma unroll
    for (int f = 0; f < 2; f++) {
        #pragma unroll
        for (int g = 0; g < 4; g++) {
            int r0 = m0 + wm + f * 16 + gid;
            int c0 = n0 + wn + g * 8 + tg * 2;
            #pragma unroll
            for (int e = 0; e < 4; e++) {
                int r = r0 + ((e >> 1) << 3);
                int c = c0 + (e & 1);
                if (r >= M || c >= N) continue;
                float v = acc[f][g][e] * alpha;
                if (bias) v += bias[c];
                if (Res)  v += Res[(long)r * ldc + c];
                if (doRelu) v = fmaxf(v, 0.f);
                C[(long)r * ldc + c] = v;
            }
        }
    }
}

// ---------------- reductions ----------------
__device__ __forceinline__ float warpSum(float v) {
    #pragma unroll
    for (int o = 16; o; o >>= 1) v += __shfl_xor_sync(0xffffffffu, v, o);
    return v;
}
__device__ __forceinline__ float warpMax(float v) {
    #pragma unroll
    for (int o = 16; o; o >>= 1) v = fmaxf(v, __shfl_xor_sync(0xffffffffu, v, o));
    return v;
}

// ---------------- LayerNorm (emits fp32 + bf16 hi/lo planes) ----------------
__global__ __launch_bounds__(256) void ln_k(const float* __restrict__ X,
                                            const float* __restrict__ g,
                                            const float* __restrict__ bta,
                                            float* __restrict__ Y,
                                            __nv_bfloat16* __restrict__ Yh,
                                            __nv_bfloat16* __restrict__ Yl)
{
    long row = blockIdx.x;
    const float* xr = X + row * PD;
    int t = threadIdx.x, lane = t & 31, wid = t >> 5;

    float s1 = 0.f, s2 = 0.f;
    for (int c = t; c < PD; c += 256) { float v = xr[c]; s1 += v; s2 += v * v; }
    s1 = warpSum(s1); s2 = warpSum(s2);
    __shared__ float sA[8], sB[8];
    if (lane == 0) { sA[wid] = s1; sB[wid] = s2; }
    __syncthreads();
    float t1 = 0.f, t2 = 0.f;
    #pragma unroll
    for (int wI = 0; wI < 8; wI++) { t1 += sA[wI]; t2 += sB[wI]; }
    float mean = t1 / (float)PD;
    float var  = t2 / (float)PD - mean * mean;
    float rs = rsqrtf(var + 1e-5f);
    for (int c = t; c < PD; c += 256) {
        float v = (xr[c] - mean) * rs * g[c] + bta[c];
        Y[row * PD + c] = v;
        __nv_bfloat16 h, l;
        bsplit(v, h, l);
        Yh[row * PD + c] = h;
        Yl[row * PD + c] = l;
    }
}

// ---------------- elementwise split ----------------
__global__ void split_k(const float* __restrict__ in,
                        __nv_bfloat16* __restrict__ oh,
                        __nv_bfloat16* __restrict__ ol, long n)
{
    for (long i = blockIdx.x * (long)blockDim.x + threadIdx.x; i < n;
         i += (long)gridDim.x * blockDim.x) {
        __nv_bfloat16 h, l;
        bsplit(in[i], h, l);
        oh[i] = h; ol[i] = l;
    }
}

// ---------------- tiled transpose + split: in [K,N] fp32 -> out [N,K] bf16 planes ----------------
__global__ void tsplit_k(const float* __restrict__ in,
                         __nv_bfloat16* __restrict__ oh,
                         __nv_bfloat16* __restrict__ ol,
                         int K, int N, int ldin,
                         long sinB, long sinH, long sout, int Hn)
{
    __shared__ float t[32][33];
    int z = blockIdx.z;
    int b = z / Hn, h = z % Hn;
    in += b * sinB + h * sinH;
    oh += (long)z * sout;
    ol += (long)z * sout;
    int kb = blockIdx.y * 32, nb = blockIdx.x * 32;
    int tx = threadIdx.x, ty = threadIdx.y;
    #pragma unroll
    for (int j = 0; j < 32; j += 8) {
        int k = kb + ty + j, n = nb + tx;
        t[ty + j][tx] = (k < K && n < N) ? in[(long)k * ldin + n] : 0.f;
    }
    __syncthreads();
    #pragma unroll
    for (int j = 0; j < 32; j += 8) {
        int n = nb + ty + j, k = kb + tx;
        if (n < N && k < K) {
            __nv_bfloat16 hh, ll;
            bsplit(t[tx][ty + j], hh, ll);
            oh[(long)n * K + k] = hh;
            ol[(long)n * K + k] = ll;
        }
    }
}

// ---------------- Enformer positional features ----------------
__global__ void pos_k(float* __restrict__ pos)
{
    int m = blockIdx.x * blockDim.x + threadIdx.x;
    if (m >= PMQ) return;
    float d = (float)(m - (PN1 - 1));
    float ad = fabsf(d);

    float fe[16], fc[16], fg[16];
    float pmax = 0.f;
    const float ln2 = 0.6931471805599453f;
    #pragma unroll
    for (int i = 0; i < 16; i++) {
        float e = 3.0f + 8.0f * (float)i / 15.0f;
        float hl = exp2f(e);
        fe[i] = expf(-ln2 / hl * ad);
        float cw = exp2f((float)(i + 1)) - 1.0f;
        fc[i] = (cw > ad) ? 1.0f : 0.0f;
        float mean = 128.0f * (float)(i + 1);
        float conc = (mean / 64.0f) * (mean / 64.0f);
        float rate = mean / 4096.0f;
        float logp = (conc - 1.0f) * logf(ad) - rate * ad
                   - (lgammaf(conc) - conc * logf(rate));
        float prob = expf(logp) + 1e-8f;
        fg[i] = prob;
        pmax = fmaxf(pmax, prob);
    }
    float sgn = (d > 0.f) ? 1.f : ((d < 0.f) ? -1.f : 0.f);
    float inv = 1.0f / pmax;
    float* row = pos + (long)m * PNRP;
    #pragma unroll
    for (int i = 0; i < 16; i++) {
        float gv = fg[i] * inv;
        row[i]      = fe[i];
        row[16 + i] = fc[i];
        row[32 + i] = gv;
        row[48 + i] = sgn * fe[i];
        row[64 + i] = sgn * fc[i];
        row[80 + i] = sgn * gv;
    }
}

// ---------------- kb = k*SCALE + rpb -> bf16 planes ----------------
__global__ void kb_k(const float* __restrict__ k, const float* __restrict__ rpb,
                     __nv_bfloat16* __restrict__ kbh, __nv_bfloat16* __restrict__ kbl,
                     int total)
{
    for (int i = blockIdx.x * blockDim.x + threadIdx.x; i < total;
         i += gridDim.x * blockDim.x) {
        float v = k[i] * PSCALE + rpb[i & 511];
        __nv_bfloat16 h, l;
        bsplit(v, h, l);
        kbh[i] = h; kbl[i] = l;
    }
}

// ---------------- fused rel-shift gather + softmax (fp32 + planes) ----------------
__global__ __launch_bounds__(128) void softmax_k(float* __restrict__ att,
                                                 const float* __restrict__ rel,
                                                 __nv_bfloat16* __restrict__ ah,
                                                 __nv_bfloat16* __restrict__ al)
{
    int i = blockIdx.x;
    long z = blockIdx.y;
    long rowoff = (z * PN1 + i) * (long)PN2;
    float* row = att + rowoff;
    const float* relz = rel + z * (long)PN2 * PMQ;
    int t = threadIdx.x, lane = t & 31, wid = t >> 5;

    float v[4];
    float mx = -1e30f;
    #pragma unroll
    for (int u = 0; u < 4; u++) {
        int j = t + u * 128;
        float val = row[j] + relz[(long)j * PMQ + (i + (PN2 - 1) - j)];
        v[u] = val;
        mx = fmaxf(mx, val);
    }
    __shared__ float sh[4];
    mx = warpMax(mx);
    if (lane == 0) sh[wid] = mx;
    __syncthreads();
    float gmx = fmaxf(fmaxf(sh[0], sh[1]), fmaxf(sh[2], sh[3]));
    __syncthreads();

    float s = 0.f;
    #pragma unroll
    for (int u = 0; u < 4; u++) { v[u] = expf(v[u] - gmx); s += v[u]; }
    s = warpSum(s);
    if (lane == 0) sh[wid] = s;
    __syncthreads();
    float gs = sh[0] + sh[1] + sh[2] + sh[3];
    float inv = 1.0f / gs;
    #pragma unroll
    for (int u = 0; u < 4; u++) {
        int j = t + u * 128;
        float p = v[u] * inv;
        row[j] = p;
        __nv_bfloat16 h, l;
        bsplit(p, h, l);
        ah[rowoff + j] = h;
        al[rowoff + j] = l;
    }
}

// ---------------- host orchestration ----------------
static inline dim3 ngrid(int M, int N, int Z) {
    return dim3((unsigned)((N + 127) / 128), (unsigned)(M / 128), (unsigned)Z);
}
static inline dim3 ogrid(int M, int N, int Z) {
    return dim3((unsigned)((N + OBN - 1) / OBN), (unsigned)((M + OBM - 1) / OBM), (unsigned)Z);
}

extern "C" void kernel_launch(void* const* d_in, const int* in_sizes, int n_in,
                              void* d_out, int out_size)
{
    const float* x     = (const float*)d_in[0];
    const float* y0    = (const float*)d_in[1];
    const float* W_res = (const float*)d_in[2];
    const float* lnx_g = (const float*)d_in[3];
    const float* lnx_b = (const float*)d_in[4];
    const float* lny_g = (const float*)d_in[5];
    const float* lny_b = (const float*)d_in[6];
    const float* Wq    = (const float*)d_in[7];
    const float* Wk    = (const float*)d_in[8];
    const float* Wv1   = (const float*)d_in[9];
    const float* Wv2   = (const float*)d_in[10];
    const float* Wo1   = (const float*)d_in[11];
    const float* bo1   = (const float*)d_in[12];
    const float* Wo2   = (const float*)d_in[13];
    const float* bo2   = (const float*)d_in[14];
    const float* Wrel  = (const float*)d_in[15];
    const float* rpb   = (const float*)d_in[16];
    const float* fx_g  = (const float*)d_in[17];
    const float* fx_b  = (const float*)d_in[18];
    const float* fx_w1 = (const float*)d_in[19];
    const float* fx_b1 = (const float*)d_in[20];
    const float* fx_w2 = (const float*)d_in[21];
    const float* fx_b2 = (const float*)d_in[22];
    const float* fy_g  = (const float*)d_in[23];
    const float* fy_b  = (const float*)d_in[24];
    const float* fy_w1 = (const float*)d_in[25];
    const float* fy_b1 = (const float*)d_in[26];
    const float* fy_w2 = (const float*)d_in[27];
    const float* fy_b2 = (const float*)d_in[28];

    cudaFuncSetAttribute(gemm_bf, cudaFuncAttributeMaxDynamicSharedMemorySize, BSMEM);

    float* S = nullptr;
    cudaGetSymbolAddress((void**)&S, g_scratch);
    __nv_bfloat16* BF = nullptr;
    cudaGetSymbolAddress((void**)&BF, g_bf);

    float* gy   = S + OFF_Y;
    float* gx1  = S + OFF_X1;
    float* gy1  = S + OFF_Y1;
    float* gq   = S + OFF_Q;
    float* gk   = S + OFF_K;
    float* gv1  = S + OFF_V1;
    float* gv2  = S + OFF_V2;
    float* gpos = S + OFF_POS;
    float* grq  = S + OFF_RELQ;
    float* grel = S + OFF_REL;
    float* gatt = S + OFF_ATT;
    float* go1  = S + OFF_OUT1;
    float* go2  = S + OFF_OUT2;
    float* gx4  = S + OFF_X4;
    float* gy4  = S + OFF_Y4;
    float* gh   = S + OFF_HID;

    // bf16 plane pointers (hi = base, lo = base + size)
    #define PLH(off) (BF + (off))
    #define PLL(off, sz) (BF + (off) + (sz))
    const long szX1 = (long)PB*PN1*PD,  szY1 = (long)PB*PN2*PD,  szY0 = (long)PB*PN2*PDY0;
    const long szQ  = (long)PB*PN1*HDK, szK = (long)PB*PN2*HDK,  szKB = szK;
    const long szRQ = (long)PMQ*HDK,    szATT = (long)PB*PH*PN1*PN2;
    const long szV2T= (long)PB*PH*PDV*PN2, szGO1 = (long)PB*PN1*HDV, szGH = (long)PB*PN1*PDFF;
    const long szWRT=(long)PDY0*PD, szWQT=(long)PD*HDK, szWKT=(long)PD*HDK;
    const long szWV2T=(long)PD*HDV, szWV1T=(long)PD*HDV, szWO1T=(long)HDV*PD;
    const long szF1=(long)PD*PDFF, szF2=(long)PDFF*PD;

    float* outx = (float*)d_out;
    float* outy = outx + (long)PB * PN1 * PD;

    dim3 tt(32, 8);

    // ---- weight transpose+split (one-shot, cheap) ----
    tsplit_k<<<dim3(PD/32, PDY0/32, 1), tt>>>(W_res, PLH(BF_WRT), PLL(BF_WRT,szWRT), PDY0, PD, PD, 0,0,0,1);
    tsplit_k<<<dim3(HDK/32, PD/32, 1), tt>>>(Wq,  PLH(BF_WQT),  PLL(BF_WQT,szWQT),  PD, HDK, HDK, 0,0,0,1);
    tsplit_k<<<dim3(HDK/32, PD/32, 1), tt>>>(Wk,  PLH(BF_WKT),  PLL(BF_WKT,szWKT),  PD, HDK, HDK, 0,0,0,1);
    tsplit_k<<<dim3(HDV/32, PD/32, 1), tt>>>(Wv2, PLH(BF_WV2T), PLL(BF_WV2T,szWV2T), PD, HDV, HDV, 0,0,0,1);
    tsplit_k<<<dim3(HDV/32, PD/32, 1), tt>>>(Wv1, PLH(BF_WV1T), PLL(BF_WV1T,szWV1T), PD, HDV, HDV, 0,0,0,1);
    tsplit_k<<<dim3(PD/32, HDV/32, 1), tt>>>(Wo1, PLH(BF_WO1T), PLL(BF_WO1T,szWO1T), HDV, PD, PD, 0,0,0,1);
    tsplit_k<<<dim3(PDFF/32, PD/32, 1), tt>>>(fx_w1, PLH(BF_FX1T), PLL(BF_FX1T,szF1), PD, PDFF, PDFF, 0,0,0,1);
    tsplit_k<<<dim3(PD/32, PDFF/32, 1), tt>>>(fx_w2, PLH(BF_FX2T), PLL(BF_FX2T,szF2), PDFF, PD, PD, 0,0,0,1);
    tsplit_k<<<dim3(PDFF/32, PD/32, 1), tt>>>(fy_w1, PLH(BF_FY1T), PLL(BF_FY1T,szF1), PD, PDFF, PDFF, 0,0,0,1);
    tsplit_k<<<dim3(PD/32, PDFF/32, 1), tt>>>(fy_w2, PLH(BF_FY2T), PLL(BF_FY2T,szF2), PDFF, PD, PD, 0,0,0,1);

    // ---- inputs ----
    ln_k<<<PB * PN1, 256>>>(x, lnx_g, lnx_b, gx1, PLH(BF_X1), PLL(BF_X1,szX1));
    split_k<<<2048, 256>>>(y0, PLH(BF_Y0), PLL(BF_Y0,szY0), szY0);

    // y = y0 @ W_res
    gemm_bf<<<ngrid(PB*PN2, PD, 1), 256, BSMEM>>>(
        PLH(BF_Y0), PLL(BF_Y0,szY0), PLH(BF_WRT), PLL(BF_WRT,szWRT),
        nullptr, nullptr, gy, nullptr, nullptr,
        PB*PN2, PD, PDY0, PDY0, PDY0, PD, 0,0,0,0,0,0, 1, 1.f, 0);
    ln_k<<<PB * PN2, 256>>>(gy, lny_g, lny_b, gy1, PLH(BF_Y1), PLL(BF_Y1,szY1));

    // q (pre-scaled), k, v2, v1
    gemm_bf<<<ngrid(PB*PN1, HDK, 1), 256, BSMEM>>>(
        PLH(BF_X1), PLL(BF_X1,szX1), PLH(BF_WQT), PLL(BF_WQT,szWQT),
        nullptr, nullptr, gq, PLH(BF_Q), PLL(BF_Q,szQ),
        PB*PN1, HDK, PD, PD, PD, HDK, 0,0,0,0,0,0, 1, PSCALE, 0);
    gemm_bf<<<ngrid(PB*PN2, HDK, 1), 256, BSMEM>>>(
        PLH(BF_Y1), PLL(BF_Y1,szY1), PLH(BF_WKT), PLL(BF_WKT,szWKT),
        nullptr, nullptr, gk, PLH(BF_K), PLL(BF_K,szK),
        PB*PN2, HDK, PD, PD, PD, HDK, 0,0,0,0,0,0, 1, 1.f, 0);
    gemm_bf<<<ngrid(PB*PN2, HDV, 1), 256, BSMEM>>>(
        PLH(BF_Y1), PLL(BF_Y1,szY1), PLH(BF_WV2T), PLL(BF_WV2T,szWV2T),
        nullptr, nullptr, gv2, nullptr, nullptr,
        PB*PN2, HDV, PD, PD, PD, HDV, 0,0,0,0,0,0, 1, 1.f, 0);
    gemm_bf<<<ngrid(PB*PN1, HDV, 1), 256, BSMEM>>>(
        PLH(BF_X1), PLL(BF_X1,szX1), PLH(BF_WV1T), PLL(BF_WV1T,szWV1T),
        nullptr, nullptr, gv1, nullptr, nullptr,
        PB*PN1, HDV, PD, PD, PD, HDV, 0,0,0,0,0,0, 1, 1.f, 0);

    // v2T planes (per b,h): [K=512 rows(j), N=96 cols(d)] -> [96, 512]
    tsplit_k<<<dim3(PDV/32, PN2/32, PB*PH), tt>>>(
        gv2, PLH(BF_V2T), PLL(BF_V2T,szV2T), PN2, PDV, HDV,
        (long)PN2*HDV, (long)PDV, (long)PDV*PN2, PH);

    // pos features + rel_q (old path) + split
    pos_k<<<(PMQ + 127) / 128, 128>>>(gpos);
    gemm_k<false,false><<<ogrid(PMQ, HDK, 1), 256>>>(gpos, Wrel, nullptr, nullptr, grq,
        PMQ, HDK, PNRP, PNRP, HDK, HDK, 0,0,0,0,0,0, 1, 1.f, 0);
    split_k<<<2048, 256>>>(grq, PLH(BF_RQ), PLL(BF_RQ,szRQ), szRQ);

    // kb planes
    kb_k<<<2048, 256>>>(gk, rpb, PLH(BF_KB), PLL(BF_KB,szKB), PB*PN2*HDK);

    // content = q_scaled @ k^T (batched over b,h)
    gemm_bf<<<ngrid(PN1, PN2, PB*PH), 256, BSMEM>>>(
        PLH(BF_Q), PLL(BF_Q,szQ), PLH(BF_K), PLL(BF_K,szK),
        nullptr, nullptr, gatt, nullptr, nullptr,
        PN1, PN2, PDK, HDK, HDK, PN2,
        (long)PN1*HDK, (long)PDK, (long)PN2*HDK, (long)PDK,
        (long)PH*PN1*PN2, (long)PN1*PN2, PH, 1.f, 0);

    // rel = kb @ rel_q^T (batched; rel_q shared across b)
    gemm_bf<<<ngrid(PN2, PMQ, PB*PH), 256, BSMEM>>>(
        PLH(BF_KB), PLL(BF_KB,szKB), PLH(BF_RQ), PLL(BF_RQ,szRQ),
        nullptr, nullptr, grel, nullptr, nullptr,
        PN2, PMQ, PDK, HDK, HDK, PMQ,
        (long)PN2*HDK, (long)PDK, 0L, (long)PDK,
        (long)PH*PN2*PMQ, (long)PN2*PMQ, PH, 1.f, 0);

    // softmax (fp32 + planes)
    softmax_k<<<dim3(PN1, PB*PH), 128>>>(gatt, grel, PLH(BF_ATT), PLL(BF_ATT,szATT));

    // out1 = attn @ v2 (planes; B = v2T per-z packed) + epilogue split
    gemm_bf<<<ngrid(PN1, PDV, PB*PH), 256, BSMEM>>>(
        PLH(BF_ATT), PLL(BF_ATT,szATT), PLH(BF_V2T), PLL(BF_V2T,szV2T),
        nullptr, nullptr, go1, PLH(BF_GO1), PLL(BF_GO1,szGO1),
        PN1, PDV, PN2, PN2, PN2, HDV,
        (long)PH*PN1*PN2, (long)PN1*PN2, (long)PH*PDV*PN2, (long)PDV*PN2,
        (long)PN1*HDV, (long)PDV, PH, 1.f, 0);

    // out2 = attn^T @ v1 (old TN path, fp32)
    gemm_k<true,false><<<ogrid(PN2, PDV, PB*PH), 256>>>(gatt, gv1, nullptr, nullptr, go2,
        PN2, PDV, PN1, PN2, HDV, HDV,
        (long)PH*PN1*PN2, (long)PN1*PN2, (long)PN1*HDV, (long)PDV,
        (long)PN2*HDV, (long)PDV, PH, 1.f, 0);

    // x4 = x + out1 @ Wo1 + bo1 (new) ; y4 = y + out2 @ Wo2 + bo2 (old)
    gemm_bf<<<ngrid(PB*PN1, PD, 1), 256, BSMEM>>>(
        PLH(BF_GO1), PLL(BF_GO1,szGO1), PLH(BF_WO1T), PLL(BF_WO1T,szWO1T),
        bo1, x, gx4, nullptr, nullptr,
        PB*PN1, PD, HDV, HDV, HDV, PD, 0,0,0,0,0,0, 1, 1.f, 0);
    gemm_k<false,false><<<ogrid(PB*PN2, PD, 1), 256>>>(go2, Wo2, bo2, gy, gy4,
        PB*PN2, PD, HDV, HDV, PD, PD, 0,0,0,0,0,0, 1, 1.f, 0);

    // FFN x
    ln_k<<<PB * PN1, 256>>>(gx4, fx_g, fx_b, gx1, PLH(BF_X1), PLL(BF_X1,szX1));
    gemm_bf<<<ngrid(PB*PN1, PDFF, 1), 256, BSMEM>>>(
        PLH(BF_X1), PLL(BF_X1,szX1), PLH(BF_FX1T), PLL(BF_FX1T,szF1),
        fx_b1, nullptr, gh, PLH(BF_GH), PLL(BF_GH,szGH),
        PB*PN1, PDFF, PD, PD, PD, PDFF, 0,0,0,0,0,0, 1, 1.f, 1);
    gemm_bf<<<ngrid(PB*PN1, PD, 1), 256, BSMEM>>>(
        PLH(BF_GH), PLL(BF_GH,szGH), PLH(BF_FX2T), PLL(BF_FX2T,szF2),
        fx_b2, gx4, outx, nullptr, nullptr,
        PB*PN1, PD, PDFF, PDFF, PDFF, PD, 0,0,0,0,0,0, 1, 1.f, 0);

    // FFN y
    ln_k<<<PB * PN2, 256>>>(gy4, fy_g, fy_b, gy1, PLH(BF_Y1), PLL(BF_Y1,szY1));
    gemm_bf<<<ngrid(PB*PN2, PDFF, 1), 256, BSMEM>>>(
        PLH(BF_Y1), PLL(BF_Y1,szY1), PLH(BF_FY1T), PLL(BF_FY1T,szF1),
        fy_b1, nullptr, gh, PLH(BF_GH), PLL(BF_GH,szGH),
        PB*PN2, PDFF, PD, PD, PD, PDFF, 0,0,0,0,0,0, 1, 1.f, 1);
    gemm_bf<<<ngrid(PB*PN2, PD, 1), 256, BSMEM>>>(
        PLH(BF_GH), PLL(BF_GH,szGH), PLH(BF_FY2T), PLL(BF_FY2T,szF2),
        fy_b2, gy4, outy, nullptr, nullptr,
        PB*PN2, PD, PDFF, PDFF, PDFF, PD, 0,0,0,0,0,0, 1, 1.f, 0);

    (void)in_sizes; (void)n_in; (void)out_size;
}

// round 9
// speedup vs baseline: 2.0953x; 1.1504x over previous
#include <cuda_runtime.h>
#include <cuda_bf16.h>
#include <cstdint>
#include <math.h>

// ---------------- problem constants ----------------
#define PB   4
#define PN1  2048
#define PN2  512
#define PD   768
#define PH   8
#define PDK  64
#define PDV  96
#define PNRP 96
#define PDY0 1536
#define PDFF 1536
#define PMQ  2560              // needed pos rows: m = i - j + 511 in [0, 2558]
#define PSCALE 0.125f          // DK^-0.5
#define HDK  512
#define HDV  768

// ---------------- fp32 scratch ----------------
#define OFF_Y      0L
#define OFF_Y1     (OFF_Y    + (long)PB*PN2*PD)
#define OFF_Q      (OFF_Y1   + (long)PB*PN2*PD)
#define OFF_K      (OFF_Q    + (long)PB*PN1*HDK)
#define OFF_V1     (OFF_K    + (long)PB*PN2*HDK)
#define OFF_V2     (OFF_V1   + (long)PB*PN1*HDV)
#define OFF_RELQ   (OFF_V2   + (long)PB*PN2*HDV)
#define OFF_REL    (OFF_RELQ + (long)PMQ*HDK)
#define OFF_ATT    (OFF_REL  + (long)PB*PH*PN2*PMQ)
#define OFF_OUT1   (OFF_ATT  + (long)PB*PH*PN1*PN2)
#define OFF_OUT2   (OFF_OUT1 + (long)PB*PN1*HDV)
#define OFF_X4     (OFF_OUT2 + (long)PB*PN2*HDV)
#define OFF_Y4     (OFF_X4   + (long)PB*PN1*PD)
#define OFF_HID    (OFF_Y4   + (long)PB*PN2*PD)
#define OFF_X1     (OFF_HID  + (long)PB*PN1*PDFF)
#define SCRATCH_TOTAL (OFF_X1 + (long)PB*PN1*PD)
__device__ float g_scratch[SCRATCH_TOTAL];

// ---------------- bf16 plane scratch (hi plane at off, lo at off+size) ----------------
#define SZ_X1   ((long)PB*PN1*PD)
#define SZ_Y1   ((long)PB*PN2*PD)
#define SZ_Y0   ((long)PB*PN2*PDY0)
#define SZ_Q    ((long)PB*PN1*HDK)
#define SZ_K    ((long)PB*PN2*HDK)
#define SZ_KB   ((long)PB*PN2*HDK)
#define SZ_RQ   ((long)PMQ*HDK)
#define SZ_ATT  ((long)PB*PH*PN1*PN2)
#define SZ_ATTT ((long)PB*PH*PN1*PN2)
#define SZ_V2T  ((long)PB*PH*PDV*PN2)
#define SZ_V1T  ((long)PB*PH*PDV*PN1)
#define SZ_GO1  ((long)PB*PN1*HDV)
#define SZ_GO2  ((long)PB*PN2*HDV)
#define SZ_GH   ((long)PB*PN1*PDFF)
#define SZ_POS  ((long)PMQ*PNRP)
#define SZ_WRT  ((long)PDY0*PD)
#define SZ_WRELT ((long)HDK*PNRP)
#define SZ_WQT  ((long)PD*HDK)
#define SZ_WKT  ((long)PD*HDK)
#define SZ_WV2T ((long)PD*HDV)
#define SZ_WV1T ((long)PD*HDV)
#define SZ_WO1T ((long)HDV*PD)
#define SZ_WO2T ((long)HDV*PD)
#define SZ_F1   ((long)PD*PDFF)
#define SZ_F2   ((long)PDFF*PD)

#define BF_X1   0L
#define BF_Y1   (BF_X1   + 2*SZ_X1)
#define BF_Y0   (BF_Y1   + 2*SZ_Y1)
#define BF_Q    (BF_Y0   + 2*SZ_Y0)
#define BF_K    (BF_Q    + 2*SZ_Q)
#define BF_KB   (BF_K    + 2*SZ_K)
#define BF_RQ   (BF_KB   + 2*SZ_KB)
#define BF_ATT  (BF_RQ   + 2*SZ_RQ)
#define BF_ATTT (BF_ATT  + 2*SZ_ATT)
#define BF_V2T  (BF_ATTT + 2*SZ_ATTT)
#define BF_V1T  (BF_V2T  + 2*SZ_V2T)
#define BF_GO1  (BF_V1T  + 2*SZ_V1T)
#define BF_GO2  (BF_GO1  + 2*SZ_GO1)
#define BF_GH   (BF_GO2  + 2*SZ_GO2)
#define BF_POS  (BF_GH   + 2*SZ_GH)
#define BF_WRT  (BF_POS  + 2*SZ_POS)
#define BF_WRELT (BF_WRT + 2*SZ_WRT)
#define BF_WQT  (BF_WRELT+ 2*SZ_WRELT)
#define BF_WKT  (BF_WQT  + 2*SZ_WQT)
#define BF_WV2T (BF_WKT  + 2*SZ_WKT)
#define BF_WV1T (BF_WV2T + 2*SZ_WV2T)
#define BF_WO1T (BF_WV1T + 2*SZ_WV1T)
#define BF_WO2T (BF_WO1T + 2*SZ_WO1T)
#define BF_FX1T (BF_WO2T + 2*SZ_WO2T)
#define BF_FX2T (BF_FX1T + 2*SZ_F1)
#define BF_FY1T (BF_FX2T + 2*SZ_F2)
#define BF_FY2T (BF_FY1T + 2*SZ_F1)
#define BF_TOTAL (BF_FY2T+ 2*SZ_F2)
__device__ __align__(256) __nv_bfloat16 g_bf[BF_TOTAL];

// =================== helpers ===================
__device__ __forceinline__ uint32_t sptr(const void* p) {
    return (uint32_t)__cvta_generic_to_shared(p);
}
__device__ __forceinline__ void ldsm4(uint32_t r[4], const __nv_bfloat16* p) {
    uint32_t a = sptr(p);
    asm volatile("ldmatrix.sync.aligned.m8n8.x4.shared.b16 {%0,%1,%2,%3}, [%4];"
                 : "=r"(r[0]), "=r"(r[1]), "=r"(r[2]), "=r"(r[3]) : "r"(a));
}
__device__ __forceinline__ void mma16816(float c[4], const uint32_t a[4], uint32_t b0, uint32_t b1) {
    asm volatile(
        "mma.sync.aligned.m16n8k16.row.col.f32.bf16.bf16.f32 "
        "{%0,%1,%2,%3}, {%4,%5,%6,%7}, {%8,%9}, {%0,%1,%2,%3};"
        : "+f"(c[0]), "+f"(c[1]), "+f"(c[2]), "+f"(c[3])
        : "r"(a[0]), "r"(a[1]), "r"(a[2]), "r"(a[3]), "r"(b0), "r"(b1));
}
__device__ __forceinline__ void bsplit(float x, __nv_bfloat16& h, __nv_bfloat16& l) {
    h = __float2bfloat16(x);
    l = __float2bfloat16(x - __bfloat162float(h));
}
__device__ __forceinline__ void cpa16(uint32_t saddr, const void* g, bool pred) {
    int sz = pred ? 16 : 0;
    asm volatile("cp.async.cg.shared.global [%0], [%1], 16, %2;"
                 :: "r"(saddr), "l"(g), "r"(sz) : "memory");
}
__device__ __forceinline__ void cpa_commit() {
    asm volatile("cp.async.commit_group;" ::: "memory");
}
template<int NW> __device__ __forceinline__ void cpa_wait() {
    asm volatile("cp.async.wait_group %0;" :: "n"(NW) : "memory");
}
__device__ __forceinline__ float warpSum(float v) {
    #pragma unroll
    for (int o = 16; o; o >>= 1) v += __shfl_xor_sync(0xffffffffu, v, o);
    return v;
}
__device__ __forceinline__ float warpMax(float v) {
    #pragma unroll
    for (int o = 16; o; o >>= 1) v = fmaxf(v, __shfl_xor_sync(0xffffffffu, v, o));
    return v;
}

// =================== pre-split bf16 GEMM with cp.async ===================
// C = alpha*(A @ B^T) (+bias)(+Res)(relu), A=[M,K] planes, B=[N,K] planes (k-contig).
// Optional epilogue split of C into Chi/Clo planes. CTA 128x128, BK=32,
// 8 warps 4m x 2n (warp 32x64), 2-stage cp.async ring. M%128==0, K%32==0; N guarded.
#define SA   40
#define BTSZ (128 * SA)          // halfwords per plane per stage
#define BSTG (4 * BTSZ)          // halfwords per stage
#define BSMEM (2 * BSTG * 2)     // bytes = 81920

__global__ __launch_bounds__(256, 2) void gemm_bf(
    const __nv_bfloat16* __restrict__ Ah, const __nv_bfloat16* __restrict__ Al,
    const __nv_bfloat16* __restrict__ Bh, const __nv_bfloat16* __restrict__ Bl,
    const float* __restrict__ bias, const float* __restrict__ Res,
    float* __restrict__ C, __nv_bfloat16* __restrict__ Chi, __nv_bfloat16* __restrict__ Clo,
    int M, int N, int K, int lda, int ldb, int ldc,
    long sAb, long sAh_, long sBb, long sBh_, long sCb, long sCh_, int Hn,
    float alpha, int doRelu)
{
    int z = blockIdx.z;
    int bb = z / Hn, hh = z % Hn;
    long ao = bb * sAb + hh * sAh_;
    long bo = bb * sBb + hh * sBh_;
    long co = bb * sCb + hh * sCh_;
    Ah += ao; Al += ao; Bh += bo; Bl += bo;
    C += co;
    if (Res) Res += co;
    if (Chi) { Chi += co; Clo += co; }

    extern __shared__ __nv_bfloat16 sm[];
    uint32_t sbase = sptr(sm);

    int m0 = blockIdx.y * 128;
    int n0 = blockIdx.x * 128;
    int tid = threadIdx.x, w = tid >> 5, lane = tid & 31;
    int wm = (w & 3) * 32;
    int wn = (w >> 2) * 64;

    float acc[2][8][4];
    #pragma unroll
    for (int f = 0; f < 2; f++)
        #pragma unroll
        for (int g = 0; g < 8; g++)
            #pragma unroll
            for (int e = 0; e < 4; e++) acc[f][g][e] = 0.f;

    int nk = K >> 5;

    auto issue = [&](int s, int buf) {
        int k0 = s << 5;
        uint32_t st = sbase + (uint32_t)buf * (BSTG * 2);
        #pragma unroll
        for (int i = 0; i < 4; i++) {              // A: 2 planes x 128 rows x 4 segs
            int idx = tid + i * 256;
            int pl = idx >> 9, rem = idx & 511, row = rem >> 2, seg = rem & 3;
            const __nv_bfloat16* g = (pl ? Al : Ah) + (long)(m0 + row) * lda + k0 + seg * 8;
            cpa16(st + (uint32_t)(pl * BTSZ + row * SA + seg * 8) * 2, g, true);
        }
        #pragma unroll
        for (int i = 0; i < 4; i++) {              // B
            int idx = tid + i * 256;
            int pl = idx >> 9, rem = idx & 511, row = rem >> 2, seg = rem & 3;
            int rg = n0 + row;
            int rc = (rg < N) ? rg : 0;
            const __nv_bfloat16* g = (pl ? Bl : Bh) + (long)rc * ldb + k0 + seg * 8;
            cpa16(st + (uint32_t)((2 + pl) * BTSZ + row * SA + seg * 8) * 2, g, rg < N);
        }
        cpa_commit();
    };

    issue(0, 0);
    issue(1, 1);

    for (int s = 0; s < nk; s++) {
        if (s + 2 <= nk) cpa_wait<1>(); else cpa_wait<0>();
        __syncthreads();

        const __nv_bfloat16* base = sm + (s & 1) * BSTG;
        const __nv_bfloat16* pAh = base;
        const __nv_bfloat16* pAl = base + BTSZ;
        const __nv_bfloat16* pBh = base + 2 * BTSZ;
        const __nv_bfloat16* pBl = base + 3 * BTSZ;

        #pragma unroll
        for (int kk = 0; kk < 32; kk += 16) {
            uint32_t ah[2][4], al[2][4];
            #pragma unroll
            for (int f = 0; f < 2; f++) {
                int r = wm + f * 16 + (lane & 15);
                int c = kk + ((lane >> 4) << 3);
                ldsm4(ah[f], pAh + r * SA + c);
                ldsm4(al[f], pAl + r * SA + c);
            }
            #pragma unroll
            for (int gp = 0; gp < 4; gp++) {
                int r = wn + gp * 16 + (lane & 7) + ((lane >> 4) << 3);
                int c = kk + (((lane >> 3) & 1) << 3);
                uint32_t th[4], tl[4];
                ldsm4(th, pBh + r * SA + c);
                ldsm4(tl, pBl + r * SA + c);
                #pragma unroll
                for (int f = 0; f < 2; f++) {
                    mma16816(acc[f][2*gp],   ah[f], th[0], th[1]);
                    mma16816(acc[f][2*gp],   al[f], th[0], th[1]);
                    mma16816(acc[f][2*gp],   ah[f], tl[0], tl[1]);
                    mma16816(acc[f][2*gp+1], ah[f], th[2], th[3]);
                    mma16816(acc[f][2*gp+1], al[f], th[2], th[3]);
                    mma16816(acc[f][2*gp+1], ah[f], tl[2], tl[3]);
                }
            }
        }
        __syncthreads();
        if (s + 2 < nk) issue(s + 2, s & 1);
    }

    // ---- epilogue ----
    int gid = lane >> 2, tg = lane & 3;
    #pragma unroll
    for (int f = 0; f < 2; f++) {
        #pragma unroll
        for (int g = 0; g < 8; g++) {
            int r0 = m0 + wm + f * 16 + gid;
            int c0 = n0 + wn + g * 8 + tg * 2;
            #pragma unroll
            for (int e = 0; e < 4; e++) {
                int r = r0 + ((e >> 1) << 3);
                int c = c0 + (e & 1);
                if (c >= N) continue;
                float v = acc[f][g][e] * alpha;
                if (bias) v += bias[c];
                if (Res)  v += Res[(long)r * ldc + c];
                if (doRelu) v = fmaxf(v, 0.f);
                C[(long)r * ldc + c] = v;
                if (Chi) {
                    __nv_bfloat16 h, l;
                    bsplit(v, h, l);
                    Chi[(long)r * ldc + c] = h;
                    Clo[(long)r * ldc + c] = l;
                }
            }
        }
    }
}

// ---------------- LayerNorm (fp32 + bf16 hi/lo planes) ----------------
__global__ __launch_bounds__(256) void ln_k(const float* __restrict__ X,
                                            const float* __restrict__ g,
                                            const float* __restrict__ bta,
                                            float* __restrict__ Y,
                                            __nv_bfloat16* __restrict__ Yh,
                                            __nv_bfloat16* __restrict__ Yl)
{
    long row = blockIdx.x;
    const float* xr = X + row * PD;
    int t = threadIdx.x, lane = t & 31, wid = t >> 5;

    float s1 = 0.f, s2 = 0.f;
    for (int c = t; c < PD; c += 256) { float v = xr[c]; s1 += v; s2 += v * v; }
    s1 = warpSum(s1); s2 = warpSum(s2);
    __shared__ float sA[8], sB[8];
    if (lane == 0) { sA[wid] = s1; sB[wid] = s2; }
    __syncthreads();
    float t1 = 0.f, t2 = 0.f;
    #pragma unroll
    for (int wI = 0; wI < 8; wI++) { t1 += sA[wI]; t2 += sB[wI]; }
    float mean = t1 / (float)PD;
    float var  = t2 / (float)PD - mean * mean;
    float rs = rsqrtf(var + 1e-5f);
    for (int c = t; c < PD; c += 256) {
        float v = (xr[c] - mean) * rs * g[c] + bta[c];
        Y[row * PD + c] = v;
        __nv_bfloat16 h, l;
        bsplit(v, h, l);
        Yh[row * PD + c] = h;
        Yl[row * PD + c] = l;
    }
}

// ---------------- elementwise split ----------------
__global__ void split_k(const float* __restrict__ in,
                        __nv_bfloat16* __restrict__ oh,
                        __nv_bfloat16* __restrict__ ol, long n)
{
    for (long i = blockIdx.x * (long)blockDim.x + threadIdx.x; i < n;
         i += (long)gridDim.x * blockDim.x) {
        __nv_bfloat16 h, l;
        bsplit(in[i], h, l);
        oh[i] = h; ol[i] = l;
    }
}

// ---------------- tiled transpose + split: in [K,N] fp32 -> out [N,K] planes ----------------
__global__ void tsplit_k(const float* __restrict__ in,
                         __nv_bfloat16* __restrict__ oh,
                         __nv_bfloat16* __restrict__ ol,
                         int K, int N, int ldin,
                         long sinB, long sinH, long sout, int Hn)
{
    __shared__ float t[32][33];
    int z = blockIdx.z;
    int b = z / Hn, h = z % Hn;
    in += b * sinB + h * sinH;
    oh += (long)z * sout;
    ol += (long)z * sout;
    int kb = blockIdx.y * 32, nb = blockIdx.x * 32;
    int tx = threadIdx.x, ty = threadIdx.y;
    #pragma unroll
    for (int j = 0; j < 32; j += 8) {
        int k = kb + ty + j, n = nb + tx;
        t[ty + j][tx] = (k < K && n < N) ? in[(long)k * ldin + n] : 0.f;
    }
    __syncthreads();
    #pragma unroll
    for (int j = 0; j < 32; j += 8) {
        int n = nb + ty + j, k = kb + tx;
        if (n < N && k < K) {
            __nv_bfloat16 hh, ll;
            bsplit(t[tx][ty + j], hh, ll);
            oh[(long)n * K + k] = hh;
            ol[(long)n * K + k] = ll;
        }
    }
}

// ---------------- batched bf16 plane transpose: [z,R,C] -> [z,C,R] ----------------
__global__ void bt_k(const __nv_bfloat16* __restrict__ ih, const __nv_bfloat16* __restrict__ il,
                     __nv_bfloat16* __restrict__ oh, __nv_bfloat16* __restrict__ ol,
                     int R, int Ccols)
{
    __shared__ uint32_t tb[32][33];
    long z = blockIdx.z;
    long off = z * (long)R * Ccols;
    ih += off; il += off; oh += off; ol += off;
    int rb = blockIdx.y * 32, cb = blockIdx.x * 32;
    int tx = threadIdx.x, ty = threadIdx.y;
    #pragma unroll
    for (int j = 0; j < 32; j += 8) {
        int r = rb + ty + j, c = cb + tx;
        uint32_t h = (uint32_t)__bfloat16_as_ushort(ih[(long)r * Ccols + c]);
        uint32_t l = (uint32_t)__bfloat16_as_ushort(il[(long)r * Ccols + c]);
        tb[ty + j][tx] = h | (l << 16);
    }
    __syncthreads();
    #pragma unroll
    for (int j = 0; j < 32; j += 8) {
        int c = cb + ty + j, r = rb + tx;
        uint32_t v = tb[tx][ty + j];
        oh[(long)c * R + r] = __ushort_as_bfloat16((unsigned short)(v & 0xFFFF));
        ol[(long)c * R + r] = __ushort_as_bfloat16((unsigned short)(v >> 16));
    }
}

// ---------------- Enformer positional features -> bf16 planes ----------------
__global__ void pos_k(__nv_bfloat16* __restrict__ ph, __nv_bfloat16* __restrict__ pl)
{
    int m = blockIdx.x * blockDim.x + threadIdx.x;
    if (m >= PMQ) return;
    float d = (float)(m - (PN1 - 1));
    float ad = fabsf(d);

    float fe[16], fc[16], fg[16];
    float pmax = 0.f;
    const float ln2 = 0.6931471805599453f;
    #pragma unroll
    for (int i = 0; i < 16; i++) {
        float e = 3.0f + 8.0f * (float)i / 15.0f;
        float hl = exp2f(e);
        fe[i] = expf(-ln2 / hl * ad);
        float cw = exp2f((float)(i + 1)) - 1.0f;
        fc[i] = (cw > ad) ? 1.0f : 0.0f;
        float mean = 128.0f * (float)(i + 1);
        float conc = (mean / 64.0f) * (mean / 64.0f);
        float rate = mean / 4096.0f;
        float logp = (conc - 1.0f) * logf(ad) - rate * ad
                   - (lgammaf(conc) - conc * logf(rate));
        float prob = expf(logp) + 1e-8f;
        fg[i] = prob;
        pmax = fmaxf(pmax, prob);
    }
    float sgn = (d > 0.f) ? 1.f : ((d < 0.f) ? -1.f : 0.f);
    float inv = 1.0f / pmax;
    long base = (long)m * PNRP;
    #pragma unroll
    for (int i = 0; i < 16; i++) {
        float gv = fg[i] * inv;
        float vals[6] = { fe[i], fc[i], gv, sgn * fe[i], sgn * fc[i], sgn * gv };
        int offs[6] = { i, 16 + i, 32 + i, 48 + i, 64 + i, 80 + i };
        #pragma unroll
        for (int q = 0; q < 6; q++) {
            __nv_bfloat16 h, l;
            bsplit(vals[q], h, l);
            ph[base + offs[q]] = h;
            pl[base + offs[q]] = l;
        }
    }
}

// ---------------- kb = k*SCALE + rpb -> bf16 planes ----------------
__global__ void kb_k(const float* __restrict__ k, const float* __restrict__ rpb,
                     __nv_bfloat16* __restrict__ kbh, __nv_bfloat16* __restrict__ kbl,
                     int total)
{
    for (int i = blockIdx.x * blockDim.x + threadIdx.x; i < total;
         i += gridDim.x * blockDim.x) {
        float v = k[i] * PSCALE + rpb[i & 511];
        __nv_bfloat16 h, l;
        bsplit(v, h, l);
        kbh[i] = h; kbl[i] = l;
    }
}

// ---------------- tiled softmax: coalesced diagonal-band gather ----------------
// Block handles 32 i-rows x 512 j. smem band: srel[j][di] = rel[z, j, i0+511-j+di].
#define SMXSM (512 * 33 * 4)
__global__ __launch_bounds__(256) void softmax2_k(
    const float* __restrict__ att,                  // content logits [z, i, j]
    const float* __restrict__ rel,                  // [z, j, m]
    __nv_bfloat16* __restrict__ ah, __nv_bfloat16* __restrict__ al)
{
    extern __shared__ float srel[];
    int i0 = blockIdx.x * 32;
    long z = blockIdx.y;
    const float* relz = rel + z * (long)PN2 * PMQ;
    int t = threadIdx.x;

    for (int idx = t; idx < PN2 * 32; idx += 256) {
        int j = idx >> 5, di = idx & 31;
        srel[j * 33 + di] = relz[(long)j * PMQ + (i0 + (PN2 - 1) - j) + di];
    }
    __syncthreads();

    int w = t >> 5, lane = t & 31;
    #pragma unroll
    for (int rr = 0; rr < 4; rr++) {
        int di = w + rr * 8;
        int i = i0 + di;
        long rowoff = (z * PN1 + i) * (long)PN2;
        const float* arow = att + rowoff;
        float v[16];
        float mx = -1e30f;
        #pragma unroll
        for (int u = 0; u < 16; u++) {
            int j = lane + u * 32;
            float val = arow[j] + srel[j * 33 + di];
            v[u] = val;
            mx = fmaxf(mx, val);
        }
        mx = warpMax(mx);
        float s = 0.f;
        #pragma unroll
        for (int u = 0; u < 16; u++) { v[u] = expf(v[u] - mx); s += v[u]; }
        s = warpSum(s);
        float inv = 1.0f / s;
        #pragma unroll
        for (int u = 0; u < 16; u++) {
            int j = lane + u * 32;
            float p = v[u] * inv;
            __nv_bfloat16 h, l;
            bsplit(p, h, l);
            ah[rowoff + j] = h;
            al[rowoff + j] = l;
        }
    }
}

// ---------------- host orchestration ----------------
static inline dim3 ngrid(int M, int N, int Z) {
    return dim3((unsigned)((N + 127) / 128), (unsigned)(M / 128), (unsigned)Z);
}

extern "C" void kernel_launch(void* const* d_in, const int* in_sizes, int n_in,
                              void* d_out, int out_size)
{
    const float* x     = (const float*)d_in[0];
    const float* y0    = (const float*)d_in[1];
    const float* W_res = (const float*)d_in[2];
    const float* lnx_g = (const float*)d_in[3];
    const float* lnx_b = (const float*)d_in[4];
    const float* lny_g = (const float*)d_in[5];
    const float* lny_b = (const float*)d_in[6];
    const float* Wq    = (const float*)d_in[7];
    const float* Wk    = (const float*)d_in[8];
    const float* Wv1   = (const float*)d_in[9];
    const float* Wv2   = (const float*)d_in[10];
    const float* Wo1   = (const float*)d_in[11];
    const float* bo1   = (const float*)d_in[12];
    const float* Wo2   = (const float*)d_in[13];
    const float* bo2   = (const float*)d_in[14];
    const float* Wrel  = (const float*)d_in[15];
    const float* rpb   = (const float*)d_in[16];
    const float* fx_g  = (const float*)d_in[17];
    const float* fx_b  = (const float*)d_in[18];
    const float* fx_w1 = (const float*)d_in[19];
    const float* fx_b1 = (const float*)d_in[20];
    const float* fx_w2 = (const float*)d_in[21];
    const float* fx_b2 = (const float*)d_in[22];
    const float* fy_g  = (const float*)d_in[23];
    const float* fy_b  = (const float*)d_in[24];
    const float* fy_w1 = (const float*)d_in[25];
    const float* fy_b1 = (const float*)d_in[26];
    const float* fy_w2 = (const float*)d_in[27];
    const float* fy_b2 = (const float*)d_in[28];

    cudaFuncSetAttribute(gemm_bf, cudaFuncAttributeMaxDynamicSharedMemorySize, BSMEM);
    cudaFuncSetAttribute(softmax2_k, cudaFuncAttributeMaxDynamicSharedMemorySize, SMXSM);

    float* S = nullptr;
    cudaGetSymbolAddress((void**)&S, g_scratch);
    __nv_bfloat16* BF = nullptr;
    cudaGetSymbolAddress((void**)&BF, g_bf);

    float* gy   = S + OFF_Y;
    float* gx1  = S + OFF_X1;
    float* gy1  = S + OFF_Y1;
    float* gq   = S + OFF_Q;
    float* gk   = S + OFF_K;
    float* gv1  = S + OFF_V1;
    float* gv2  = S + OFF_V2;
    float* grq  = S + OFF_RELQ;
    float* grel = S + OFF_REL;
    float* gatt = S + OFF_ATT;
    float* go1  = S + OFF_OUT1;
    float* go2  = S + OFF_OUT2;
    float* gx4  = S + OFF_X4;
    float* gy4  = S + OFF_Y4;
    float* gh   = S + OFF_HID;

    #define PLH(off) (BF + (off))
    #define PLL(off, sz) (BF + (off) + (sz))

    float* outx = (float*)d_out;
    float* outy = outx + (long)PB * PN1 * PD;

    dim3 tt(32, 8);

    // ---- weight transpose+split ----
    tsplit_k<<<dim3(PD/32, PDY0/32, 1), tt>>>(W_res, PLH(BF_WRT), PLL(BF_WRT,SZ_WRT), PDY0, PD, PD, 0,0,0,1);
    tsplit_k<<<dim3(HDK/32, PD/32, 1), tt>>>(Wq,  PLH(BF_WQT),  PLL(BF_WQT,SZ_WQT),  PD, HDK, HDK, 0,0,0,1);
    tsplit_k<<<dim3(HDK/32, PD/32, 1), tt>>>(Wk,  PLH(BF_WKT),  PLL(BF_WKT,SZ_WKT),  PD, HDK, HDK, 0,0,0,1);
    tsplit_k<<<dim3(HDV/32, PD/32, 1), tt>>>(Wv2, PLH(BF_WV2T), PLL(BF_WV2T,SZ_WV2T), PD, HDV, HDV, 0,0,0,1);
    tsplit_k<<<dim3(HDV/32, PD/32, 1), tt>>>(Wv1, PLH(BF_WV1T), PLL(BF_WV1T,SZ_WV1T), PD, HDV, HDV, 0,0,0,1);
    tsplit_k<<<dim3(PD/32, HDV/32, 1), tt>>>(Wo1, PLH(BF_WO1T), PLL(BF_WO1T,SZ_WO1T), HDV, PD, PD, 0,0,0,1);
    tsplit_k<<<dim3(PD/32, HDV/32, 1), tt>>>(Wo2, PLH(BF_WO2T), PLL(BF_WO2T,SZ_WO2T), HDV, PD, PD, 0,0,0,1);
    tsplit_k<<<dim3(HDK/32, PNRP/32, 1), tt>>>(Wrel, PLH(BF_WRELT), PLL(BF_WRELT,SZ_WRELT), PNRP, HDK, HDK, 0,0,0,1);
    tsplit_k<<<dim3(PDFF/32, PD/32, 1), tt>>>(fx_w1, PLH(BF_FX1T), PLL(BF_FX1T,SZ_F1), PD, PDFF, PDFF, 0,0,0,1);
    tsplit_k<<<dim3(PD/32, PDFF/32, 1), tt>>>(fx_w2, PLH(BF_FX2T), PLL(BF_FX2T,SZ_F2), PDFF, PD, PD, 0,0,0,1);
    tsplit_k<<<dim3(PDFF/32, PD/32, 1), tt>>>(fy_w1, PLH(BF_FY1T), PLL(BF_FY1T,SZ_F1), PD, PDFF, PDFF, 0,0,0,1);
    tsplit_k<<<dim3(PD/32, PDFF/32, 1), tt>>>(fy_w2, PLH(BF_FY2T), PLL(BF_FY2T,SZ_F2), PDFF, PD, PD, 0,0,0,1);

    // ---- inputs ----
    ln_k<<<PB * PN1, 256>>>(x, lnx_g, lnx_b, gx1, PLH(BF_X1), PLL(BF_X1,SZ_X1));
    split_k<<<2048, 256>>>(y0, PLH(BF_Y0), PLL(BF_Y0,SZ_Y0), SZ_Y0);

    // y = y0 @ W_res
    gemm_bf<<<ngrid(PB*PN2, PD, 1), 256, BSMEM>>>(
        PLH(BF_Y0), PLL(BF_Y0,SZ_Y0), PLH(BF_WRT), PLL(BF_WRT,SZ_WRT),
        nullptr, nullptr, gy, nullptr, nullptr,
        PB*PN2, PD, PDY0, PDY0, PDY0, PD, 0,0,0,0,0,0, 1, 1.f, 0);
    ln_k<<<PB * PN2, 256>>>(gy, lny_g, lny_b, gy1, PLH(BF_Y1), PLL(BF_Y1,SZ_Y1));

    // q (pre-scaled), k, v2, v1
    gemm_bf<<<ngrid(PB*PN1, HDK, 1), 256, BSMEM>>>(
        PLH(BF_X1), PLL(BF_X1,SZ_X1), PLH(BF_WQT), PLL(BF_WQT,SZ_WQT),
        nullptr, nullptr, gq, PLH(BF_Q), PLL(BF_Q,SZ_Q),
        PB*PN1, HDK, PD, PD, PD, HDK, 0,0,0,0,0,0, 1, PSCALE, 0);
    gemm_bf<<<ngrid(PB*PN2, HDK, 1), 256, BSMEM>>>(
        PLH(BF_Y1), PLL(BF_Y1,SZ_Y1), PLH(BF_WKT), PLL(BF_WKT,SZ_WKT),
        nullptr, nullptr, gk, PLH(BF_K), PLL(BF_K,SZ_K),
        PB*PN2, HDK, PD, PD, PD, HDK, 0,0,0,0,0,0, 1, 1.f, 0);
    gemm_bf<<<ngrid(PB*PN2, HDV, 1), 256, BSMEM>>>(
        PLH(BF_Y1), PLL(BF_Y1,SZ_Y1), PLH(BF_WV2T), PLL(BF_WV2T,SZ_WV2T),
        nullptr, nullptr, gv2, nullptr, nullptr,
        PB*PN2, HDV, PD, PD, PD, HDV, 0,0,0,0,0,0, 1, 1.f, 0);
    gemm_bf<<<ngrid(PB*PN1, HDV, 1), 256, BSMEM>>>(
        PLH(BF_X1), PLL(BF_X1,SZ_X1), PLH(BF_WV1T), PLL(BF_WV1T,SZ_WV1T),
        nullptr, nullptr, gv1, nullptr, nullptr,
        PB*PN1, HDV, PD, PD, PD, HDV, 0,0,0,0,0,0, 1, 1.f, 0);

    // v2T / v1T planes per (b,h)
    tsplit_k<<<dim3(PDV/32, PN2/32, PB*PH), tt>>>(
        gv2, PLH(BF_V2T), PLL(BF_V2T,SZ_V2T), PN2, PDV, HDV,
        (long)PN2*HDV, (long)PDV, (long)PDV*PN2, PH);
    tsplit_k<<<dim3(PDV/32, PN1/32, PB*PH), tt>>>(
        gv1, PLH(BF_V1T), PLL(BF_V1T,SZ_V1T), PN1, PDV, HDV,
        (long)PN1*HDV, (long)PDV, (long)PDV*PN1, PH);

    // pos features (planes) + rel_q = pos @ Wrel^T^T  (epilogue split)
    pos_k<<<(PMQ + 127) / 128, 128>>>(PLH(BF_POS), PLL(BF_POS,SZ_POS));
    gemm_bf<<<ngrid(PMQ, HDK, 1), 256, BSMEM>>>(
        PLH(BF_POS), PLL(BF_POS,SZ_POS), PLH(BF_WRELT), PLL(BF_WRELT,SZ_WRELT),
        nullptr, nullptr, grq, PLH(BF_RQ), PLL(BF_RQ,SZ_RQ),
        PMQ, HDK, PNRP, PNRP, PNRP, HDK, 0,0,0,0,0,0, 1, 1.f, 0);

    // kb planes
    kb_k<<<2048, 256>>>(gk, rpb, PLH(BF_KB), PLL(BF_KB,SZ_KB), PB*PN2*HDK);

    // content = q_scaled @ k^T (batched over b,h)
    gemm_bf<<<ngrid(PN1, PN2, PB*PH), 256, BSMEM>>>(
        PLH(BF_Q), PLL(BF_Q,SZ_Q), PLH(BF_K), PLL(BF_K,SZ_K),
        nullptr, nullptr, gatt, nullptr, nullptr,
        PN1, PN2, PDK, HDK, HDK, PN2,
        (long)PN1*HDK, (long)PDK, (long)PN2*HDK, (long)PDK,
        (long)PH*PN1*PN2, (long)PN1*PN2, PH, 1.f, 0);

    // rel = kb @ rel_q^T (batched; rel_q shared across b)
    gemm_bf<<<ngrid(PN2, PMQ, PB*PH), 256, BSMEM>>>(
        PLH(BF_KB), PLL(BF_KB,SZ_KB), PLH(BF_RQ), PLL(BF_RQ,SZ_RQ),
        nullptr, nullptr, grel, nullptr, nullptr,
        PN2, PMQ, PDK, HDK, HDK, PMQ,
        (long)PN2*HDK, (long)PDK, 0L, (long)PDK,
        (long)PH*PN2*PMQ, (long)PN2*PMQ, PH, 1.f, 0);

    // tiled softmax -> att planes
    softmax2_k<<<dim3(PN1/32, PB*PH), 256, SMXSM>>>(
        gatt, grel, PLH(BF_ATT), PLL(BF_ATT,SZ_ATT));

    // attT planes for out2
    bt_k<<<dim3(PN2/32, PN1/32, PB*PH), tt>>>(
        PLH(BF_ATT), PLL(BF_ATT,SZ_ATT), PLH(BF_ATTT), PLL(BF_ATTT,SZ_ATTT), PN1, PN2);

    // out1 = attn @ v2 (epilogue split)
    gemm_bf<<<ngrid(PN1, PDV, PB*PH), 256, BSMEM>>>(
        PLH(BF_ATT), PLL(BF_ATT,SZ_ATT), PLH(BF_V2T), PLL(BF_V2T,SZ_V2T),
        nullptr, nullptr, go1, PLH(BF_GO1), PLL(BF_GO1,SZ_GO1),
        PN1, PDV, PN2, PN2, PN2, HDV,
        (long)PH*PN1*PN2, (long)PN1*PN2, (long)PH*PDV*PN2, (long)PDV*PN2,
        (long)PN1*HDV, (long)PDV, PH, 1.f, 0);

    // out2 = attn^T @ v1 (epilogue split)
    gemm_bf<<<ngrid(PN2, PDV, PB*PH), 256, BSMEM>>>(
        PLH(BF_ATTT), PLL(BF_ATTT,SZ_ATTT), PLH(BF_V1T), PLL(BF_V1T,SZ_V1T),
        nullptr, nullptr, go2, PLH(BF_GO2), PLL(BF_GO2,SZ_GO2),
        PN2, PDV, PN1, PN1, PN1, HDV,
        (long)PH*PN2*PN1, (long)PN2*PN1, (long)PH*PDV*PN1, (long)PDV*PN1,
        (long)PN2*HDV, (long)PDV, PH, 1.f, 0);

    // x4 = x + out1 @ Wo1 + bo1 ; y4 = y + out2 @ Wo2 + bo2
    gemm_bf<<<ngrid(PB*PN1, PD, 1), 256, BSMEM>>>(
        PLH(BF_GO1), PLL(BF_GO1,SZ_GO1), PLH(BF_WO1T), PLL(BF_WO1T,SZ_WO1T),
        bo1, x, gx4, nullptr, nullptr,
        PB*PN1, PD, HDV, HDV, HDV, PD, 0,0,0,0,0,0, 1, 1.f, 0);
    gemm_bf<<<ngrid(PB*PN2, PD, 1), 256, BSMEM>>>(
        PLH(BF_GO2), PLL(BF_GO2,SZ_GO2), PLH(BF_WO2T), PLL(BF_WO2T,SZ_WO2T),
        bo2, gy, gy4, nullptr, nullptr,
        PB*PN2, PD, HDV, HDV, HDV, PD, 0,0,0,0,0,0, 1, 1.f, 0);

    // FFN x
    ln_k<<<PB * PN1, 256>>>(gx4, fx_g, fx_b, gx1, PLH(BF_X1), PLL(BF_X1,SZ_X1));
    gemm_bf<<<ngrid(PB*PN1, PDFF, 1), 256, BSMEM>>>(
        PLH(BF_X1), PLL(BF_X1,SZ_X1), PLH(BF_FX1T), PLL(BF_FX1T,SZ_F1),
        fx_b1, nullptr, gh, PLH(BF_GH), PLL(BF_GH,SZ_GH),
        PB*PN1, PDFF, PD, PD, PD, PDFF, 0,0,0,0,0,0, 1, 1.f, 1);
    gemm_bf<<<ngrid(PB*PN1, PD, 1), 256, BSMEM>>>(
        PLH(BF_GH), PLL(BF_GH,SZ_GH), PLH(BF_FX2T), PLL(BF_FX2T,SZ_F2),
        fx_b2, gx4, outx, nullptr, nullptr,
        PB*PN1, PD, PDFF, PDFF, PDFF, PD, 0,0,0,0,0,0, 1, 1.f, 0);

    // FFN y
    ln_k<<<PB * PN2, 256>>>(gy4, fy_g, fy_b, gy1, PLH(BF_Y1), PLL(BF_Y1,SZ_Y1));
    gemm_bf<<<ngrid(PB*PN2, PDFF, 1), 256, BSMEM>>>(
        PLH(BF_Y1), PLL(BF_Y1,SZ_Y1), PLH(BF_FY1T), PLL(BF_FY1T,SZ_F1),
        fy_b1, nullptr, gh, PLH(BF_GH), PLL(BF_GH,SZ_GH),
        PB*PN2, PDFF, PD, PD, PD, PDFF, 0,0,0,0,0,0, 1, 1.f, 1);
    gemm_bf<<<ngrid(PB*PN2, PD, 1), 256, BSMEM>>>(
        PLH(BF_GH), PLL(BF_GH,SZ_GH), PLH(BF_FY2T), PLL(BF_FY2T,SZ_F2),
        fy_b2, gy4, outy, nullptr, nullptr,
        PB*PN2, PD, PDFF, PDFF, PDFF, PD, 0,0,0,0,0,0, 1, 1.f, 0);

    (void)in_sizes; (void)n_in; (void)out_size;
}

// round 10
// speedup vs baseline: 2.2023x; 1.0511x over previous
#include <cuda_runtime.h>
#include <cuda_bf16.h>
#include <cstdint>
#include <math.h>

// ---------------- problem constants ----------------
#define PB   4
#define PN1  2048
#define PN2  512
#define PD   768
#define PH   8
#define PDK  64
#define PDV  96
#define PNRP 96
#define PDY0 1536
#define PDFF 1536
#define PMQ  2560              // needed pos rows: m = i - j + 511 in [0, 2558]
#define PSCALE 0.125f          // DK^-0.5
#define HDK  512
#define HDV  768

// ---------------- fp32 scratch ----------------
#define OFF_Y      0L
#define OFF_Y1     (OFF_Y    + (long)PB*PN2*PD)
#define OFF_K      (OFF_Y1   + (long)PB*PN2*PD)
#define OFF_V1     (OFF_K    + (long)PB*PN2*HDK)
#define OFF_V2     (OFF_V1   + (long)PB*PN1*HDV)
#define OFF_REL    (OFF_V2   + (long)PB*PN2*HDV)
#define OFF_ATT    (OFF_REL  + (long)PB*PH*PN2*PMQ)
#define OFF_X4     (OFF_ATT  + (long)PB*PH*PN1*PN2)
#define OFF_Y4     (OFF_X4   + (long)PB*PN1*PD)
#define OFF_X1     (OFF_Y4   + (long)PB*PN2*PD)
#define SCRATCH_TOTAL (OFF_X1 + (long)PB*PN1*PD)
__device__ float g_scratch[SCRATCH_TOTAL];

// ---------------- bf16 plane scratch ----------------
#define SZ_X1   ((long)PB*PN1*PD)
#define SZ_Y1   ((long)PB*PN2*PD)
#define SZ_Y0   ((long)PB*PN2*PDY0)
#define SZ_Q    ((long)PB*PN1*HDK)
#define SZ_K    ((long)PB*PN2*HDK)
#define SZ_KB   ((long)PB*PN2*HDK)
#define SZ_RQ   ((long)PMQ*HDK)
#define SZ_ATT  ((long)PB*PH*PN1*PN2)
#define SZ_ATTT ((long)PB*PH*PN1*PN2)
#define SZ_V2T  ((long)PB*PH*PDV*PN2)
#define SZ_V1T  ((long)PB*PH*PDV*PN1)
#define SZ_GO1  ((long)PB*PN1*HDV)
#define SZ_GO2  ((long)PB*PN2*HDV)
#define SZ_GH   ((long)PB*PN1*PDFF)
#define SZ_POS  ((long)PMQ*PNRP)
#define SZ_WRT  ((long)PDY0*PD)
#define SZ_WRELT ((long)HDK*PNRP)
#define SZ_WQT  ((long)PD*HDK)
#define SZ_WKT  ((long)PD*HDK)
#define SZ_WV2T ((long)PD*HDV)
#define SZ_WV1T ((long)PD*HDV)
#define SZ_WO1T ((long)HDV*PD)
#define SZ_WO2T ((long)HDV*PD)
#define SZ_F1   ((long)PD*PDFF)
#define SZ_F2   ((long)PDFF*PD)

#define BF_X1   0L
#define BF_Y1   (BF_X1   + 2*SZ_X1)
#define BF_Y0   (BF_Y1   + 2*SZ_Y1)
#define BF_Q    (BF_Y0   + 2*SZ_Y0)
#define BF_K    (BF_Q    + 2*SZ_Q)
#define BF_KB   (BF_K    + 2*SZ_K)
#define BF_RQ   (BF_KB   + 2*SZ_KB)
#define BF_ATT  (BF_RQ   + 2*SZ_RQ)
#define BF_ATTT (BF_ATT  + SZ_ATT)            // single plane
#define BF_V2T  (BF_ATTT + SZ_ATTT)           // single plane
#define BF_V1T  (BF_V2T  + 2*SZ_V2T)
#define BF_GO1  (BF_V1T  + 2*SZ_V1T)
#define BF_GO2  (BF_GO1  + 2*SZ_GO1)
#define BF_GH   (BF_GO2  + 2*SZ_GO2)
#define BF_POS  (BF_GH   + 2*SZ_GH)
#define BF_WRT  (BF_POS  + 2*SZ_POS)
#define BF_WRELT (BF_WRT + 2*SZ_WRT)
#define BF_WQT  (BF_WRELT+ 2*SZ_WRELT)
#define BF_WKT  (BF_WQT  + 2*SZ_WQT)
#define BF_WV2T (BF_WKT  + 2*SZ_WKT)
#define BF_WV1T (BF_WV2T + 2*SZ_WV2T)
#define BF_WO1T (BF_WV1T + 2*SZ_WV1T)
#define BF_WO2T (BF_WO1T + 2*SZ_WO1T)
#define BF_FX1T (BF_WO2T + 2*SZ_WO2T)
#define BF_FX2T (BF_FX1T + 2*SZ_F1)
#define BF_FY1T (BF_FX2T + 2*SZ_F2)
#define BF_FY2T (BF_FY1T + 2*SZ_F1)
#define BF_TOTAL (BF_FY2T+ 2*SZ_F2)
__device__ __align__(256) __nv_bfloat16 g_bf[BF_TOTAL];

// =================== helpers ===================
__device__ __forceinline__ uint32_t sptr(const void* p) {
    return (uint32_t)__cvta_generic_to_shared(p);
}
__device__ __forceinline__ void ldsm4(uint32_t r[4], const __nv_bfloat16* p) {
    uint32_t a = sptr(p);
    asm volatile("ldmatrix.sync.aligned.m8n8.x4.shared.b16 {%0,%1,%2,%3}, [%4];"
                 : "=r"(r[0]), "=r"(r[1]), "=r"(r[2]), "=r"(r[3]) : "r"(a));
}
__device__ __forceinline__ void mma16816(float c[4], const uint32_t a[4], uint32_t b0, uint32_t b1) {
    asm volatile(
        "mma.sync.aligned.m16n8k16.row.col.f32.bf16.bf16.f32 "
        "{%0,%1,%2,%3}, {%4,%5,%6,%7}, {%8,%9}, {%0,%1,%2,%3};"
        : "+f"(c[0]), "+f"(c[1]), "+f"(c[2]), "+f"(c[3])
        : "r"(a[0]), "r"(a[1]), "r"(a[2]), "r"(a[3]), "r"(b0), "r"(b1));
}
__device__ __forceinline__ void bsplit(float x, __nv_bfloat16& h, __nv_bfloat16& l) {
    h = __float2bfloat16(x);
    l = __float2bfloat16(x - __bfloat162float(h));
}
__device__ __forceinline__ void cpa16(uint32_t saddr, const void* g, bool pred) {
    int sz = pred ? 16 : 0;
    asm volatile("cp.async.cg.shared.global [%0], [%1], 16, %2;"
                 :: "r"(saddr), "l"(g), "r"(sz) : "memory");
}
__device__ __forceinline__ void cpa_commit() {
    asm volatile("cp.async.commit_group;" ::: "memory");
}
template<int NW> __device__ __forceinline__ void cpa_wait() {
    asm volatile("cp.async.wait_group %0;" :: "n"(NW) : "memory");
}
__device__ __forceinline__ float warpSum(float v) {
    #pragma unroll
    for (int o = 16; o; o >>= 1) v += __shfl_xor_sync(0xffffffffu, v, o);
    return v;
}
__device__ __forceinline__ float warpMax(float v) {
    #pragma unroll
    for (int o = 16; o; o >>= 1) v = fmaxf(v, __shfl_xor_sync(0xffffffffu, v, o));
    return v;
}

// =================== pre-split bf16 GEMM with cp.async ===================
// C = alpha*(A @ B^T) (+bias)(+Res)(relu).  A=[M,K] planes (lo optional),
// B=[N,K] planes, all k-contig. C fp32 optional; Chi/Clo planes optional.
// CTA tile 128 x BN (BN=128 or 96), BK=32, 8 warps 4m x 2n, warp 32 x BN/2.
// 2-stage cp.async ring. M%128==0, K%32==0; N guarded vs BN grid.
#define SA   40
#define BTSZ (128 * SA)          // halfwords per plane slot per stage
#define BSTG (4 * BTSZ)          // halfwords per stage
#define BSMEM (2 * BSTG * 2)     // bytes = 81920

template <int BN, bool UAL>
__global__ __launch_bounds__(256, 2) void gemm_bf(
    const __nv_bfloat16* __restrict__ Ah, const __nv_bfloat16* __restrict__ Al,
    const __nv_bfloat16* __restrict__ Bh, const __nv_bfloat16* __restrict__ Bl,
    const float* __restrict__ bias, const float* __restrict__ Res,
    float* __restrict__ C, __nv_bfloat16* __restrict__ Chi, __nv_bfloat16* __restrict__ Clo,
    int M, int N, int K, int lda, int ldb, int ldc,
    long sAb, long sAh_, long sBb, long sBh_, long sCb, long sCh_, int Hn,
    float alpha, int doRelu)
{
    constexpr int NG = BN / 32;          // #16-col B groups per warp tile
    int z = blockIdx.z;
    int bb = z / Hn, hh = z % Hn;
    long ao = bb * sAb + hh * sAh_;
    long bo = bb * sBb + hh * sBh_;
    long co = bb * sCb + hh * sCh_;
    Ah += ao; if (UAL) Al += ao;
    Bh += bo; Bl += bo;
    if (C) C += co;
    if (Res) Res += co;
    if (Chi) { Chi += co; Clo += co; }

    extern __shared__ __nv_bfloat16 sm[];
    uint32_t sbase = sptr(sm);

    int m0 = blockIdx.y * 128;
    int n0 = blockIdx.x * BN;
    int tid = threadIdx.x, w = tid >> 5, lane = tid & 31;
    int wm = (w & 3) * 32;
    int wn = (w >> 2) * (BN / 2);

    float acc[2][2 * NG][4];
    #pragma unroll
    for (int f = 0; f < 2; f++)
        #pragma unroll
        for (int g = 0; g < 2 * NG; g++)
            #pragma unroll
            for (int e = 0; e < 4; e++) acc[f][g][e] = 0.f;

    int nk = K >> 5;

    auto issue = [&](int s, int buf) {
        int k0 = s << 5;
        uint32_t st = sbase + (uint32_t)buf * (BSTG * 2);
        constexpr int AIT = UAL ? 4 : 2;           // A: (1 or 2 planes) x 128r x 4seg
        #pragma unroll
        for (int i = 0; i < AIT; i++) {
            int idx = tid + i * 256;
            int pl = idx >> 9, rem = idx & 511, row = rem >> 2, seg = rem & 3;
            const __nv_bfloat16* g = (pl ? Al : Ah) + (long)(m0 + row) * lda + k0 + seg * 8;
            cpa16(st + (uint32_t)(pl * BTSZ + row * SA + seg * 8) * 2, g, true);
        }
        constexpr int BIT = (BN * 8) / 256;        // B: 2 planes x BN rows x 4 seg
        #pragma unroll
        for (int i = 0; i < BIT; i++) {
            int idx = tid + i * 256;
            int pl = idx / (BN * 4), rem = idx % (BN * 4), row = rem >> 2, seg = rem & 3;
            int rg = n0 + row;
            int rc = (rg < N) ? rg : 0;
            const __nv_bfloat16* g = (pl ? Bl : Bh) + (long)rc * ldb + k0 + seg * 8;
            cpa16(st + (uint32_t)((2 + pl) * BTSZ + row * SA + seg * 8) * 2, g, rg < N);
        }
        cpa_commit();
    };

    issue(0, 0);
    issue(1, 1);

    for (int s = 0; s < nk; s++) {
        if (s + 2 <= nk) cpa_wait<1>(); else cpa_wait<0>();
        __syncthreads();

        const __nv_bfloat16* base = sm + (s & 1) * BSTG;
        const __nv_bfloat16* pAh = base;
        const __nv_bfloat16* pAl = base + BTSZ;
        const __nv_bfloat16* pBh = base + 2 * BTSZ;
        const __nv_bfloat16* pBl = base + 3 * BTSZ;

        #pragma unroll
        for (int kk = 0; kk < 32; kk += 16) {
            uint32_t ah[2][4], al[2][4];
            #pragma unroll
            for (int f = 0; f < 2; f++) {
                int r = wm + f * 16 + (lane & 15);
                int c = kk + ((lane >> 4) << 3);
                ldsm4(ah[f], pAh + r * SA + c);
                if (UAL) ldsm4(al[f], pAl + r * SA + c);
            }
            #pragma unroll
            for (int gp = 0; gp < NG; gp++) {
                int r = wn + gp * 16 + (lane & 7) + ((lane >> 4) << 3);
                int c = kk + (((lane >> 3) & 1) << 3);
                uint32_t th[4], tl[4];
                ldsm4(th, pBh + r * SA + c);
                ldsm4(tl, pBl + r * SA + c);
                #pragma unroll
                for (int f = 0; f < 2; f++) {
                    mma16816(acc[f][2*gp],   ah[f], th[0], th[1]);
                    if (UAL) mma16816(acc[f][2*gp], al[f], th[0], th[1]);
                    mma16816(acc[f][2*gp],   ah[f], tl[0], tl[1]);
                    mma16816(acc[f][2*gp+1], ah[f], th[2], th[3]);
                    if (UAL) mma16816(acc[f][2*gp+1], al[f], th[2], th[3]);
                    mma16816(acc[f][2*gp+1], ah[f], tl[2], tl[3]);
                }
            }
        }
        __syncthreads();
        if (s + 2 < nk) issue(s + 2, s & 1);
    }

    // ---- epilogue ----
    int gid = lane >> 2, tg = lane & 3;
    #pragma unroll
    for (int f = 0; f < 2; f++) {
        #pragma unroll
        for (int g = 0; g < 2 * NG; g++) {
            int r0 = m0 + wm + f * 16 + gid;
            int c0 = n0 + wn + g * 8 + tg * 2;
            #pragma unroll
            for (int e = 0; e < 4; e++) {
                int r = r0 + ((e >> 1) << 3);
                int c = c0 + (e & 1);
                if (c >= N) continue;
                float v = acc[f][g][e] * alpha;
                if (bias) v += bias[c];
                if (Res)  v += Res[(long)r * ldc + c];
                if (doRelu) v = fmaxf(v, 0.f);
                if (C) C[(long)r * ldc + c] = v;
                if (Chi) {
                    __nv_bfloat16 h, l;
                    bsplit(v, h, l);
                    Chi[(long)r * ldc + c] = h;
                    Clo[(long)r * ldc + c] = l;
                }
            }
        }
    }
}

// ---------------- LayerNorm (fp32 + bf16 hi/lo planes) ----------------
__global__ __launch_bounds__(256) void ln_k(const float* __restrict__ X,
                                            const float* __restrict__ g,
                                            const float* __restrict__ bta,
                                            float* __restrict__ Y,
                                            __nv_bfloat16* __restrict__ Yh,
                                            __nv_bfloat16* __restrict__ Yl)
{
    long row = blockIdx.x;
    const float* xr = X + row * PD;
    int t = threadIdx.x, lane = t & 31, wid = t >> 5;

    float s1 = 0.f, s2 = 0.f;
    for (int c = t; c < PD; c += 256) { float v = xr[c]; s1 += v; s2 += v * v; }
    s1 = warpSum(s1); s2 = warpSum(s2);
    __shared__ float sA[8], sB[8];
    if (lane == 0) { sA[wid] = s1; sB[wid] = s2; }
    __syncthreads();
    float t1 = 0.f, t2 = 0.f;
    #pragma unroll
    for (int wI = 0; wI < 8; wI++) { t1 += sA[wI]; t2 += sB[wI]; }
    float mean = t1 / (float)PD;
    float var  = t2 / (float)PD - mean * mean;
    float rs = rsqrtf(var + 1e-5f);
    for (int c = t; c < PD; c += 256) {
        float v = (xr[c] - mean) * rs * g[c] + bta[c];
        if (Y) Y[row * PD + c] = v;
        __nv_bfloat16 h, l;
        bsplit(v, h, l);
        Yh[row * PD + c] = h;
        Yl[row * PD + c] = l;
    }
}

// ---------------- elementwise split ----------------
__global__ void split_k(const float* __restrict__ in,
                        __nv_bfloat16* __restrict__ oh,
                        __nv_bfloat16* __restrict__ ol, long n)
{
    for (long i = blockIdx.x * (long)blockDim.x + threadIdx.x; i < n;
         i += (long)gridDim.x * blockDim.x) {
        __nv_bfloat16 h, l;
        bsplit(in[i], h, l);
        oh[i] = h; ol[i] = l;
    }
}

// ---------------- tiled transpose + split: in [K,N] fp32 -> out [N,K] planes ----------------
__global__ void tsplit_k(const float* __restrict__ in,
                         __nv_bfloat16* __restrict__ oh,
                         __nv_bfloat16* __restrict__ ol,
                         int K, int N, int ldin,
                         long sinB, long sinH, long sout, int Hn)
{
    __shared__ float t[32][33];
    int z = blockIdx.z;
    int b = z / Hn, h = z % Hn;
    in += b * sinB + h * sinH;
    oh += (long)z * sout;
    if (ol) ol += (long)z * sout;
    int kb = blockIdx.y * 32, nb = blockIdx.x * 32;
    int tx = threadIdx.x, ty = threadIdx.y;
    #pragma unroll
    for (int j = 0; j < 32; j += 8) {
        int k = kb + ty + j, n = nb + tx;
        t[ty + j][tx] = (k < K && n < N) ? in[(long)k * ldin + n] : 0.f;
    }
    __syncthreads();
    #pragma unroll
    for (int j = 0; j < 32; j += 8) {
        int n = nb + ty + j, k = kb + tx;
        if (n < N && k < K) {
            __nv_bfloat16 hh, ll;
            bsplit(t[tx][ty + j], hh, ll);
            oh[(long)n * K + k] = hh;
            if (ol) ol[(long)n * K + k] = ll;
        }
    }
}

// ---------------- batched single-plane bf16 transpose: [z,R,C] -> [z,C,R] ----------------
__global__ void bt_k(const __nv_bfloat16* __restrict__ ih,
                     __nv_bfloat16* __restrict__ oh,
                     int R, int Ccols)
{
    __shared__ unsigned short tb[32][33];
    long z = blockIdx.z;
    long off = z * (long)R * Ccols;
    ih += off; oh += off;
    int rb = blockIdx.y * 32, cb = blockIdx.x * 32;
    int tx = threadIdx.x, ty = threadIdx.y;
    #pragma unroll
    for (int j = 0; j < 32; j += 8) {
        int r = rb + ty + j, c = cb + tx;
        tb[ty + j][tx] = __bfloat16_as_ushort(ih[(long)r * Ccols + c]);
    }
    __syncthreads();
    #pragma unroll
    for (int j = 0; j < 32; j += 8) {
        int c = cb + ty + j, r = rb + tx;
        oh[(long)c * R + r] = __ushort_as_bfloat16(tb[tx][ty + j]);
    }
}

// ---------------- Enformer positional features -> bf16 planes ----------------
__global__ void pos_k(__nv_bfloat16* __restrict__ ph, __nv_bfloat16* __restrict__ pl)
{
    int m = blockIdx.x * blockDim.x + threadIdx.x;
    if (m >= PMQ) return;
    float d = (float)(m - (PN1 - 1));
    float ad = fabsf(d);

    float fe[16], fc[16], fg[16];
    float pmax = 0.f;
    const float ln2 = 0.6931471805599453f;
    #pragma unroll
    for (int i = 0; i < 16; i++) {
        float e = 3.0f + 8.0f * (float)i / 15.0f;
        float hl = exp2f(e);
        fe[i] = expf(-ln2 / hl * ad);
        float cw = exp2f((float)(i + 1)) - 1.0f;
        fc[i] = (cw > ad) ? 1.0f : 0.0f;
        float mean = 128.0f * (float)(i + 1);
        float conc = (mean / 64.0f) * (mean / 64.0f);
        float rate = mean / 4096.0f;
        float logp = (conc - 1.0f) * logf(ad) - rate * ad
                   - (lgammaf(conc) - conc * logf(rate));
        float prob = expf(logp) + 1e-8f;
        fg[i] = prob;
        pmax = fmaxf(pmax, prob);
    }
    float sgn = (d > 0.f) ? 1.f : ((d < 0.f) ? -1.f : 0.f);
    float inv = 1.0f / pmax;
    long base = (long)m * PNRP;
    #pragma unroll
    for (int i = 0; i < 16; i++) {
        float gv = fg[i] * inv;
        float vals[6] = { fe[i], fc[i], gv, sgn * fe[i], sgn * fc[i], sgn * gv };
        int offs[6] = { i, 16 + i, 32 + i, 48 + i, 64 + i, 80 + i };
        #pragma unroll
        for (int q = 0; q < 6; q++) {
            __nv_bfloat16 h, l;
            bsplit(vals[q], h, l);
            ph[base + offs[q]] = h;
            pl[base + offs[q]] = l;
        }
    }
}

// ---------------- kb = k*SCALE + rpb -> bf16 planes ----------------
__global__ void kb_k(const float* __restrict__ k, const float* __restrict__ rpb,
                     __nv_bfloat16* __restrict__ kbh, __nv_bfloat16* __restrict__ kbl,
                     int total)
{
    for (int i = blockIdx.x * blockDim.x + threadIdx.x; i < total;
         i += gridDim.x * blockDim.x) {
        float v = k[i] * PSCALE + rpb[i & 511];
        __nv_bfloat16 h, l;
        bsplit(v, h, l);
        kbh[i] = h; kbl[i] = l;
    }
}

// ---------------- tiled softmax: coalesced diagonal-band gather ----------------
// Block: 32 i-rows x 512 j. srel[j][di] = rel[z, j, i0+511-j+di]. Output: bf16 probs.
#define SMXSM (512 * 33 * 4)
__global__ __launch_bounds__(256) void softmax2_k(
    const float* __restrict__ att,                  // content logits [z, i, j]
    const float* __restrict__ rel,                  // [z, j, m]
    __nv_bfloat16* __restrict__ ah)
{
    extern __shared__ float srel[];
    int i0 = blockIdx.x * 32;
    long z = blockIdx.y;
    const float* relz = rel + z * (long)PN2 * PMQ;
    int t = threadIdx.x;

    for (int idx = t; idx < PN2 * 32; idx += 256) {
        int j = idx >> 5, di = idx & 31;
        srel[j * 33 + di] = relz[(long)j * PMQ + (i0 + (PN2 - 1) - j) + di];
    }
    __syncthreads();

    int w = t >> 5, lane = t & 31;
    #pragma unroll
    for (int rr = 0; rr < 4; rr++) {
        int di = w + rr * 8;
        int i = i0 + di;
        long rowoff = (z * PN1 + i) * (long)PN2;
        const float* arow = att + rowoff;
        float v[16];
        float mx = -1e30f;
        #pragma unroll
        for (int u = 0; u < 16; u++) {
            int j = lane + u * 32;
            float val = arow[j] + srel[j * 33 + di];
            v[u] = val;
            mx = fmaxf(mx, val);
        }
        mx = warpMax(mx);
        float s = 0.f;
        #pragma unroll
        for (int u = 0; u < 16; u++) { v[u] = expf(v[u] - mx); s += v[u]; }
        s = warpSum(s);
        float inv = 1.0f / s;
        #pragma unroll
        for (int u = 0; u < 16; u++) {
            int j = lane + u * 32;
            ah[rowoff + j] = __float2bfloat16(v[u] * inv);
        }
    }
}

// ---------------- host orchestration ----------------
static inline dim3 ngrid(int M, int N, int BN, int Z) {
    return dim3((unsigned)((N + BN - 1) / BN), (unsigned)(M / 128), (unsigned)Z);
}

extern "C" void kernel_launch(void* const* d_in, const int* in_sizes, int n_in,
                              void* d_out, int out_size)
{
    const float* x     = (const float*)d_in[0];
    const float* y0    = (const float*)d_in[1];
    const float* W_res = (const float*)d_in[2];
    const float* lnx_g = (const float*)d_in[3];
    const float* lnx_b = (const float*)d_in[4];
    const float* lny_g = (const float*)d_in[5];
    const float* lny_b = (const float*)d_in[6];
    const float* Wq    = (const float*)d_in[7];
    const float* Wk    = (const float*)d_in[8];
    const float* Wv1   = (const float*)d_in[9];
    const float* Wv2   = (const float*)d_in[10];
    const float* Wo1   = (const float*)d_in[11];
    const float* bo1   = (const float*)d_in[12];
    const float* Wo2   = (const float*)d_in[13];
    const float* bo2   = (const float*)d_in[14];
    const float* Wrel  = (const float*)d_in[15];
    const float* rpb   = (const float*)d_in[16];
    const float* fx_g  = (const float*)d_in[17];
    const float* fx_b  = (const float*)d_in[18];
    const float* fx_w1 = (const float*)d_in[19];
    const float* fx_b1 = (const float*)d_in[20];
    const float* fx_w2 = (const float*)d_in[21];
    const float* fx_b2 = (const float*)d_in[22];
    const float* fy_g  = (const float*)d_in[23];
    const float* fy_b  = (const float*)d_in[24];
    const float* fy_w1 = (const float*)d_in[25];
    const float* fy_b1 = (const float*)d_in[26];
    const float* fy_w2 = (const float*)d_in[27];
    const float* fy_b2 = (const float*)d_in[28];

    cudaFuncSetAttribute(gemm_bf<128, true>, cudaFuncAttributeMaxDynamicSharedMemorySize, BSMEM);
    cudaFuncSetAttribute(gemm_bf<96, false>, cudaFuncAttributeMaxDynamicSharedMemorySize, BSMEM);
    cudaFuncSetAttribute(softmax2_k, cudaFuncAttributeMaxDynamicSharedMemorySize, SMXSM);

    float* S = nullptr;
    cudaGetSymbolAddress((void**)&S, g_scratch);
    __nv_bfloat16* BF = nullptr;
    cudaGetSymbolAddress((void**)&BF, g_bf);

    float* gy   = S + OFF_Y;
    float* gx1  = S + OFF_X1;
    float* gy1  = S + OFF_Y1;
    float* gk   = S + OFF_K;
    float* gv1  = S + OFF_V1;
    float* gv2  = S + OFF_V2;
    float* grel = S + OFF_REL;
    float* gatt = S + OFF_ATT;
    float* gx4  = S + OFF_X4;
    float* gy4  = S + OFF_Y4;

    #define PLH(off) (BF + (off))
    #define PLL(off, sz) (BF + (off) + (sz))

    float* outx = (float*)d_out;
    float* outy = outx + (long)PB * PN1 * PD;

    dim3 tt(32, 8);

    // ---- weight transpose+split ----
    tsplit_k<<<dim3(PD/32, PDY0/32, 1), tt>>>(W_res, PLH(BF_WRT), PLL(BF_WRT,SZ_WRT), PDY0, PD, PD, 0,0,0,1);
    tsplit_k<<<dim3(HDK/32, PD/32, 1), tt>>>(Wq,  PLH(BF_WQT),  PLL(BF_WQT,SZ_WQT),  PD, HDK, HDK, 0,0,0,1);
    tsplit_k<<<dim3(HDK/32, PD/32, 1), tt>>>(Wk,  PLH(BF_WKT),  PLL(BF_WKT,SZ_WKT),  PD, HDK, HDK, 0,0,0,1);
    tsplit_k<<<dim3(HDV/32, PD/32, 1), tt>>>(Wv2, PLH(BF_WV2T), PLL(BF_WV2T,SZ_WV2T), PD, HDV, HDV, 0,0,0,1);
    tsplit_k<<<dim3(HDV/32, PD/32, 1), tt>>>(Wv1, PLH(BF_WV1T), PLL(BF_WV1T,SZ_WV1T), PD, HDV, HDV, 0,0,0,1);
    tsplit_k<<<dim3(PD/32, HDV/32, 1), tt>>>(Wo1, PLH(BF_WO1T), PLL(BF_WO1T,SZ_WO1T), HDV, PD, PD, 0,0,0,1);
    tsplit_k<<<dim3(PD/32, HDV/32, 1), tt>>>(Wo2, PLH(BF_WO2T), PLL(BF_WO2T,SZ_WO2T), HDV, PD, PD, 0,0,0,1);
    tsplit_k<<<dim3(HDK/32, PNRP/32, 1), tt>>>(Wrel, PLH(BF_WRELT), PLL(BF_WRELT,SZ_WRELT), PNRP, HDK, HDK, 0,0,0,1);
    tsplit_k<<<dim3(PDFF/32, PD/32, 1), tt>>>(fx_w1, PLH(BF_FX1T), PLL(BF_FX1T,SZ_F1), PD, PDFF, PDFF, 0,0,0,1);
    tsplit_k<<<dim3(PD/32, PDFF/32, 1), tt>>>(fx_w2, PLH(BF_FX2T), PLL(BF_FX2T,SZ_F2), PDFF, PD, PD, 0,0,0,1);
    tsplit_k<<<dim3(PDFF/32, PD/32, 1), tt>>>(fy_w1, PLH(BF_FY1T), PLL(BF_FY1T,SZ_F1), PD, PDFF, PDFF, 0,0,0,1);
    tsplit_k<<<dim3(PD/32, PDFF/32, 1), tt>>>(fy_w2, PLH(BF_FY2T), PLL(BF_FY2T,SZ_F2), PDFF, PD, PD, 0,0,0,1);

    // ---- inputs ----
    ln_k<<<PB * PN1, 256>>>(x, lnx_g, lnx_b, gx1, PLH(BF_X1), PLL(BF_X1,SZ_X1));
    split_k<<<2048, 256>>>(y0, PLH(BF_Y0), PLL(BF_Y0,SZ_Y0), SZ_Y0);

    // y = y0 @ W_res
    gemm_bf<128,true><<<ngrid(PB*PN2, PD, 128, 1), 256, BSMEM>>>(
        PLH(BF_Y0), PLL(BF_Y0,SZ_Y0), PLH(BF_WRT), PLL(BF_WRT,SZ_WRT),
        nullptr, nullptr, gy, nullptr, nullptr,
        PB*PN2, PD, PDY0, PDY0, PDY0, PD, 0,0,0,0,0,0, 1, 1.f, 0);
    ln_k<<<PB * PN2, 256>>>(gy, lny_g, lny_b, gy1, PLH(BF_Y1), PLL(BF_Y1,SZ_Y1));

    // q (pre-scaled, planes only), k, v2, v1
    gemm_bf<128,true><<<ngrid(PB*PN1, HDK, 128, 1), 256, BSMEM>>>(
        PLH(BF_X1), PLL(BF_X1,SZ_X1), PLH(BF_WQT), PLL(BF_WQT,SZ_WQT),
        nullptr, nullptr, nullptr, PLH(BF_Q), PLL(BF_Q,SZ_Q),
        PB*PN1, HDK, PD, PD, PD, HDK, 0,0,0,0,0,0, 1, PSCALE, 0);
    gemm_bf<128,true><<<ngrid(PB*PN2, HDK, 128, 1), 256, BSMEM>>>(
        PLH(BF_Y1), PLL(BF_Y1,SZ_Y1), PLH(BF_WKT), PLL(BF_WKT,SZ_WKT),
        nullptr, nullptr, gk, PLH(BF_K), PLL(BF_K,SZ_K),
        PB*PN2, HDK, PD, PD, PD, HDK, 0,0,0,0,0,0, 1, 1.f, 0);
    gemm_bf<128,true><<<ngrid(PB*PN2, HDV, 128, 1), 256, BSMEM>>>(
        PLH(BF_Y1), PLL(BF_Y1,SZ_Y1), PLH(BF_WV2T), PLL(BF_WV2T,SZ_WV2T),
        nullptr, nullptr, gv2, nullptr, nullptr,
        PB*PN2, HDV, PD, PD, PD, HDV, 0,0,0,0,0,0, 1, 1.f, 0);
    gemm_bf<128,true><<<ngrid(PB*PN1, HDV, 128, 1), 256, BSMEM>>>(
        PLH(BF_X1), PLL(BF_X1,SZ_X1), PLH(BF_WV1T), PLL(BF_WV1T,SZ_WV1T),
        nullptr, nullptr, gv1, nullptr, nullptr,
        PB*PN1, HDV, PD, PD, PD, HDV, 0,0,0,0,0,0, 1, 1.f, 0);

    // v2T single-plane (hi only; out1 is 2-pass on B via planes of v2T? -> need both planes)
    // NOTE: out1/out2 keep v planes (hi+lo); attn is the single-plane operand.
    tsplit_k<<<dim3(PDV/32, PN2/32, PB*PH), tt>>>(
        gv2, PLH(BF_V2T), PLL(BF_V2T,SZ_V2T), PN2, PDV, HDV,
        (long)PN2*HDV, (long)PDV, (long)PDV*PN2, PH);
    tsplit_k<<<dim3(PDV/32, PN1/32, PB*PH), tt>>>(
        gv1, PLH(BF_V1T), PLL(BF_V1T,SZ_V1T), PN1, PDV, HDV,
        (long)PN1*HDV, (long)PDV, (long)PDV*PN1, PH);

    // pos features + rel_q (planes only)
    pos_k<<<(PMQ + 127) / 128, 128>>>(PLH(BF_POS), PLL(BF_POS,SZ_POS));
    gemm_bf<128,true><<<ngrid(PMQ, HDK, 128, 1), 256, BSMEM>>>(
        PLH(BF_POS), PLL(BF_POS,SZ_POS), PLH(BF_WRELT), PLL(BF_WRELT,SZ_WRELT),
        nullptr, nullptr, nullptr, PLH(BF_RQ), PLL(BF_RQ,SZ_RQ),
        PMQ, HDK, PNRP, PNRP, PNRP, HDK, 0,0,0,0,0,0, 1, 1.f, 0);

    // kb planes
    kb_k<<<2048, 256>>>(gk, rpb, PLH(BF_KB), PLL(BF_KB,SZ_KB), PB*PN2*HDK);

    // content = q_scaled @ k^T
    gemm_bf<128,true><<<ngrid(PN1, PN2, 128, PB*PH), 256, BSMEM>>>(
        PLH(BF_Q), PLL(BF_Q,SZ_Q), PLH(BF_K), PLL(BF_K,SZ_K),
        nullptr, nullptr, gatt, nullptr, nullptr,
        PN1, PN2, PDK, HDK, HDK, PN2,
        (long)PN1*HDK, (long)PDK, (long)PN2*HDK, (long)PDK,
        (long)PH*PN1*PN2, (long)PN1*PN2, PH, 1.f, 0);

    // rel = kb @ rel_q^T
    gemm_bf<128,true><<<ngrid(PN2, PMQ, 128, PB*PH), 256, BSMEM>>>(
        PLH(BF_KB), PLL(BF_KB,SZ_KB), PLH(BF_RQ), PLL(BF_RQ,SZ_RQ),
        nullptr, nullptr, grel, nullptr, nullptr,
        PN2, PMQ, PDK, HDK, HDK, PMQ,
        (long)PN2*HDK, (long)PDK, 0L, (long)PDK,
        (long)PH*PN2*PMQ, (long)PN2*PMQ, PH, 1.f, 0);

    // tiled softmax -> single bf16 plane
    softmax2_k<<<dim3(PN1/32, PB*PH), 256, SMXSM>>>(gatt, grel, PLH(BF_ATT));

    // attT (single plane)
    bt_k<<<dim3(PN2/32, PN1/32, PB*PH), tt>>>(PLH(BF_ATT), PLH(BF_ATTT), PN1, PN2);

    // out1 = attn @ v2  (BN=96 tile, 2-pass; planes out)
    gemm_bf<96,false><<<ngrid(PN1, PDV, 96, PB*PH), 256, BSMEM>>>(
        PLH(BF_ATT), nullptr, PLH(BF_V2T), PLL(BF_V2T,SZ_V2T),
        nullptr, nullptr, nullptr, PLH(BF_GO1), PLL(BF_GO1,SZ_GO1),
        PN1, PDV, PN2, PN2, PN2, HDV,
        (long)PH*PN1*PN2, (long)PN1*PN2, (long)PH*PDV*PN2, (long)PDV*PN2,
        (long)PN1*HDV, (long)PDV, PH, 1.f, 0);

    // out2 = attn^T @ v1 (BN=96, 2-pass; planes out)
    gemm_bf<96,false><<<ngrid(PN2, PDV, 96, PB*PH), 256, BSMEM>>>(
        PLH(BF_ATTT), nullptr, PLH(BF_V1T), PLL(BF_V1T,SZ_V1T),
        nullptr, nullptr, nullptr, PLH(BF_GO2), PLL(BF_GO2,SZ_GO2),
        PN2, PDV, PN1, PN1, PN1, HDV,
        (long)PH*PN2*PN1, (long)PN2*PN1, (long)PH*PDV*PN1, (long)PDV*PN1,
        (long)PN2*HDV, (long)PDV, PH, 1.f, 0);

    // x4 = x + out1 @ Wo1 + bo1 ; y4 = y + out2 @ Wo2 + bo2
    gemm_bf<128,true><<<ngrid(PB*PN1, PD, 128, 1), 256, BSMEM>>>(
        PLH(BF_GO1), PLL(BF_GO1,SZ_GO1), PLH(BF_WO1T), PLL(BF_WO1T,SZ_WO1T),
        bo1, x, gx4, nullptr, nullptr,
        PB*PN1, PD, HDV, HDV, HDV, PD, 0,0,0,0,0,0, 1, 1.f, 0);
    gemm_bf<128,true><<<ngrid(PB*PN2, PD, 128, 1), 256, BSMEM>>>(
        PLH(BF_GO2), PLL(BF_GO2,SZ_GO2), PLH(BF_WO2T), PLL(BF_WO2T,SZ_WO2T),
        bo2, gy, gy4, nullptr, nullptr,
        PB*PN2, PD, HDV, HDV, HDV, PD, 0,0,0,0,0,0, 1, 1.f, 0);

    // FFN x
    ln_k<<<PB * PN1, 256>>>(gx4, fx_g, fx_b, gx1, PLH(BF_X1), PLL(BF_X1,SZ_X1));
    gemm_bf<128,true><<<ngrid(PB*PN1, PDFF, 128, 1), 256, BSMEM>>>(
        PLH(BF_X1), PLL(BF_X1,SZ_X1), PLH(BF_FX1T), PLL(BF_FX1T,SZ_F1),
        fx_b1, nullptr, nullptr, PLH(BF_GH), PLL(BF_GH,SZ_GH),
        PB*PN1, PDFF, PD, PD, PD, PDFF, 0,0,0,0,0,0, 1, 1.f, 1);
    gemm_bf<128,true><<<ngrid(PB*PN1, PD, 128, 1), 256, BSMEM>>>(
        PLH(BF_GH), PLL(BF_GH,SZ_GH), PLH(BF_FX2T), PLL(BF_FX2T,SZ_F2),
        fx_b2, gx4, outx, nullptr, nullptr,
        PB*PN1, PD, PDFF, PDFF, PDFF, PD, 0,0,0,0,0,0, 1, 1.f, 0);

    // FFN y
    ln_k<<<PB * PN2, 256>>>(gy4, fy_g, fy_b, gy1, PLH(BF_Y1), PLL(BF_Y1,SZ_Y1));
    gemm_bf<128,true><<<ngrid(PB*PN2, PDFF, 128, 1), 256, BSMEM>>>(
        PLH(BF_Y1), PLL(BF_Y1,SZ_Y1), PLH(BF_FY1T), PLL(BF_FY1T,SZ_F1),
        fy_b1, nullptr, nullptr, PLH(BF_GH), PLL(BF_GH,SZ_GH),
        PB*PN2, PDFF, PD, PD, PD, PDFF, 0,0,0,0,0,0, 1, 1.f, 1);
    gemm_bf<128,true><<<ngrid(PB*PN2, PD, 128, 1), 256, BSMEM>>>(
        PLH(BF_GH), PLL(BF_GH,SZ_GH), PLH(BF_FY2T), PLL(BF_FY2T,SZ_F2),
        fy_b2, gy4, outy, nullptr, nullptr,
        PB*PN2, PD, PDFF, PDFF, PDFF, PD, 0,0,0,0,0,0, 1, 1.f, 0);

    (void)in_sizes; (void)n_in; (void)out_size;
}

// round 14
// speedup vs baseline: 2.5945x; 1.1781x over previous
#include <cuda_runtime.h>
#include <cuda_bf16.h>
#include <cstdint>
#include <math.h>

// ---------------- problem constants ----------------
#define PB   4
#define PN1  2048
#define PN2  512
#define PD   768
#define PH   8
#define PDK  64
#define PDV  96
#define PNRP 96
#define PDY0 1536
#define PDFF 1536
#define PMQ  2560              // needed pos rows: m = i - j + 511 in [0, 2558]
#define PSCALE 0.125f          // DK^-0.5
#define HDK  512
#define HDV  768

// ---------------- fp32 scratch ----------------
#define OFF_Y      0L
#define OFF_Y1     (OFF_Y    + (long)PB*PN2*PD)
#define OFF_K      (OFF_Y1   + (long)PB*PN2*PD)
#define OFF_V1     (OFF_K    + (long)PB*PN2*HDK)
#define OFF_V2     (OFF_V1   + (long)PB*PN1*HDV)
#define OFF_REL    (OFF_V2   + (long)PB*PN2*HDV)
#define OFF_ATT    (OFF_REL  + (long)PB*PH*PN2*PMQ)
#define OFF_X4     (OFF_ATT  + (long)PB*PH*PN1*PN2)
#define OFF_Y4     (OFF_X4   + (long)PB*PN1*PD)
#define OFF_X1     (OFF_Y4   + (long)PB*PN2*PD)
#define SCRATCH_TOTAL (OFF_X1 + (long)PB*PN1*PD)
__device__ float g_scratch[SCRATCH_TOTAL];

// ---------------- bf16 plane scratch ----------------
#define SZ_X1   ((long)PB*PN1*PD)
#define SZ_Y1   ((long)PB*PN2*PD)
#define SZ_Y0   ((long)PB*PN2*PDY0)
#define SZ_Q    ((long)PB*PN1*HDK)
#define SZ_K    ((long)PB*PN2*HDK)
#define SZ_KB   ((long)PB*PN2*HDK)
#define SZ_RQ   ((long)PMQ*HDK)
#define SZ_ATT  ((long)PB*PH*PN1*PN2)
#define SZ_ATTT ((long)PB*PH*PN1*PN2)
#define SZ_V2T  ((long)PB*PH*PDV*PN2)
#define SZ_V1T  ((long)PB*PH*PDV*PN1)
#define SZ_GO1  ((long)PB*PN1*HDV)
#define SZ_GO2  ((long)PB*PN2*HDV)
#define SZ_GH   ((long)PB*PN1*PDFF)
#define SZ_POS  ((long)PMQ*PNRP)
#define SZ_WRT  ((long)PDY0*PD)
#define SZ_WRELT ((long)HDK*PNRP)
#define SZ_WQT  ((long)PD*HDK)
#define SZ_WKT  ((long)PD*HDK)
#define SZ_WV2T ((long)PD*HDV)
#define SZ_WV1T ((long)PD*HDV)
#define SZ_WO1T ((long)HDV*PD)
#define SZ_WO2T ((long)HDV*PD)
#define SZ_F1   ((long)PD*PDFF)
#define SZ_F2   ((long)PDFF*PD)

#define BF_X1   0L
#define BF_Y1   (BF_X1   + 2*SZ_X1)
#define BF_Y0   (BF_Y1   + 2*SZ_Y1)
#define BF_Q    (BF_Y0   + 2*SZ_Y0)
#define BF_K    (BF_Q    + 2*SZ_Q)
#define BF_KB   (BF_K    + 2*SZ_K)             // single plane
#define BF_RQ   (BF_KB   + SZ_KB)
#define BF_ATT  (BF_RQ   + 2*SZ_RQ)            // single plane
#define BF_ATTT (BF_ATT  + SZ_ATT)             // single plane
#define BF_V2T  (BF_ATTT + SZ_ATTT)
#define BF_V1T  (BF_V2T  + 2*SZ_V2T)
#define BF_GO1  (BF_V1T  + 2*SZ_V1T)           // single plane
#define BF_GO2  (BF_GO1  + SZ_GO1)             // single plane
#define BF_GH   (BF_GO2  + SZ_GO2)             // single plane
#define BF_POS  (BF_GH   + SZ_GH)
#define BF_WRT  (BF_POS  + 2*SZ_POS)
#define BF_WRELT (BF_WRT + 2*SZ_WRT)
#define BF_WQT  (BF_WRELT+ 2*SZ_WRELT)
#define BF_WKT  (BF_WQT  + 2*SZ_WQT)
#define BF_WV2T (BF_WKT  + 2*SZ_WKT)
#define BF_WV1T (BF_WV2T + 2*SZ_WV2T)
#define BF_WO1T (BF_WV1T + 2*SZ_WV1T)
#define BF_WO2T (BF_WO1T + 2*SZ_WO1T)
#define BF_FX1T (BF_WO2T + 2*SZ_WO2T)
#define BF_FX2T (BF_FX1T + 2*SZ_F1)
#define BF_FY1T (BF_FX2T + 2*SZ_F2)
#define BF_FY2T (BF_FY1T + 2*SZ_F1)
#define BF_TOTAL (BF_FY2T+ 2*SZ_F2)
__device__ __align__(256) __nv_bfloat16 g_bf[BF_TOTAL];

// =================== helpers ===================
__device__ __forceinline__ uint32_t sptr(const void* p) {
    return (uint32_t)__cvta_generic_to_shared(p);
}
__device__ __forceinline__ void ldsm4(uint32_t r[4], const __nv_bfloat16* p) {
    uint32_t a = sptr(p);
    asm volatile("ldmatrix.sync.aligned.m8n8.x4.shared.b16 {%0,%1,%2,%3}, [%4];"
                 : "=r"(r[0]), "=r"(r[1]), "=r"(r[2]), "=r"(r[3]) : "r"(a));
}
__device__ __forceinline__ void mma16816(float c[4], const uint32_t a[4], uint32_t b0, uint32_t b1) {
    asm volatile(
        "mma.sync.aligned.m16n8k16.row.col.f32.bf16.bf16.f32 "
        "{%0,%1,%2,%3}, {%4,%5,%6,%7}, {%8,%9}, {%0,%1,%2,%3};"
        : "+f"(c[0]), "+f"(c[1]), "+f"(c[2]), "+f"(c[3])
        : "r"(a[0]), "r"(a[1]), "r"(a[2]), "r"(a[3]), "r"(b0), "r"(b1));
}
__device__ __forceinline__ void bsplit(float x, __nv_bfloat16& h, __nv_bfloat16& l) {
    h = __float2bfloat16(x);
    l = __float2bfloat16(x - __bfloat162float(h));
}
__device__ __forceinline__ void cpa16(uint32_t saddr, const void* g, bool pred) {
    int sz = pred ? 16 : 0;
    asm volatile("cp.async.cg.shared.global [%0], [%1], 16, %2;"
                 :: "r"(saddr), "l"(g), "r"(sz) : "memory");
}
__device__ __forceinline__ void cpa_commit() {
    asm volatile("cp.async.commit_group;" ::: "memory");
}
template<int NW> __device__ __forceinline__ void cpa_wait() {
    asm volatile("cp.async.wait_group %0;" :: "n"(NW) : "memory");
}
__device__ __forceinline__ float warpSum(float v) {
    #pragma unroll
    for (int o = 16; o; o >>= 1) v += __shfl_xor_sync(0xffffffffu, v, o);
    return v;
}
__device__ __forceinline__ float warpMax(float v) {
    #pragma unroll
    for (int o = 16; o; o >>= 1) v = fmaxf(v, __shfl_xor_sync(0xffffffffu, v, o));
    return v;
}

// =================== pre-split bf16 GEMM with cp.async ===================
// C = alpha*(A @ B^T) (+bias)(+Res)(relu).  A=[M,K] planes (lo optional via UAL),
// B=[N,K] planes, all k-contig. C fp32 optional; Chi plane optional (Clo optional).
// CTA tile 128 x BN (128 or 96), BK=32, 8 warps 4m x 2n, warp 32 x BN/2.
// 2-stage cp.async ring. M%128==0, K%32==0; N guarded vs BN grid.
#define SA   40
#define BTSZ (128 * SA)
#define BSTG (4 * BTSZ)
#define BSMEM (2 * BSTG * 2)     // 81920 bytes

template <int BN, bool UAL>
__global__ __launch_bounds__(256, 2) void gemm_bf(
    const __nv_bfloat16* __restrict__ Ah, const __nv_bfloat16* __restrict__ Al,
    const __nv_bfloat16* __restrict__ Bh, const __nv_bfloat16* __restrict__ Bl,
    const float* __restrict__ bias, const float* __restrict__ Res,
    float* __restrict__ C, __nv_bfloat16* __restrict__ Chi, __nv_bfloat16* __restrict__ Clo,
    int M, int N, int K, int lda, int ldb, int ldc,
    long sAb, long sAh_, long sBb, long sBh_, long sCb, long sCh_, int Hn,
    float alpha, int doRelu)
{
    constexpr int NG = BN / 32;
    int z = blockIdx.z;
    int bb = z / Hn, hh = z % Hn;
    long ao = bb * sAb + hh * sAh_;
    long bo = bb * sBb + hh * sBh_;
    long co = bb * sCb + hh * sCh_;
    Ah += ao; if (UAL) Al += ao;
    Bh += bo; Bl += bo;
    if (C) C += co;
    if (Res) Res += co;
    if (Chi) Chi += co;
    if (Clo) Clo += co;

    extern __shared__ __nv_bfloat16 sm[];
    uint32_t sbase = sptr(sm);

    int m0 = blockIdx.y * 128;
    int n0 = blockIdx.x * BN;
    int tid = threadIdx.x, w = tid >> 5, lane = tid & 31;
    int wm = (w & 3) * 32;
    int wn = (w >> 2) * (BN / 2);

    float acc[2][2 * NG][4];
    #pragma unroll
    for (int f = 0; f < 2; f++)
        #pragma unroll
        for (int g = 0; g < 2 * NG; g++)
            #pragma unroll
            for (int e = 0; e < 4; e++) acc[f][g][e] = 0.f;

    int nk = K >> 5;

    auto issue = [&](int s, int buf) {
        int k0 = s << 5;
        uint32_t st = sbase + (uint32_t)buf * (BSTG * 2);
        constexpr int AIT = UAL ? 4 : 2;
        #pragma unroll
        for (int i = 0; i < AIT; i++) {
            int idx = tid + i * 256;
            int pl = idx >> 9, rem = idx & 511, row = rem >> 2, seg = rem & 3;
            const __nv_bfloat16* g = (pl ? Al : Ah) + (long)(m0 + row) * lda + k0 + seg * 8;
            cpa16(st + (uint32_t)(pl * BTSZ + row * SA + seg * 8) * 2, g, true);
        }
        constexpr int BIT = (BN * 8) / 256;
        #pragma unroll
        for (int i = 0; i < BIT; i++) {
            int idx = tid + i * 256;
            int pl = idx / (BN * 4), rem = idx % (BN * 4), row = rem >> 2, seg = rem & 3;
            int rg = n0 + row;
            int rc = (rg < N) ? rg : 0;
            const __nv_bfloat16* g = (pl ? Bl : Bh) + (long)rc * ldb + k0 + seg * 8;
            cpa16(st + (uint32_t)((2 + pl) * BTSZ + row * SA + seg * 8) * 2, g, rg < N);
        }
        cpa_commit();
    };

    issue(0, 0);
    issue(1, 1);

    for (int s = 0; s < nk; s++) {
        if (s + 2 <= nk) cpa_wait<1>(); else cpa_wait<0>();
        __syncthreads();

        const __nv_bfloat16* base = sm + (s & 1) * BSTG;
        const __nv_bfloat16* pAh = base;
        const __nv_bfloat16* pAl = base + BTSZ;
        const __nv_bfloat16* pBh = base + 2 * BTSZ;
        const __nv_bfloat16* pBl = base + 3 * BTSZ;

        #pragma unroll
        for (int kk = 0; kk < 32; kk += 16) {
            uint32_t ah[2][4], al[2][4];
            #pragma unroll
            for (int f = 0; f < 2; f++) {
                int r = wm + f * 16 + (lane & 15);
                int c = kk + ((lane >> 4) << 3);
                ldsm4(ah[f], pAh + r * SA + c);
                if (UAL) ldsm4(al[f], pAl + r * SA + c);
            }
            #pragma unroll
            for (int gp = 0; gp < NG; gp++) {
                int r = wn + gp * 16 + (lane & 7) + ((lane >> 4) << 3);
                int c = kk + (((lane >> 3) & 1) << 3);
                uint32_t th[4], tl[4];
                ldsm4(th, pBh + r * SA + c);
                ldsm4(tl, pBl + r * SA + c);
                #pragma unroll
                for (int f = 0; f < 2; f++) {
                    mma16816(acc[f][2*gp],   ah[f], th[0], th[1]);
                    if (UAL) mma16816(acc[f][2*gp], al[f], th[0], th[1]);
                    mma16816(acc[f][2*gp],   ah[f], tl[0], tl[1]);
                    mma16816(acc[f][2*gp+1], ah[f], th[2], th[3]);
                    if (UAL) mma16816(acc[f][2*gp+1], al[f], th[2], th[3]);
                    mma16816(acc[f][2*gp+1], ah[f], tl[2], tl[3]);
                }
            }
        }
        __syncthreads();
        if (s + 2 < nk) issue(s + 2, s & 1);
    }

    // ---- epilogue ----
    int gid = lane >> 2, tg = lane & 3;
    #pragma unroll
    for (int f = 0; f < 2; f++) {
        #pragma unroll
        for (int g = 0; g < 2 * NG; g++) {
            int r0 = m0 + wm + f * 16 + gid;
            int c0 = n0 + wn + g * 8 + tg * 2;
            #pragma unroll
            for (int e = 0; e < 4; e++) {
                int r = r0 + ((e >> 1) << 3);
                int c = c0 + (e & 1);
                if (c >= N) continue;
                float v = acc[f][g][e] * alpha;
                if (bias) v += bias[c];
                if (Res)  v += Res[(long)r * ldc + c];
                if (doRelu) v = fmaxf(v, 0.f);
                if (C) C[(long)r * ldc + c] = v;
                if (Chi) {
                    if (Clo) {
                        __nv_bfloat16 h, l;
                        bsplit(v, h, l);
                        Chi[(long)r * ldc + c] = h;
                        Clo[(long)r * ldc + c] = l;
                    } else {
                        Chi[(long)r * ldc + c] = __float2bfloat16(v);
                    }
                }
            }
        }
    }
}

// ---------------- LayerNorm (fp32 + bf16 hi/lo planes) ----------------
__global__ __launch_bounds__(256) void ln_k(const float* __restrict__ X,
                                            const float* __restrict__ g,
                                            const float* __restrict__ bta,
                                            float* __restrict__ Y,
                                            __nv_bfloat16* __restrict__ Yh,
                                            __nv_bfloat16* __restrict__ Yl)
{
    long row = blockIdx.x;
    const float* xr = X + row * PD;
    int t = threadIdx.x, lane = t & 31, wid = t >> 5;

    float s1 = 0.f, s2 = 0.f;
    for (int c = t; c < PD; c += 256) { float v = xr[c]; s1 += v; s2 += v * v; }
    s1 = warpSum(s1); s2 = warpSum(s2);
    __shared__ float sA[8], sB[8];
    if (lane == 0) { sA[wid] = s1; sB[wid] = s2; }
    __syncthreads();
    float t1 = 0.f, t2 = 0.f;
    #pragma unroll
    for (int wI = 0; wI < 8; wI++) { t1 += sA[wI]; t2 += sB[wI]; }
    float mean = t1 / (float)PD;
    float var  = t2 / (float)PD - mean * mean;
    float rs = rsqrtf(var + 1e-5f);
    for (int c = t; c < PD; c += 256) {
        float v = (xr[c] - mean) * rs * g[c] + bta[c];
        if (Y) Y[row * PD + c] = v;
        __nv_bfloat16 h, l;
        bsplit(v, h, l);
        Yh[row * PD + c] = h;
        Yl[row * PD + c] = l;
    }
}

// ---------------- elementwise split ----------------
__global__ void split_k(const float* __restrict__ in,
                        __nv_bfloat16* __restrict__ oh,
                        __nv_bfloat16* __restrict__ ol, long n)
{
    for (long i = blockIdx.x * (long)blockDim.x + threadIdx.x; i < n;
         i += (long)gridDim.x * blockDim.x) {
        __nv_bfloat16 h, l;
        bsplit(in[i], h, l);
        oh[i] = h; ol[i] = l;
    }
}

// ---------------- tiled transpose + split (fp32 -> bf16 planes) ----------------
__global__ void tsplit_k(const float* __restrict__ in,
                         __nv_bfloat16* __restrict__ oh,
                         __nv_bfloat16* __restrict__ ol,
                         int K, int N, int ldin,
                         long sinB, long sinH, long sout, int Hn)
{
    __shared__ float t[32][33];
    int z = blockIdx.z;
    int b = z / Hn, h = z % Hn;
    in += b * sinB + h * sinH;
    oh += (long)z * sout;
    if (ol) ol += (long)z * sout;
    int kb = blockIdx.y * 32, nb = blockIdx.x * 32;
    int tx = threadIdx.x, ty = threadIdx.y;
    #pragma unroll
    for (int j = 0; j < 32; j += 8) {
        int k = kb + ty + j, n = nb + tx;
        t[ty + j][tx] = (k < K && n < N) ? in[(long)k * ldin + n] : 0.f;
    }
    __syncthreads();
    #pragma unroll
    for (int j = 0; j < 32; j += 8) {
        int n = nb + ty + j, k = kb + tx;
        if (n < N && k < K) {
            __nv_bfloat16 hh, ll;
            bsplit(t[tx][ty + j], hh, ll);
            oh[(long)n * K + k] = hh;
            if (ol) ol[(long)n * K + k] = ll;
        }
    }
}

// ---------------- batched weight transpose+split (all 12 weights, 1 launch) ----------------
struct WSegs {
    const float* src[12];
    __nv_bfloat16* oh[12];
    __nv_bfloat16* ol[12];
    int K[12];
    int N[12];
};
__global__ void wsplit_all(WSegs W)
{
    int seg = blockIdx.z;
    int K = W.K[seg], N = W.N[seg];
    int kb = blockIdx.y * 32, nb = blockIdx.x * 32;
    if (kb >= K || nb >= N) return;
    const float* in = W.src[seg];
    __nv_bfloat16* oh = W.oh[seg];
    __nv_bfloat16* ol = W.ol[seg];
    __shared__ float t[32][33];
    int tx = threadIdx.x, ty = threadIdx.y;
    #pragma unroll
    for (int j = 0; j < 32; j += 8) {
        int k = kb + ty + j, n = nb + tx;
        t[ty + j][tx] = (k < K && n < N) ? in[(long)k * N + n] : 0.f;
    }
    __syncthreads();
    #pragma unroll
    for (int j = 0; j < 32; j += 8) {
        int n = nb + ty + j, k = kb + tx;
        if (n < N && k < K) {
            __nv_bfloat16 hh, ll;
            bsplit(t[tx][ty + j], hh, ll);
            oh[(long)n * K + k] = hh;
            ol[(long)n * K + k] = ll;
        }
    }
}

// ---------------- batched single-plane bf16 transpose ----------------
__global__ void bt_k(const __nv_bfloat16* __restrict__ ih,
                     __nv_bfloat16* __restrict__ oh,
                     int R, int Ccols)
{
    __shared__ unsigned short tb[32][33];
    long z = blockIdx.z;
    long off = z * (long)R * Ccols;
    ih += off; oh += off;
    int rb = blockIdx.y * 32, cb = blockIdx.x * 32;
    int tx = threadIdx.x, ty = threadIdx.y;
    #pragma unroll
    for (int j = 0; j < 32; j += 8) {
        int r = rb + ty + j, c = cb + tx;
        tb[ty + j][tx] = __bfloat16_as_ushort(ih[(long)r * Ccols + c]);
    }
    __syncthreads();
    #pragma unroll
    for (int j = 0; j < 32; j += 8) {
        int c = cb + ty + j, r = rb + tx;
        oh[(long)c * R + r] = __ushort_as_bfloat16(tb[tx][ty + j]);
    }
}

// ---------------- Enformer positional features -> bf16 planes ----------------
__global__ void pos_k(__nv_bfloat16* __restrict__ ph, __nv_bfloat16* __restrict__ pl)
{
    int m = blockIdx.x * blockDim.x + threadIdx.x;
    if (m >= PMQ) return;
    float d = (float)(m - (PN1 - 1));
    float ad = fabsf(d);

    float fe[16], fc[16], fg[16];
    float pmax = 0.f;
    const float ln2 = 0.6931471805599453f;
    #pragma unroll
    for (int i = 0; i < 16; i++) {
        float e = 3.0f + 8.0f * (float)i / 15.0f;
        float hl = exp2f(e);
        fe[i] = expf(-ln2 / hl * ad);
        float cw = exp2f((float)(i + 1)) - 1.0f;
        fc[i] = (cw > ad) ? 1.0f : 0.0f;
        float mean = 128.0f * (float)(i + 1);
        float conc = (mean / 64.0f) * (mean / 64.0f);
        float rate = mean / 4096.0f;
        float logp = (conc - 1.0f) * logf(ad) - rate * ad
                   - (lgammaf(conc) - conc * logf(rate));
        float prob = expf(logp) + 1e-8f;
        fg[i] = prob;
        pmax = fmaxf(pmax, prob);
    }
    float sgn = (d > 0.f) ? 1.f : ((d < 0.f) ? -1.f : 0.f);
    float inv = 1.0f / pmax;
    long base = (long)m * PNRP;
    #pragma unroll
    for (int i = 0; i < 16; i++) {
        float gv = fg[i] * inv;
        float vals[6] = { fe[i], fc[i], gv, sgn * fe[i], sgn * fc[i], sgn * gv };
        int offs[6] = { i, 16 + i, 32 + i, 48 + i, 64 + i, 80 + i };
        #pragma unroll
        for (int q = 0; q < 6; q++) {
            __nv_bfloat16 h, l;
            bsplit(vals[q], h, l);
            ph[base + offs[q]] = h;
            pl[base + offs[q]] = l;
        }
    }
}

// ---------------- kb = k*SCALE + rpb -> single bf16 plane ----------------
__global__ void kb_k(const float* __restrict__ k, const float* __restrict__ rpb,
                     __nv_bfloat16* __restrict__ kbh, int total)
{
    for (int i = blockIdx.x * blockDim.x + threadIdx.x; i < total;
         i += gridDim.x * blockDim.x)
        kbh[i] = __float2bfloat16(k[i] * PSCALE + rpb[i & 511]);
}

// ---------------- tiled softmax: coalesced diagonal-band gather ----------------
#define SMXSM (512 * 33 * 4)
__global__ __launch_bounds__(256) void softmax2_k(
    const float* __restrict__ att, const float* __restrict__ rel,
    __nv_bfloat16* __restrict__ ah)
{
    extern __shared__ float srel[];
    int i0 = blockIdx.x * 32;
    long z = blockIdx.y;
    const float* relz = rel + z * (long)PN2 * PMQ;
    int t = threadIdx.x;

    for (int idx = t; idx < PN2 * 32; idx += 256) {
        int j = idx >> 5, di = idx & 31;
        srel[j * 33 + di] = relz[(long)j * PMQ + (i0 + (PN2 - 1) - j) + di];
    }
    __syncthreads();

    int w = t >> 5, lane = t & 31;
    #pragma unroll
    for (int rr = 0; rr < 4; rr++) {
        int di = w + rr * 8;
        int i = i0 + di;
        long rowoff = (z * PN1 + i) * (long)PN2;
        const float* arow = att + rowoff;
        float v[16];
        float mx = -1e30f;
        #pragma unroll
        for (int u = 0; u < 16; u++) {
            int j = lane + u * 32;
            float val = arow[j] + srel[j * 33 + di];
            v[u] = val;
            mx = fmaxf(mx, val);
        }
        mx = warpMax(mx);
        float s = 0.f;
        #pragma unroll
        for (int u = 0; u < 16; u++) { v[u] = expf(v[u] - mx); s += v[u]; }
        s = warpSum(s);
        float inv = 1.0f / s;
        #pragma unroll
        for (int u = 0; u < 16; u++) {
            int j = lane + u * 32;
            ah[rowoff + j] = __float2bfloat16(v[u] * inv);
        }
    }
}

// ---------------- host orchestration ----------------
static inline dim3 ngrid(int M, int N, int BN, int Z) {
    return dim3((unsigned)((N + BN - 1) / BN), (unsigned)(M / 128), (unsigned)Z);
}

extern "C" void kernel_launch(void* const* d_in, const int* in_sizes, int n_in,
                              void* d_out, int out_size)
{
    const float* x     = (const float*)d_in[0];
    const float* y0    = (const float*)d_in[1];
    const float* W_res = (const float*)d_in[2];
    const float* lnx_g = (const float*)d_in[3];
    const float* lnx_b = (const float*)d_in[4];
    const float* lny_g = (const float*)d_in[5];
    const float* lny_b = (const float*)d_in[6];
    const float* Wq    = (const float*)d_in[7];
    const float* Wk    = (const float*)d_in[8];
    const float* Wv1   = (const float*)d_in[9];
    const float* Wv2   = (const float*)d_in[10];
    const float* Wo1   = (const float*)d_in[11];
    const float* bo1   = (const float*)d_in[12];
    const float* Wo2   = (const float*)d_in[13];
    const float* bo2   = (const float*)d_in[14];
    const float* Wrel  = (const float*)d_in[15];
    const float* rpb   = (const float*)d_in[16];
    const float* fx_g  = (const float*)d_in[17];
    const float* fx_b  = (const float*)d_in[18];
    const float* fx_w1 = (const float*)d_in[19];
    const float* fx_b1 = (const float*)d_in[20];
    const float* fx_w2 = (const float*)d_in[21];
    const float* fx_b2 = (const float*)d_in[22];
    const float* fy_g  = (const float*)d_in[23];
    const float* fy_b  = (const float*)d_in[24];
    const float* fy_w1 = (const float*)d_in[25];
    const float* fy_b1 = (const float*)d_in[26];
    const float* fy_w2 = (const float*)d_in[27];
    const float* fy_b2 = (const float*)d_in[28];

    cudaFuncSetAttribute(gemm_bf<128, true>,  cudaFuncAttributeMaxDynamicSharedMemorySize, BSMEM);
    cudaFuncSetAttribute(gemm_bf<128, false>, cudaFuncAttributeMaxDynamicSharedMemorySize, BSMEM);
    cudaFuncSetAttribute(gemm_bf<96, false>,  cudaFuncAttributeMaxDynamicSharedMemorySize, BSMEM);
    cudaFuncSetAttribute(softmax2_k, cudaFuncAttributeMaxDynamicSharedMemorySize, SMXSM);

    float* S = nullptr;
    cudaGetSymbolAddress((void**)&S, g_scratch);
    __nv_bfloat16* BF = nullptr;
    cudaGetSymbolAddress((void**)&BF, g_bf);

    float* gy   = S + OFF_Y;
    float* gx1  = S + OFF_X1;
    float* gy1  = S + OFF_Y1;
    float* gk   = S + OFF_K;
    float* gv1  = S + OFF_V1;
    float* gv2  = S + OFF_V2;
    float* grel = S + OFF_REL;
    float* gatt = S + OFF_ATT;
    float* gx4  = S + OFF_X4;
    float* gy4  = S + OFF_Y4;

    #define PLH(off) (BF + (off))
    #define PLL(off, sz) (BF + (off) + (sz))

    float* outx = (float*)d_out;
    float* outy = outx + (long)PB * PN1 * PD;

    dim3 tt(32, 8);

    // ---- ALL weight transpose+splits in ONE launch ----
    {
        WSegs Wg;
        const float* srcs[12] = { W_res, Wq, Wk, Wv2, Wv1, Wo1, Wo2, Wrel,
                                  fx_w1, fx_w2, fy_w1, fy_w2 };
        long ohs[12] = { BF_WRT, BF_WQT, BF_WKT, BF_WV2T, BF_WV1T, BF_WO1T, BF_WO2T, BF_WRELT,
                         BF_FX1T, BF_FX2T, BF_FY1T, BF_FY2T };
        long szs[12] = { SZ_WRT, SZ_WQT, SZ_WKT, SZ_WV2T, SZ_WV1T, SZ_WO1T, SZ_WO2T, SZ_WRELT,
                         SZ_F1, SZ_F2, SZ_F1, SZ_F2 };
        int Ks[12] = { PDY0, PD, PD, PD, PD, HDV, HDV, PNRP, PD, PDFF, PD, PDFF };
        int Ns[12] = { PD, HDK, HDK, HDV, HDV, PD, PD, HDK, PDFF, PD, PDFF, PD };
        for (int i = 0; i < 12; i++) {
            Wg.src[i] = srcs[i];
            Wg.oh[i] = BF + ohs[i];
            Wg.ol[i] = BF + ohs[i] + szs[i];
            Wg.K[i] = Ks[i];
            Wg.N[i] = Ns[i];
        }
        wsplit_all<<<dim3(48, 48, 12), tt>>>(Wg);
    }

    // ---- inputs ----
    ln_k<<<PB * PN1, 256>>>(x, lnx_g, lnx_b, gx1, PLH(BF_X1), PLL(BF_X1,SZ_X1));
    split_k<<<2048, 256>>>(y0, PLH(BF_Y0), PLL(BF_Y0,SZ_Y0), SZ_Y0);

    // y = y0 @ W_res  (3-pass)
    gemm_bf<128,true><<<ngrid(PB*PN2, PD, 128, 1), 256, BSMEM>>>(
        PLH(BF_Y0), PLL(BF_Y0,SZ_Y0), PLH(BF_WRT), PLL(BF_WRT,SZ_WRT),
        nullptr, nullptr, gy, nullptr, nullptr,
        PB*PN2, PD, PDY0, PDY0, PDY0, PD, 0,0,0,0,0,0, 1, 1.f, 0);
    ln_k<<<PB * PN2, 256>>>(gy, lny_g, lny_b, gy1, PLH(BF_Y1), PLL(BF_Y1,SZ_Y1));

    // q (pre-scaled, planes only; 3-pass), k (3-pass), v2/v1 (2-pass)
    gemm_bf<128,true><<<ngrid(PB*PN1, HDK, 128, 1), 256, BSMEM>>>(
        PLH(BF_X1), PLL(BF_X1,SZ_X1), PLH(BF_WQT), PLL(BF_WQT,SZ_WQT),
        nullptr, nullptr, nullptr, PLH(BF_Q), PLL(BF_Q,SZ_Q),
        PB*PN1, HDK, PD, PD, PD, HDK, 0,0,0,0,0,0, 1, PSCALE, 0);
    gemm_bf<128,true><<<ngrid(PB*PN2, HDK, 128, 1), 256, BSMEM>>>(
        PLH(BF_Y1), PLL(BF_Y1,SZ_Y1), PLH(BF_WKT), PLL(BF_WKT,SZ_WKT),
        nullptr, nullptr, gk, PLH(BF_K), PLL(BF_K,SZ_K),
        PB*PN2, HDK, PD, PD, PD, HDK, 0,0,0,0,0,0, 1, 1.f, 0);
    gemm_bf<128,false><<<ngrid(PB*PN2, HDV, 128, 1), 256, BSMEM>>>(
        PLH(BF_Y1), nullptr, PLH(BF_WV2T), PLL(BF_WV2T,SZ_WV2T),
        nullptr, nullptr, gv2, nullptr, nullptr,
        PB*PN2, HDV, PD, PD, PD, HDV, 0,0,0,0,0,0, 1, 1.f, 0);
    gemm_bf<128,false><<<ngrid(PB*PN1, HDV, 128, 1), 256, BSMEM>>>(
        PLH(BF_X1), nullptr, PLH(BF_WV1T), PLL(BF_WV1T,SZ_WV1T),
        nullptr, nullptr, gv1, nullptr, nullptr,
        PB*PN1, HDV, PD, PD, PD, HDV, 0,0,0,0,0,0, 1, 1.f, 0);

    // v2T / v1T planes per (b,h)
    tsplit_k<<<dim3(PDV/32, PN2/32, PB*PH), tt>>>(
        gv2, PLH(BF_V2T), PLL(BF_V2T,SZ_V2T), PN2, PDV, HDV,
        (long)PN2*HDV, (long)PDV, (long)PDV*PN2, PH);
    tsplit_k<<<dim3(PDV/32, PN1/32, PB*PH), tt>>>(
        gv1, PLH(BF_V1T), PLL(BF_V1T,SZ_V1T), PN1, PDV, HDV,
        (long)PN1*HDV, (long)PDV, (long)PDV*PN1, PH);

    // pos features + rel_q (planes only; 3-pass)
    pos_k<<<(PMQ + 127) / 128, 128>>>(PLH(BF_POS), PLL(BF_POS,SZ_POS));
    gemm_bf<128,true><<<ngrid(PMQ, HDK, 128, 1), 256, BSMEM>>>(
        PLH(BF_POS), PLL(BF_POS,SZ_POS), PLH(BF_WRELT), PLL(BF_WRELT,SZ_WRELT),
        nullptr, nullptr, nullptr, PLH(BF_RQ), PLL(BF_RQ,SZ_RQ),
        PMQ, HDK, PNRP, PNRP, PNRP, HDK, 0,0,0,0,0,0, 1, 1.f, 0);

    // kb single plane
    kb_k<<<2048, 256>>>(gk, rpb, PLH(BF_KB), PB*PN2*HDK);

    // content = q_scaled @ k^T  (3-pass)
    gemm_bf<128,true><<<ngrid(PN1, PN2, 128, PB*PH), 256, BSMEM>>>(
        PLH(BF_Q), PLL(BF_Q,SZ_Q), PLH(BF_K), PLL(BF_K,SZ_K),
        nullptr, nullptr, gatt, nullptr, nullptr,
        PN1, PN2, PDK, HDK, HDK, PN2,
        (long)PN1*HDK, (long)PDK, (long)PN2*HDK, (long)PDK,
        (long)PH*PN1*PN2, (long)PN1*PN2, PH, 1.f, 0);

    // rel = kb @ rel_q^T  (2-pass: kb single plane)
    gemm_bf<128,false><<<ngrid(PN2, PMQ, 128, PB*PH), 256, BSMEM>>>(
        PLH(BF_KB), nullptr, PLH(BF_RQ), PLL(BF_RQ,SZ_RQ),
        nullptr, nullptr, grel, nullptr, nullptr,
        PN2, PMQ, PDK, HDK, HDK, PMQ,
        (long)PN2*HDK, (long)PDK, 0L, (long)PDK,
        (long)PH*PN2*PMQ, (long)PN2*PMQ, PH, 1.f, 0);

    // tiled softmax -> single bf16 plane
    softmax2_k<<<dim3(PN1/32, PB*PH), 256, SMXSM>>>(gatt, grel, PLH(BF_ATT));

    // attT (single plane)
    bt_k<<<dim3(PN2/32, PN1/32, PB*PH), tt>>>(PLH(BF_ATT), PLH(BF_ATTT), PN1, PN2);

    // out1 = attn @ v2  (2-pass; hi-only output)
    gemm_bf<96,false><<<ngrid(PN1, PDV, 96, PB*PH), 256, BSMEM>>>(
        PLH(BF_ATT), nullptr, PLH(BF_V2T), PLL(BF_V2T,SZ_V2T),
        nullptr, nullptr, nullptr, PLH(BF_GO1), nullptr,
        PN1, PDV, PN2, PN2, PN2, HDV,
        (long)PH*PN1*PN2, (long)PN1*PN2, (long)PH*PDV*PN2, (long)PDV*PN2,
        (long)PN1*HDV, (long)PDV, PH, 1.f, 0);

    // out2 = attn^T @ v1 (2-pass; hi-only output)
    gemm_bf<96,false><<<ngrid(PN2, PDV, 96, PB*PH), 256, BSMEM>>>(
        PLH(BF_ATTT), nullptr, PLH(BF_V1T), PLL(BF_V1T,SZ_V1T),
        nullptr, nullptr, nullptr, PLH(BF_GO2), nullptr,
        PN2, PDV, PN1, PN1, PN1, HDV,
        (long)PH*PN2*PN1, (long)PN2*PN1, (long)PH*PDV*PN1, (long)PDV*PN1,
        (long)PN2*HDV, (long)PDV, PH, 1.f, 0);

    // x4 = x + out1 @ Wo1 + bo1 ; y4 = y + out2 @ Wo2 + bo2   (2-pass on A)
    gemm_bf<128,false><<<ngrid(PB*PN1, PD, 128, 1), 256, BSMEM>>>(
        PLH(BF_GO1), nullptr, PLH(BF_WO1T), PLL(BF_WO1T,SZ_WO1T),
        bo1, x, gx4, nullptr, nullptr,
        PB*PN1, PD, HDV, HDV, HDV, PD, 0,0,0,0,0,0, 1, 1.f, 0);
    gemm_bf<128,false><<<ngrid(PB*PN2, PD, 128, 1), 256, BSMEM>>>(
        PLH(BF_GO2), nullptr, PLH(BF_WO2T), PLL(BF_WO2T,SZ_WO2T),
        bo2, gy, gy4, nullptr, nullptr,
        PB*PN2, PD, HDV, HDV, HDV, PD, 0,0,0,0,0,0, 1, 1.f, 0);

    // FFN x: LN (3-pass in), hidden hi-only, FFN2 2-pass
    ln_k<<<PB * PN1, 256>>>(gx4, fx_g, fx_b, gx1, PLH(BF_X1), PLL(BF_X1,SZ_X1));
    gemm_bf<128,true><<<ngrid(PB*PN1, PDFF, 128, 1), 256, BSMEM>>>(
        PLH(BF_X1), PLL(BF_X1,SZ_X1), PLH(BF_FX1T), PLL(BF_FX1T,SZ_F1),
        fx_b1, nullptr, nullptr, PLH(BF_GH), nullptr,
        PB*PN1, PDFF, PD, PD, PD, PDFF, 0,0,0,0,0,0, 1, 1.f, 1);
    gemm_bf<128,false><<<ngrid(PB*PN1, PD, 128, 1), 256, BSMEM>>>(
        PLH(BF_GH), nullptr, PLH(BF_FX2T), PLL(BF_FX2T,SZ_F2),
        fx_b2, gx4, outx, nullptr, nullptr,
        PB*PN1, PD, PDFF, PDFF, PDFF, PD, 0,0,0,0,0,0, 1, 1.f, 0);

    // FFN y
    ln_k<<<PB * PN2, 256>>>(gy4, fy_g, fy_b, gy1, PLH(BF_Y1), PLL(BF_Y1,SZ_Y1));
    gemm_bf<128,true><<<ngrid(PB*PN2, PDFF, 128, 1), 256, BSMEM>>>(
        PLH(BF_Y1), PLL(BF_Y1,SZ_Y1), PLH(BF_FY1T), PLL(BF_FY1T,SZ_F1),
        fy_b1, nullptr, nullptr, PLH(BF_GH), nullptr,
        PB*PN2, PDFF, PD, PD, PD, PDFF, 0,0,0,0,0,0, 1, 1.f, 1);
    gemm_bf<128,false><<<ngrid(PB*PN2, PD, 128, 1), 256, BSMEM>>>(
        PLH(BF_GH), nullptr, PLH(BF_FY2T), PLL(BF_FY2T,SZ_F2),
        fy_b2, gy4, outy, nullptr, nullptr,
        PB*PN2, PD, PDFF, PDFF, PDFF, PD, 0,0,0,0,0,0, 1, 1.f, 0);

    (void)in_sizes; (void)n_in; (void)out_size;
}